// round 1
// baseline (speedup 1.0000x reference)
#include <cuda_runtime.h>
#include <cuda_bf16.h>
#include <cstdint>

// Problem constants
#define B_   4
#define S_   1024
#define P_   128
#define NX_  1024
#define H_   16
#define DH_  64
#define T_   (P_ + S_)      // 1152
#define BS_  (B_ * S_)      // 4096
#define BP_  (B_ * P_)      // 512

// Scratch (static device globals; no allocation allowed)
__device__ float g_qkv[(size_t)BS_ * 3 * NX_];   // [4096, 3072]
__device__ float g_ekv[(size_t)BP_ * 2 * NX_];   // [512, 2048]
__device__ float g_a  [(size_t)BS_ * NX_];       // [4096, 1024]

// ----------------------------------------------------------------------------
// Tiled fp32 GEMM: C[M,N] = A[M,K] @ B[K,N] + bias[N]
// Block tile 128x128, K-step 8, 256 threads, 8x8 per-thread microtile.
// Requires M%128==0, N%128==0, K%8==0 (true for all three GEMMs here).
// ----------------------------------------------------------------------------
__global__ __launch_bounds__(256) void sgemm_bias(
    const float* __restrict__ A, const float* __restrict__ B,
    const float* __restrict__ bias, float* __restrict__ C,
    int M, int N, int K)
{
    __shared__ float As[8][128];
    __shared__ float Bs[8][128];

    const int bx = blockIdx.x;   // N tile
    const int by = blockIdx.y;   // M tile
    const int tid = threadIdx.x;
    const int tx = tid & 15;     // 0..15 -> N micro
    const int ty = tid >> 4;     // 0..15 -> M micro

    const float* Ab = A + (size_t)by * 128 * K;
    const float* Bb = B + (size_t)bx * 128;

    const int arow = tid >> 1;          // 0..127
    const int acol = (tid & 1) << 2;    // 0 or 4
    const int brow = tid >> 5;          // 0..7
    const int bcol = (tid & 31) << 2;   // 0..124

    float acc[8][8];
#pragma unroll
    for (int i = 0; i < 8; i++)
#pragma unroll
        for (int j = 0; j < 8; j++) acc[i][j] = 0.f;

    for (int k0 = 0; k0 < K; k0 += 8) {
        float4 av = *(const float4*)(Ab + (size_t)arow * K + k0 + acol);
        float4 bv = *(const float4*)(Bb + (size_t)(k0 + brow) * N + bcol);
        __syncthreads();
        As[acol + 0][arow] = av.x;
        As[acol + 1][arow] = av.y;
        As[acol + 2][arow] = av.z;
        As[acol + 3][arow] = av.w;
        *(float4*)(&Bs[brow][bcol]) = bv;
        __syncthreads();
#pragma unroll
        for (int kk = 0; kk < 8; kk++) {
            float ar[8], br[8];
            *(float4*)(ar)     = *(const float4*)(&As[kk][ty * 8]);
            *(float4*)(ar + 4) = *(const float4*)(&As[kk][ty * 8 + 4]);
            *(float4*)(br)     = *(const float4*)(&Bs[kk][tx * 8]);
            *(float4*)(br + 4) = *(const float4*)(&Bs[kk][tx * 8 + 4]);
#pragma unroll
            for (int i = 0; i < 8; i++)
#pragma unroll
                for (int j = 0; j < 8; j++)
                    acc[i][j] += ar[i] * br[j];
        }
    }

    // Epilogue with bias
    const int ncol = bx * 128 + tx * 8;
    float4 bsv0 = *(const float4*)(bias + ncol);
    float4 bsv1 = *(const float4*)(bias + ncol + 4);
#pragma unroll
    for (int i = 0; i < 8; i++) {
        size_t row = (size_t)by * 128 + ty * 8 + i;
        float4 o0, o1;
        o0.x = acc[i][0] + bsv0.x; o0.y = acc[i][1] + bsv0.y;
        o0.z = acc[i][2] + bsv0.z; o0.w = acc[i][3] + bsv0.w;
        o1.x = acc[i][4] + bsv1.x; o1.y = acc[i][5] + bsv1.y;
        o1.z = acc[i][6] + bsv1.z; o1.w = acc[i][7] + bsv1.w;
        *(float4*)(C + row * N + ncol)     = o0;
        *(float4*)(C + row * N + ncol + 4) = o1;
    }
}

// ----------------------------------------------------------------------------
// Fused attention: per (b,h), 8 queries per block (warp per query),
// online softmax over T=1152 keys in 32-key tiles staged in shared memory.
// Masking: keys [0,P) are memory (always visible, + (1-Mmask)*-1e4 bias),
// keys [P,T) are self tokens with causal mask and attention_mask bias.
// Output written head-merged into g_a[(b*S+s)*NX + h*64 + d].
// ----------------------------------------------------------------------------
#define QTILE 8
#define KTILE 32

__global__ __launch_bounds__(256) void attn_kernel(
    const float* __restrict__ qkv,   // [BS, 3*NX]
    const float* __restrict__ ekv,   // [BP, 2*NX]
    const float* __restrict__ Mmask, // [B, P]
    const float* __restrict__ amask, // [B,1,1,S]
    float* __restrict__ out)         // [BS, NX]
{
    const int bh = blockIdx.y;
    const int b = bh / H_;
    const int h = bh % H_;
    const int q0 = blockIdx.x * QTILE;
    const int tid = threadIdx.x;
    const int qi = tid >> 5;    // warp id = query within tile
    const int lane = tid & 31;

    __shared__ float qs[QTILE][DH_];
    __shared__ float ks[KTILE][DH_ + 1];  // pad 65: conflict-free scalar by-row reads
    __shared__ float vs[KTILE][DH_ + 2];  // pad 66: even stride, 2-way worst case

    // Load Q tile
    for (int i = tid; i < QTILE * DH_; i += 256) {
        int r = i >> 6, d = i & 63;
        qs[r][d] = qkv[(size_t)(b * S_ + q0 + r) * (3 * NX_) + h * DH_ + d];
    }

    float m = -1e30f, l = 0.f;
    float acc0 = 0.f, acc1 = 0.f;   // dims 2*lane, 2*lane+1
    const int s_idx = q0 + qi;

    for (int t0 = 0; t0 < T_; t0 += KTILE) {
        __syncthreads();
        // Stage K/V tile
        for (int i = tid; i < KTILE * DH_; i += 256) {
            int r = i >> 6, d = i & 63;
            int t = t0 + r;
            float kv, vv;
            if (t < P_) {
                const float* e = ekv + (size_t)(b * P_ + t) * (2 * NX_);
                kv = e[h * DH_ + d];
                vv = e[NX_ + h * DH_ + d];
            } else {
                const float* sp = qkv + (size_t)(b * S_ + (t - P_)) * (3 * NX_);
                kv = sp[NX_ + h * DH_ + d];
                vv = sp[2 * NX_ + h * DH_ + d];
            }
            ks[r][d] = kv;
            vs[r][d] = vv;
        }
        __syncthreads();

        // Logit for key (t0 + lane), query (q0 + qi)
        float dot = 0.f;
#pragma unroll
        for (int d = 0; d < DH_; d++)
            dot += qs[qi][d] * ks[lane][d];

        const int t = t0 + lane;
        float logit;
        if (t < P_) {
            logit = dot * 0.125f + (1.f - Mmask[b * P_ + t]) * -10000.f;
        } else {
            const int tt = t - P_;
            const float am = amask[b * S_ + tt];
            logit = (tt <= s_idx) ? (dot * 0.125f + am) : (-10000.f + am);
        }

        // Online softmax (warp = one query row)
        float tmax = logit;
#pragma unroll
        for (int o = 16; o; o >>= 1)
            tmax = fmaxf(tmax, __shfl_xor_sync(0xffffffffu, tmax, o));
        const float m_new = fmaxf(m, tmax);
        const float p = __expf(logit - m_new);
        const float alpha = __expf(m - m_new);
        float psum = p;
#pragma unroll
        for (int o = 16; o; o >>= 1)
            psum += __shfl_xor_sync(0xffffffffu, psum, o);
        l = l * alpha + psum;
        m = m_new;

        acc0 *= alpha;
        acc1 *= alpha;
#pragma unroll
        for (int t2 = 0; t2 < KTILE; t2++) {
            const float pt = __shfl_sync(0xffffffffu, p, t2);
            acc0 += pt * vs[t2][2 * lane];
            acc1 += pt * vs[t2][2 * lane + 1];
        }
    }

    const float inv = 1.f / l;
    const size_t o = (size_t)(b * S_ + s_idx) * NX_ + h * DH_;
    out[o + 2 * lane]     = acc0 * inv;
    out[o + 2 * lane + 1] = acc1 * inv;
}

// ----------------------------------------------------------------------------
// Launch
// ----------------------------------------------------------------------------
extern "C" void kernel_launch(void* const* d_in, const int* in_sizes, int n_in,
                              void* d_out, int out_size)
{
    const float* x      = (const float*)d_in[0];   // [B,S,NX]
    const float* M      = (const float*)d_in[1];   // [B,P,NX]
    const float* Mmask  = (const float*)d_in[2];   // [B,P]
    const float* amask  = (const float*)d_in[3];   // [B,1,1,S]
    const float* W_attn = (const float*)d_in[4];   // [NX, 3NX]
    const float* b_attn = (const float*)d_in[5];   // [3NX]
    const float* W_mem  = (const float*)d_in[6];   // [NX, 2NX]
    const float* b_mem  = (const float*)d_in[7];   // [2NX]
    const float* W_proj = (const float*)d_in[8];   // [NX, NX]
    const float* b_proj = (const float*)d_in[9];   // [NX]
    float* out = (float*)d_out;

    float* qkv; cudaGetSymbolAddress((void**)&qkv, g_qkv);
    float* ekv; cudaGetSymbolAddress((void**)&ekv, g_ekv);
    float* a;   cudaGetSymbolAddress((void**)&a,   g_a);

    // 1) qkv = x @ W_attn + b_attn   : [4096,1024]@[1024,3072]
    {
        dim3 grid(3 * NX_ / 128, BS_ / 128);
        sgemm_bias<<<grid, 256>>>(x, W_attn, b_attn, qkv, BS_, 3 * NX_, NX_);
    }
    // 2) ekv = M @ W_mem + b_mem     : [512,1024]@[1024,2048]
    {
        dim3 grid(2 * NX_ / 128, BP_ / 128);
        sgemm_bias<<<grid, 256>>>(M, W_mem, b_mem, ekv, BP_, 2 * NX_, NX_);
    }
    // 3) attention -> a
    {
        dim3 grid(S_ / QTILE, B_ * H_);
        attn_kernel<<<grid, 256>>>(qkv, ekv, Mmask, amask, a);
    }
    // 4) out = a @ W_proj + b_proj   : [4096,1024]@[1024,1024]
    {
        dim3 grid(NX_ / 128, BS_ / 128);
        sgemm_bias<<<grid, 256>>>(a, W_proj, b_proj, out, BS_, NX_, NX_);
    }
}

// round 2
// speedup vs baseline: 2.2287x; 2.2287x over previous
#include <cuda_runtime.h>
#include <cuda_bf16.h>
#include <cstdint>

// Problem constants
#define B_   4
#define S_   1024
#define P_   128
#define NX_  1024
#define H_   16
#define DH_  64
#define T_   (P_ + S_)      // 1152
#define BS_  (B_ * S_)      // 4096
#define BP_  (B_ * P_)      // 512

// Scratch (static device globals; no allocation allowed)
__device__ float g_qkv[(size_t)BS_ * 3 * NX_];   // [4096, 3072]
__device__ float g_ekv[(size_t)BP_ * 2 * NX_];   // [512, 2048]
__device__ float g_a  [(size_t)BS_ * NX_];       // [4096, 1024]

// ----------------------------------------------------------------------------
// Tiled fp32 GEMM: C[M,N] = A[M,K] @ B[K,N] + bias[N]   (unchanged from R1)
// ----------------------------------------------------------------------------
__global__ __launch_bounds__(256) void sgemm_bias(
    const float* __restrict__ A, const float* __restrict__ B,
    const float* __restrict__ bias, float* __restrict__ C,
    int M, int N, int K)
{
    __shared__ float As[8][128];
    __shared__ float Bs[8][128];

    const int bx = blockIdx.x;
    const int by = blockIdx.y;
    const int tid = threadIdx.x;
    const int tx = tid & 15;
    const int ty = tid >> 4;

    const float* Ab = A + (size_t)by * 128 * K;
    const float* Bb = B + (size_t)bx * 128;

    const int arow = tid >> 1;
    const int acol = (tid & 1) << 2;
    const int brow = tid >> 5;
    const int bcol = (tid & 31) << 2;

    float acc[8][8];
#pragma unroll
    for (int i = 0; i < 8; i++)
#pragma unroll
        for (int j = 0; j < 8; j++) acc[i][j] = 0.f;

    for (int k0 = 0; k0 < K; k0 += 8) {
        float4 av = *(const float4*)(Ab + (size_t)arow * K + k0 + acol);
        float4 bv = *(const float4*)(Bb + (size_t)(k0 + brow) * N + bcol);
        __syncthreads();
        As[acol + 0][arow] = av.x;
        As[acol + 1][arow] = av.y;
        As[acol + 2][arow] = av.z;
        As[acol + 3][arow] = av.w;
        *(float4*)(&Bs[brow][bcol]) = bv;
        __syncthreads();
#pragma unroll
        for (int kk = 0; kk < 8; kk++) {
            float ar[8], br[8];
            *(float4*)(ar)     = *(const float4*)(&As[kk][ty * 8]);
            *(float4*)(ar + 4) = *(const float4*)(&As[kk][ty * 8 + 4]);
            *(float4*)(br)     = *(const float4*)(&Bs[kk][tx * 8]);
            *(float4*)(br + 4) = *(const float4*)(&Bs[kk][tx * 8 + 4]);
#pragma unroll
            for (int i = 0; i < 8; i++)
#pragma unroll
                for (int j = 0; j < 8; j++)
                    acc[i][j] += ar[i] * br[j];
        }
    }

    const int ncol = bx * 128 + tx * 8;
    float4 bsv0 = *(const float4*)(bias + ncol);
    float4 bsv1 = *(const float4*)(bias + ncol + 4);
#pragma unroll
    for (int i = 0; i < 8; i++) {
        size_t row = (size_t)by * 128 + ty * 8 + i;
        float4 o0, o1;
        o0.x = acc[i][0] + bsv0.x; o0.y = acc[i][1] + bsv0.y;
        o0.z = acc[i][2] + bsv0.z; o0.w = acc[i][3] + bsv0.w;
        o1.x = acc[i][4] + bsv1.x; o1.y = acc[i][5] + bsv1.y;
        o1.z = acc[i][6] + bsv1.z; o1.w = acc[i][7] + bsv1.w;
        *(float4*)(C + row * N + ncol)     = o0;
        *(float4*)(C + row * N + ncol + 4) = o1;
    }
}

// ----------------------------------------------------------------------------
// Flash attention, fp32, block tile 64 queries x 64 keys.
// 256 threads as 16x16; each thread owns a 4x4 microtile of S and of O.
// smem (dynamic): Qs[64][64] d-major (scaled by 1/8), Ks[64][64] d-major,
//                 Vs[64][64] t-major, Ps[64][68] c-major (padded).
// Causal tile skipping: block bx needs P/64 + bx + 1 key tiles.
// ----------------------------------------------------------------------------
#define AQ 64
#define AK 64
#define PSTRIDE 68
#define ATTN_SMEM ((3 * 64 * 64 + 64 * PSTRIDE) * 4)

__global__ __launch_bounds__(256) void attn_flash(
    const float* __restrict__ qkv,   // [BS, 3*NX]
    const float* __restrict__ ekv,   // [BP, 2*NX]
    const float* __restrict__ Mmask, // [B, P]
    const float* __restrict__ amask, // [B,1,1,S]
    float* __restrict__ out)         // [BS, NX]
{
    extern __shared__ float sm[];
    float* Qs = sm;                  // [64][64]  Qs[d*64 + r]
    float* Ks = Qs + 64 * 64;        // [64][64]  Ks[d*64 + t]
    float* Vs = Ks + 64 * 64;        // [64][64]  Vs[t*64 + d]
    float* Ps = Vs + 64 * 64;        // [64][68]  Ps[c*PSTRIDE + r]

    const int bh = blockIdx.y;
    const int b = bh >> 4, h = bh & 15;
    const int q0 = blockIdx.x * AQ;
    const int tid = threadIdx.x;
    const int tx = tid & 15;         // key-col / dh-col group
    const int ty = tid >> 4;         // query-row group

    // ---- Load Q tile, transposed to d-major, pre-scaled by 1/sqrt(dh) ----
#pragma unroll
    for (int it = 0; it < 4; it++) {
        const int fid = tid + it * 256;      // 0..1023 float4 slots
        const int r = fid & 63;
        const int dq = fid >> 6;             // 0..15
        const float4 qv = *(const float4*)(
            qkv + (size_t)(b * S_ + q0 + r) * (3 * NX_) + h * DH_ + dq * 4);
        Qs[(dq * 4 + 0) * 64 + r] = qv.x * 0.125f;
        Qs[(dq * 4 + 1) * 64 + r] = qv.y * 0.125f;
        Qs[(dq * 4 + 2) * 64 + r] = qv.z * 0.125f;
        Qs[(dq * 4 + 3) * 64 + r] = qv.w * 0.125f;
    }

    float m[4], l[4], o[4][4];
#pragma unroll
    for (int i = 0; i < 4; i++) {
        m[i] = -1e30f; l[i] = 0.f;
#pragma unroll
        for (int j = 0; j < 4; j++) o[i][j] = 0.f;
    }

    const int ntiles = (P_ / AK) + blockIdx.x + 1;

    for (int kt = 0; kt < ntiles; kt++) {
        const int t0 = kt * AK;
        __syncthreads();

        // ---- Stage K (transposed, d-major) and V (t-major) ----
#pragma unroll
        for (int it = 0; it < 4; it++) {
            const int fid = tid + it * 256;
            // K: lane -> t (conflict-free transpose stores)
            {
                const int t = fid & 63;
                const int dq = fid >> 6;
                const int tg = t0 + t;
                const float* kptr = (tg < P_)
                    ? ekv + (size_t)(b * P_ + tg) * (2 * NX_) + h * DH_
                    : qkv + (size_t)(b * S_ + tg - P_) * (3 * NX_) + NX_ + h * DH_;
                const float4 kv = *(const float4*)(kptr + dq * 4);
                Ks[(dq * 4 + 0) * 64 + t] = kv.x;
                Ks[(dq * 4 + 1) * 64 + t] = kv.y;
                Ks[(dq * 4 + 2) * 64 + t] = kv.z;
                Ks[(dq * 4 + 3) * 64 + t] = kv.w;
            }
            // V: direct copy
            {
                const int tv = fid >> 4;
                const int dv = (fid & 15) * 4;
                const int tg = t0 + tv;
                const float* vptr = (tg < P_)
                    ? ekv + (size_t)(b * P_ + tg) * (2 * NX_) + NX_ + h * DH_
                    : qkv + (size_t)(b * S_ + tg - P_) * (3 * NX_) + 2 * NX_ + h * DH_;
                *(float4*)(Vs + tv * 64 + dv) = *(const float4*)(vptr + dv);
            }
        }
        __syncthreads();

        // ---- S = Q @ K^T (4x4 microtile) ----
        float s[4][4];
#pragma unroll
        for (int i = 0; i < 4; i++)
#pragma unroll
            for (int j = 0; j < 4; j++) s[i][j] = 0.f;

#pragma unroll 8
        for (int kk = 0; kk < 64; kk++) {
            const float4 q4 = *(const float4*)(Qs + kk * 64 + ty * 4);
            const float4 k4 = *(const float4*)(Ks + kk * 64 + tx * 4);
            const float qa[4] = {q4.x, q4.y, q4.z, q4.w};
            const float ka[4] = {k4.x, k4.y, k4.z, k4.w};
#pragma unroll
            for (int i = 0; i < 4; i++)
#pragma unroll
                for (int j = 0; j < 4; j++)
                    s[i][j] += qa[i] * ka[j];
        }

        // ---- Column bias / causal info ----
        float cb[4];   // additive bias per column
        int ttj[4];    // self-token index, or -1 for memory columns
#pragma unroll
        for (int j = 0; j < 4; j++) {
            const int t = t0 + tx * 4 + j;
            if (t < P_) {
                cb[j] = (1.f - Mmask[b * P_ + t]) * -10000.f;
                ttj[j] = -1;
            } else {
                const int tt = t - P_;
                cb[j] = amask[b * S_ + tt];
                ttj[j] = tt;
            }
        }

        // ---- Online softmax per row (reduce across the 16-lane tx group) ----
#pragma unroll
        for (int i = 0; i < 4; i++) {
            const int r = q0 + ty * 4 + i;
            float lo[4];
#pragma unroll
            for (int j = 0; j < 4; j++) {
                const bool vis = (ttj[j] < 0) | (ttj[j] <= r);
                lo[j] = (vis ? s[i][j] : -10000.f) + cb[j];
            }
            float mx = fmaxf(fmaxf(lo[0], lo[1]), fmaxf(lo[2], lo[3]));
#pragma unroll
            for (int off = 1; off < 16; off <<= 1)
                mx = fmaxf(mx, __shfl_xor_sync(0xffffffffu, mx, off));
            const float mn = fmaxf(m[i], mx);
            const float alpha = __expf(m[i] - mn);
            float p[4], ps = 0.f;
#pragma unroll
            for (int j = 0; j < 4; j++) { p[j] = __expf(lo[j] - mn); ps += p[j]; }
#pragma unroll
            for (int off = 1; off < 16; off <<= 1)
                ps += __shfl_xor_sync(0xffffffffu, ps, off);
            l[i] = l[i] * alpha + ps;
            m[i] = mn;
#pragma unroll
            for (int j = 0; j < 4; j++) o[i][j] *= alpha;
#pragma unroll
            for (int j = 0; j < 4; j++)
                Ps[(tx * 4 + j) * PSTRIDE + ty * 4 + i] = p[j];
        }
        __syncthreads();

        // ---- O += P @ V (4x4 microtile) ----
#pragma unroll 8
        for (int c = 0; c < 64; c++) {
            const float4 p4 = *(const float4*)(Ps + c * PSTRIDE + ty * 4);
            const float4 v4 = *(const float4*)(Vs + c * 64 + tx * 4);
            const float pa[4] = {p4.x, p4.y, p4.z, p4.w};
            const float va[4] = {v4.x, v4.y, v4.z, v4.w};
#pragma unroll
            for (int i = 0; i < 4; i++)
#pragma unroll
                for (int j = 0; j < 4; j++)
                    o[i][j] += pa[i] * va[j];
        }
    }

    // ---- Epilogue ----
#pragma unroll
    for (int i = 0; i < 4; i++) {
        const float inv = 1.f / l[i];
        float4 ov;
        ov.x = o[i][0] * inv; ov.y = o[i][1] * inv;
        ov.z = o[i][2] * inv; ov.w = o[i][3] * inv;
        const size_t off = (size_t)(b * S_ + q0 + ty * 4 + i) * NX_ + h * DH_ + tx * 4;
        *(float4*)(out + off) = ov;
    }
}

// ----------------------------------------------------------------------------
// Launch
// ----------------------------------------------------------------------------
extern "C" void kernel_launch(void* const* d_in, const int* in_sizes, int n_in,
                              void* d_out, int out_size)
{
    const float* x      = (const float*)d_in[0];
    const float* M      = (const float*)d_in[1];
    const float* Mmask  = (const float*)d_in[2];
    const float* amask  = (const float*)d_in[3];
    const float* W_attn = (const float*)d_in[4];
    const float* b_attn = (const float*)d_in[5];
    const float* W_mem  = (const float*)d_in[6];
    const float* b_mem  = (const float*)d_in[7];
    const float* W_proj = (const float*)d_in[8];
    const float* b_proj = (const float*)d_in[9];
    float* out = (float*)d_out;

    float* qkv; cudaGetSymbolAddress((void**)&qkv, g_qkv);
    float* ekv; cudaGetSymbolAddress((void**)&ekv, g_ekv);
    float* a;   cudaGetSymbolAddress((void**)&a,   g_a);

    cudaFuncSetAttribute(attn_flash, cudaFuncAttributeMaxDynamicSharedMemorySize,
                         ATTN_SMEM);

    // 1) qkv = x @ W_attn + b_attn
    {
        dim3 grid(3 * NX_ / 128, BS_ / 128);
        sgemm_bias<<<grid, 256>>>(x, W_attn, b_attn, qkv, BS_, 3 * NX_, NX_);
    }
    // 2) ekv = M @ W_mem + b_mem
    {
        dim3 grid(2 * NX_ / 128, BP_ / 128);
        sgemm_bias<<<grid, 256>>>(M, W_mem, b_mem, ekv, BP_, 2 * NX_, NX_);
    }
    // 3) flash attention -> a
    {
        dim3 grid(S_ / AQ, B_ * H_);
        attn_flash<<<grid, 256, ATTN_SMEM>>>(qkv, ekv, Mmask, amask, a);
    }
    // 4) out = a @ W_proj + b_proj
    {
        dim3 grid(NX_ / 128, BS_ / 128);
        sgemm_bias<<<grid, 256>>>(a, W_proj, b_proj, out, BS_, NX_, NX_);
    }
}

// round 3
// speedup vs baseline: 2.6950x; 1.2092x over previous
#include <cuda_runtime.h>
#include <cuda_bf16.h>
#include <cstdint>

// Problem constants
#define B_   4
#define S_   1024
#define P_   128
#define NX_  1024
#define H_   16
#define DH_  64
#define T_   (P_ + S_)      // 1152
#define BS_  (B_ * S_)      // 4096
#define BP_  (B_ * P_)      // 512

// Scratch (static device globals; no allocation allowed)
__device__ float g_qkv[(size_t)BS_ * 3 * NX_];   // [4096, 3072]
__device__ float g_ekv[(size_t)BP_ * 2 * NX_];   // [512, 2048]
__device__ float g_a  [(size_t)BS_ * NX_];       // [4096, 1024]

// ----------------------------------------------------------------------------
// Tiled fp32 GEMM: C[M,N] = A[M,K] @ B[K,N] + bias[N]   (unchanged)
// ----------------------------------------------------------------------------
__global__ __launch_bounds__(256) void sgemm_bias(
    const float* __restrict__ A, const float* __restrict__ B,
    const float* __restrict__ bias, float* __restrict__ C,
    int M, int N, int K)
{
    __shared__ float As[8][128];
    __shared__ float Bs[8][128];

    const int bx = blockIdx.x;
    const int by = blockIdx.y;
    const int tid = threadIdx.x;
    const int tx = tid & 15;
    const int ty = tid >> 4;

    const float* Ab = A + (size_t)by * 128 * K;
    const float* Bb = B + (size_t)bx * 128;

    const int arow = tid >> 1;
    const int acol = (tid & 1) << 2;
    const int brow = tid >> 5;
    const int bcol = (tid & 31) << 2;

    float acc[8][8];
#pragma unroll
    for (int i = 0; i < 8; i++)
#pragma unroll
        for (int j = 0; j < 8; j++) acc[i][j] = 0.f;

    for (int k0 = 0; k0 < K; k0 += 8) {
        float4 av = *(const float4*)(Ab + (size_t)arow * K + k0 + acol);
        float4 bv = *(const float4*)(Bb + (size_t)(k0 + brow) * N + bcol);
        __syncthreads();
        As[acol + 0][arow] = av.x;
        As[acol + 1][arow] = av.y;
        As[acol + 2][arow] = av.z;
        As[acol + 3][arow] = av.w;
        *(float4*)(&Bs[brow][bcol]) = bv;
        __syncthreads();
#pragma unroll
        for (int kk = 0; kk < 8; kk++) {
            float ar[8], br[8];
            *(float4*)(ar)     = *(const float4*)(&As[kk][ty * 8]);
            *(float4*)(ar + 4) = *(const float4*)(&As[kk][ty * 8 + 4]);
            *(float4*)(br)     = *(const float4*)(&Bs[kk][tx * 8]);
            *(float4*)(br + 4) = *(const float4*)(&Bs[kk][tx * 8 + 4]);
#pragma unroll
            for (int i = 0; i < 8; i++)
#pragma unroll
                for (int j = 0; j < 8; j++)
                    acc[i][j] += ar[i] * br[j];
        }
    }

    const int ncol = bx * 128 + tx * 8;
    float4 bsv0 = *(const float4*)(bias + ncol);
    float4 bsv1 = *(const float4*)(bias + ncol + 4);
#pragma unroll
    for (int i = 0; i < 8; i++) {
        size_t row = (size_t)by * 128 + ty * 8 + i;
        float4 o0, o1;
        o0.x = acc[i][0] + bsv0.x; o0.y = acc[i][1] + bsv0.y;
        o0.z = acc[i][2] + bsv0.z; o0.w = acc[i][3] + bsv0.w;
        o1.x = acc[i][4] + bsv1.x; o1.y = acc[i][5] + bsv1.y;
        o1.z = acc[i][6] + bsv1.z; o1.w = acc[i][7] + bsv1.w;
        *(float4*)(C + row * N + ncol)     = o0;
        *(float4*)(C + row * N + ncol + 4) = o1;
    }
}

// ----------------------------------------------------------------------------
// tf32 mma.sync helpers
// ----------------------------------------------------------------------------
__device__ __forceinline__ uint32_t f2tf32(float x) {
    uint32_t u;
    asm("cvt.rna.tf32.f32 %0, %1;" : "=r"(u) : "f"(x));
    return u;
}

__device__ __forceinline__ void mma_tf32(float c[4], const uint32_t a[4],
                                         uint32_t b0, uint32_t b1) {
    asm volatile(
        "mma.sync.aligned.m16n8k8.row.col.f32.tf32.tf32.f32 "
        "{%0,%1,%2,%3}, {%4,%5,%6,%7}, {%8,%9}, {%0,%1,%2,%3};"
        : "+f"(c[0]), "+f"(c[1]), "+f"(c[2]), "+f"(c[3])
        : "r"(a[0]), "r"(a[1]), "r"(a[2]), "r"(a[3]), "r"(b0), "r"(b1));
}

// ----------------------------------------------------------------------------
// Flash attention with tf32 tensor cores.
// Block: 128 queries x one (b,h). 8 warps, warp w owns rows 16w..16w+15.
// Key loop in 64-key tiles staged to smem (tf32-rounded), causal tile skip.
//
// Smem (floats, stride 68 pads all fragment access conflict-free):
//   Ks [64][68], Vs [64][68], Ps [8 warps][16][68], Cb [64]
//   Q is staged once into the Ks+Vs region (128 rows x 68) before the loop.
// ----------------------------------------------------------------------------
#define KSTRIDE 68
#define ATTN_SMEM ((2 * 64 * KSTRIDE + 8 * 16 * KSTRIDE + 64) * 4)

__global__ __launch_bounds__(256) void attn_mma(
    const float* __restrict__ qkv,   // [BS, 3*NX]
    const float* __restrict__ ekv,   // [BP, 2*NX]
    const float* __restrict__ Mmask, // [B, P]
    const float* __restrict__ amask, // [B,1,1,S]
    float* __restrict__ out)         // [BS, NX]
{
    extern __shared__ float sm[];
    float* Ks = sm;                          // [64][68]
    float* Vs = sm + 64 * KSTRIDE;           // [64][68]
    float* Ps = sm + 2 * 64 * KSTRIDE;       // [8][16][68]
    float* Cb = Ps + 8 * 16 * KSTRIDE;       // [64]
    uint32_t* Ksu = (uint32_t*)Ks;
    uint32_t* Vsu = (uint32_t*)Vs;
    uint32_t* Qtu = (uint32_t*)sm;           // Q staged over Ks+Vs: [128][68]

    const int bh = blockIdx.y;
    const int b = bh >> 4, h = bh & 15;
    const int q0 = blockIdx.x * 128;
    const int tid = threadIdx.x;
    const int w = tid >> 5;
    const int lane = tid & 31;
    const int gr = lane >> 2;     // group row 0..7
    const int tg = lane & 3;      // thread in group 0..3

    // ---- Stage Q (scaled 1/8, tf32-rounded) into Qtmp [128][68] ----
#pragma unroll
    for (int it = 0; it < 8; it++) {
        const int fid = tid + it * 256;          // 2048 float4 slots
        const int r = fid >> 4;
        const int c4 = (fid & 15) * 4;
        const float4 q = *(const float4*)(
            qkv + (size_t)(b * S_ + q0 + r) * (3 * NX_) + h * DH_ + c4);
        uint32_t* d = Qtu + r * KSTRIDE + c4;
        d[0] = f2tf32(q.x * 0.125f);
        d[1] = f2tf32(q.y * 0.125f);
        d[2] = f2tf32(q.z * 0.125f);
        d[3] = f2tf32(q.w * 0.125f);
    }
    __syncthreads();

    // ---- Load Q a-fragments (held in registers for the whole key loop) ----
    uint32_t aQ[8][4];
    {
        const int r0 = 16 * w + gr;
#pragma unroll
        for (int kf = 0; kf < 8; kf++) {
            aQ[kf][0] = Qtu[r0 * KSTRIDE + 8 * kf + tg];
            aQ[kf][1] = Qtu[(r0 + 8) * KSTRIDE + 8 * kf + tg];
            aQ[kf][2] = Qtu[r0 * KSTRIDE + 8 * kf + tg + 4];
            aQ[kf][3] = Qtu[(r0 + 8) * KSTRIDE + 8 * kf + tg + 4];
        }
    }

    float m0 = -1e30f, m1 = -1e30f, l0 = 0.f, l1 = 0.f;
    float o[8][4];
#pragma unroll
    for (int nf = 0; nf < 8; nf++)
#pragma unroll
        for (int j = 0; j < 4; j++) o[nf][j] = 0.f;

    uint32_t* Pswu = (uint32_t*)(Ps + w * 16 * KSTRIDE);
    const int r0g = q0 + 16 * w + gr;   // global query row (in S) of frag row 0
    const int r1g = r0g + 8;
    const int ntiles = 2 * blockIdx.x + 4;

    for (int kt = 0; kt < ntiles; kt++) {
        const int t0k = kt * 64;
        __syncthreads();   // protect Q/Ks/Vs (and Ps a-frag reads) from overwrite

        // ---- Stage K, V (tf32-rounded) and column bias ----
#pragma unroll
        for (int it = 0; it < 4; it++) {
            const int fid = tid + it * 256;      // 1024 float4 slots
            const int t = fid >> 4;
            const int c4 = (fid & 15) * 4;
            const int tg_ = t0k + t;
            const float* kp;
            const float* vp;
            if (tg_ < P_) {
                const float* e = ekv + (size_t)(b * P_ + tg_) * (2 * NX_) + h * DH_;
                kp = e;
                vp = e + NX_;
            } else {
                const float* s = qkv + (size_t)(b * S_ + tg_ - P_) * (3 * NX_) + h * DH_;
                kp = s + NX_;
                vp = s + 2 * NX_;
            }
            const float4 kv = *(const float4*)(kp + c4);
            const float4 vv = *(const float4*)(vp + c4);
            uint32_t* kd = Ksu + t * KSTRIDE + c4;
            kd[0] = f2tf32(kv.x); kd[1] = f2tf32(kv.y);
            kd[2] = f2tf32(kv.z); kd[3] = f2tf32(kv.w);
            uint32_t* vd = Vsu + t * KSTRIDE + c4;
            vd[0] = f2tf32(vv.x); vd[1] = f2tf32(vv.y);
            vd[2] = f2tf32(vv.z); vd[3] = f2tf32(vv.w);
        }
        if (tid < 64) {
            const int t = t0k + tid;
            Cb[tid] = (t < P_) ? (1.f - Mmask[b * P_ + t]) * -10000.f
                               : amask[b * S_ + (t - P_)];
        }
        __syncthreads();

        // ---- S = Q @ K^T via tensor cores ----
        float s[8][4];
#pragma unroll
        for (int nf = 0; nf < 8; nf++)
#pragma unroll
            for (int j = 0; j < 4; j++) s[nf][j] = 0.f;

#pragma unroll
        for (int kf = 0; kf < 8; kf++) {
#pragma unroll
            for (int nf = 0; nf < 8; nf++) {
                const uint32_t kb0 = Ksu[(8 * nf + gr) * KSTRIDE + 8 * kf + tg];
                const uint32_t kb1 = Ksu[(8 * nf + gr) * KSTRIDE + 8 * kf + tg + 4];
                mma_tf32(s[nf], aQ[kf], kb0, kb1);
            }
        }

        // ---- Mask + online softmax (rows live in 4-lane groups) ----
        float mx0 = -1e30f, mx1 = -1e30f;
#pragma unroll
        for (int nf = 0; nf < 8; nf++) {
            const int tc = t0k + 8 * nf + 2 * tg;
            const float cb0 = Cb[8 * nf + 2 * tg];
            const float cb1 = Cb[8 * nf + 2 * tg + 1];
            const int ts0 = tc - P_;          // self index (neg for memory cols)
            const int ts1 = ts0 + 1;
            const float l00 = (ts0 <= r0g ? s[nf][0] : -10000.f) + cb0;
            const float l01 = (ts1 <= r0g ? s[nf][1] : -10000.f) + cb1;
            const float l10 = (ts0 <= r1g ? s[nf][2] : -10000.f) + cb0;
            const float l11 = (ts1 <= r1g ? s[nf][3] : -10000.f) + cb1;
            s[nf][0] = l00; s[nf][1] = l01; s[nf][2] = l10; s[nf][3] = l11;
            mx0 = fmaxf(mx0, fmaxf(l00, l01));
            mx1 = fmaxf(mx1, fmaxf(l10, l11));
        }
        mx0 = fmaxf(mx0, __shfl_xor_sync(0xffffffffu, mx0, 1));
        mx0 = fmaxf(mx0, __shfl_xor_sync(0xffffffffu, mx0, 2));
        mx1 = fmaxf(mx1, __shfl_xor_sync(0xffffffffu, mx1, 1));
        mx1 = fmaxf(mx1, __shfl_xor_sync(0xffffffffu, mx1, 2));

        const float nm0 = fmaxf(m0, mx0);
        const float nm1 = fmaxf(m1, mx1);
        const float al0 = __expf(m0 - nm0);
        const float al1 = __expf(m1 - nm1);
        float ps0 = 0.f, ps1 = 0.f;
#pragma unroll
        for (int nf = 0; nf < 8; nf++) {
            const float p00 = __expf(s[nf][0] - nm0);
            const float p01 = __expf(s[nf][1] - nm0);
            const float p10 = __expf(s[nf][2] - nm1);
            const float p11 = __expf(s[nf][3] - nm1);
            ps0 += p00 + p01;
            ps1 += p10 + p11;
            Pswu[gr * KSTRIDE + 8 * nf + 2 * tg]       = f2tf32(p00);
            Pswu[gr * KSTRIDE + 8 * nf + 2 * tg + 1]   = f2tf32(p01);
            Pswu[(gr + 8) * KSTRIDE + 8 * nf + 2 * tg]     = f2tf32(p10);
            Pswu[(gr + 8) * KSTRIDE + 8 * nf + 2 * tg + 1] = f2tf32(p11);
        }
        ps0 += __shfl_xor_sync(0xffffffffu, ps0, 1);
        ps0 += __shfl_xor_sync(0xffffffffu, ps0, 2);
        ps1 += __shfl_xor_sync(0xffffffffu, ps1, 1);
        ps1 += __shfl_xor_sync(0xffffffffu, ps1, 2);
        l0 = l0 * al0 + ps0;
        l1 = l1 * al1 + ps1;
        m0 = nm0; m1 = nm1;

#pragma unroll
        for (int nf = 0; nf < 8; nf++) {
            o[nf][0] *= al0; o[nf][1] *= al0;
            o[nf][2] *= al1; o[nf][3] *= al1;
        }
        __syncwarp();

        // ---- O += P @ V via tensor cores (P re-laid-out through smem) ----
#pragma unroll
        for (int kf = 0; kf < 8; kf++) {
            uint32_t aP[4];
            aP[0] = Pswu[gr * KSTRIDE + 8 * kf + tg];
            aP[1] = Pswu[(gr + 8) * KSTRIDE + 8 * kf + tg];
            aP[2] = Pswu[gr * KSTRIDE + 8 * kf + tg + 4];
            aP[3] = Pswu[(gr + 8) * KSTRIDE + 8 * kf + tg + 4];
#pragma unroll
            for (int nf = 0; nf < 8; nf++) {
                const uint32_t vb0 = Vsu[(8 * kf + tg) * KSTRIDE + 8 * nf + gr];
                const uint32_t vb1 = Vsu[(8 * kf + tg + 4) * KSTRIDE + 8 * nf + gr];
                mma_tf32(o[nf], aP, vb0, vb1);
            }
        }
    }

    // ---- Epilogue ----
    const float inv0 = 1.f / l0;
    const float inv1 = 1.f / l1;
#pragma unroll
    for (int nf = 0; nf < 8; nf++) {
        const size_t base0 = (size_t)(b * S_ + r0g) * NX_ + h * DH_ + 8 * nf + 2 * tg;
        const size_t base1 = (size_t)(b * S_ + r1g) * NX_ + h * DH_ + 8 * nf + 2 * tg;
        float2 v0, v1;
        v0.x = o[nf][0] * inv0; v0.y = o[nf][1] * inv0;
        v1.x = o[nf][2] * inv1; v1.y = o[nf][3] * inv1;
        *(float2*)(out + base0) = v0;
        *(float2*)(out + base1) = v1;
    }
}

// ----------------------------------------------------------------------------
// Launch
// ----------------------------------------------------------------------------
extern "C" void kernel_launch(void* const* d_in, const int* in_sizes, int n_in,
                              void* d_out, int out_size)
{
    const float* x      = (const float*)d_in[0];
    const float* M      = (const float*)d_in[1];
    const float* Mmask  = (const float*)d_in[2];
    const float* amask  = (const float*)d_in[3];
    const float* W_attn = (const float*)d_in[4];
    const float* b_attn = (const float*)d_in[5];
    const float* W_mem  = (const float*)d_in[6];
    const float* b_mem  = (const float*)d_in[7];
    const float* W_proj = (const float*)d_in[8];
    const float* b_proj = (const float*)d_in[9];
    float* out = (float*)d_out;

    float* qkv; cudaGetSymbolAddress((void**)&qkv, g_qkv);
    float* ekv; cudaGetSymbolAddress((void**)&ekv, g_ekv);
    float* a;   cudaGetSymbolAddress((void**)&a,   g_a);

    cudaFuncSetAttribute(attn_mma, cudaFuncAttributeMaxDynamicSharedMemorySize,
                         ATTN_SMEM);

    // 1) qkv = x @ W_attn + b_attn
    {
        dim3 grid(3 * NX_ / 128, BS_ / 128);
        sgemm_bias<<<grid, 256>>>(x, W_attn, b_attn, qkv, BS_, 3 * NX_, NX_);
    }
    // 2) ekv = M @ W_mem + b_mem
    {
        dim3 grid(2 * NX_ / 128, BP_ / 128);
        sgemm_bias<<<grid, 256>>>(M, W_mem, b_mem, ekv, BP_, 2 * NX_, NX_);
    }
    // 3) flash attention (tensor cores) -> a
    {
        dim3 grid(S_ / 128, B_ * H_);
        attn_mma<<<grid, 256, ATTN_SMEM>>>(qkv, ekv, Mmask, amask, a);
    }
    // 4) out = a @ W_proj + b_proj
    {
        dim3 grid(NX_ / 128, BS_ / 128);
        sgemm_bias<<<grid, 256>>>(a, W_proj, b_proj, out, BS_, NX_, NX_);
    }
}

// round 4
// speedup vs baseline: 5.0664x; 1.8799x over previous
#include <cuda_runtime.h>
#include <cuda_bf16.h>
#include <cstdint>

// Problem constants
#define B_   4
#define S_   1024
#define P_   128
#define NX_  1024
#define H_   16
#define DH_  64
#define T_   (P_ + S_)      // 1152
#define BS_  (B_ * S_)      // 4096
#define BP_  (B_ * P_)      // 512

// Scratch (static device globals; no allocation allowed)
__device__ float g_qkv[(size_t)BS_ * 3 * NX_];   // [4096, 3072]
__device__ float g_ekv[(size_t)BP_ * 2 * NX_];   // [512, 2048]
__device__ float g_a  [(size_t)BS_ * NX_];       // [4096, 1024]

// ----------------------------------------------------------------------------
// Common MMA helpers
// ----------------------------------------------------------------------------
__device__ __forceinline__ uint32_t f2tf32(float x) {
    uint32_t u;
    asm("cvt.rna.tf32.f32 %0, %1;" : "=r"(u) : "f"(x));
    return u;
}

__device__ __forceinline__ void mma_tf32(float c[4], const uint32_t a[4],
                                         uint32_t b0, uint32_t b1) {
    asm volatile(
        "mma.sync.aligned.m16n8k8.row.col.f32.tf32.tf32.f32 "
        "{%0,%1,%2,%3}, {%4,%5,%6,%7}, {%8,%9}, {%0,%1,%2,%3};"
        : "+f"(c[0]), "+f"(c[1]), "+f"(c[2]), "+f"(c[3])
        : "r"(a[0]), "r"(a[1]), "r"(a[2]), "r"(a[3]), "r"(b0), "r"(b1));
}

__device__ __forceinline__ void ldsm_x4(uint32_t& r0, uint32_t& r1,
                                        uint32_t& r2, uint32_t& r3,
                                        const void* p) {
    uint32_t a = (uint32_t)__cvta_generic_to_shared(p);
    asm volatile("ldmatrix.sync.aligned.m8n8.x4.shared.b16 {%0,%1,%2,%3}, [%4];"
                 : "=r"(r0), "=r"(r1), "=r"(r2), "=r"(r3) : "r"(a));
}

// ----------------------------------------------------------------------------
// tf32 tensor-core GEMM: C[M,N] = A[M,K] @ B[K,N] + bias[N]
// Block 128x128, 8 warps (4M x 2N), warp tile m32 x n64, K-chunk 32.
// smem: As [m][k] stride 36, Bs [n][k] stride 36 (tf32-rounded at stage time).
// Fragments via ldmatrix.x4 (tf32-as-2xb16, non-transposed).
// Requires M%128==0, N%128==0, K%32==0.
// ----------------------------------------------------------------------------
#define GST 36

__global__ __launch_bounds__(256) void tf32_gemm_bias(
    const float* __restrict__ A, const float* __restrict__ B,
    const float* __restrict__ bias, float* __restrict__ C,
    int M, int N, int K)
{
    __shared__ uint32_t As[128 * GST];
    __shared__ uint32_t Bs[128 * GST];

    const int tid = threadIdx.x;
    const int w = tid >> 5, lane = tid & 31;
    const int gr = lane >> 2, tg = lane & 3;
    const int m0w = (w & 3) * 32;
    const int n0w = (w >> 2) * 64;

    const int lq = lane >> 3;
    const int lr = lane & 7;
    // ldmatrix lane address offsets (see fragment maps)
    const int a_row = lr + ((lq & 1) << 3);       // + m-base
    const int a_col = (lq >> 1) << 2;             // + 8*kf
    const int b_row = lr + ((lq >> 1) << 3);      // + n-base
    const int b_col = (lq & 1) << 2;              // + 8*kf

    const float* Ag = A + (size_t)(blockIdx.y * 128) * K;
    const float* Bg = B + blockIdx.x * 128;

    // Staging indices
    const int sa_row = tid >> 1;                  // unused pattern variant
    (void)sa_row;
    const int bkr = lane & 7;                     // B k-row within 8-group
    const int bc4 = ((w << 2) + (lane >> 3)) << 2;// B n-column (float4)

    float c[2][8][4];
#pragma unroll
    for (int mi = 0; mi < 2; mi++)
#pragma unroll
        for (int nf = 0; nf < 8; nf++)
#pragma unroll
            for (int j = 0; j < 4; j++) c[mi][nf][j] = 0.f;

    const int nk = K >> 5;
    float4 ra[4], rb[4];

    // Load chunk 0
#pragma unroll
    for (int it = 0; it < 4; it++) {
        const int fid = tid + it * 256;
        const int row = fid >> 3;
        const int c4 = (fid & 7) << 2;
        ra[it] = *(const float4*)(Ag + (size_t)row * K + c4);
        rb[it] = *(const float4*)(Bg + (size_t)(it * 8 + bkr) * N + bc4);
    }

    for (int kc = 0; kc < nk; kc++) {
        __syncthreads();
        // Store staged chunk (tf32-rounded)
#pragma unroll
        for (int it = 0; it < 4; it++) {
            const int fid = tid + it * 256;
            const int row = fid >> 3;
            const int c4 = (fid & 7) << 2;
            uint4 ua;
            ua.x = f2tf32(ra[it].x); ua.y = f2tf32(ra[it].y);
            ua.z = f2tf32(ra[it].z); ua.w = f2tf32(ra[it].w);
            *(uint4*)(As + row * GST + c4) = ua;
            const int kr = it * 8 + bkr;
            Bs[(bc4 + 0) * GST + kr] = f2tf32(rb[it].x);
            Bs[(bc4 + 1) * GST + kr] = f2tf32(rb[it].y);
            Bs[(bc4 + 2) * GST + kr] = f2tf32(rb[it].z);
            Bs[(bc4 + 3) * GST + kr] = f2tf32(rb[it].w);
        }
        __syncthreads();

        // Prefetch next chunk (overlaps with MMA below)
        if (kc + 1 < nk) {
            const int k0 = (kc + 1) << 5;
#pragma unroll
            for (int it = 0; it < 4; it++) {
                const int fid = tid + it * 256;
                const int row = fid >> 3;
                const int c4 = (fid & 7) << 2;
                ra[it] = *(const float4*)(Ag + (size_t)row * K + k0 + c4);
                rb[it] = *(const float4*)(Bg + (size_t)(k0 + it * 8 + bkr) * N + bc4);
            }
        }

        // Compute
#pragma unroll
        for (int kf = 0; kf < 4; kf++) {
            const int kb = kf << 3;
            uint32_t a0[4], a1[4];
            ldsm_x4(a0[0], a0[1], a0[2], a0[3],
                    As + (m0w + a_row) * GST + kb + a_col);
            ldsm_x4(a1[0], a1[1], a1[2], a1[3],
                    As + (m0w + 16 + a_row) * GST + kb + a_col);
#pragma unroll
            for (int p = 0; p < 4; p++) {
                uint32_t b0, b1, b2, b3;
                ldsm_x4(b0, b1, b2, b3,
                        Bs + (n0w + 16 * p + b_row) * GST + kb + b_col);
                mma_tf32(c[0][2 * p],     a0, b0, b1);
                mma_tf32(c[1][2 * p],     a1, b0, b1);
                mma_tf32(c[0][2 * p + 1], a0, b2, b3);
                mma_tf32(c[1][2 * p + 1], a1, b2, b3);
            }
        }
    }

    // Epilogue with bias
#pragma unroll
    for (int nf = 0; nf < 8; nf++) {
        const int col = blockIdx.x * 128 + n0w + 8 * nf + 2 * tg;
        const float bb0 = bias[col];
        const float bb1 = bias[col + 1];
#pragma unroll
        for (int mi = 0; mi < 2; mi++) {
            const size_t r0 = (size_t)(blockIdx.y * 128 + m0w + 16 * mi + gr);
            float2 v0, v1;
            v0.x = c[mi][nf][0] + bb0; v0.y = c[mi][nf][1] + bb1;
            v1.x = c[mi][nf][2] + bb0; v1.y = c[mi][nf][3] + bb1;
            *(float2*)(C + r0 * N + col)       = v0;
            *(float2*)(C + (r0 + 8) * N + col) = v1;
        }
    }
}

// ----------------------------------------------------------------------------
// Flash attention with tf32 tensor cores (unchanged from R3).
// ----------------------------------------------------------------------------
#define KSTRIDE 68
#define ATTN_SMEM ((2 * 64 * KSTRIDE + 8 * 16 * KSTRIDE + 64) * 4)

__global__ __launch_bounds__(256) void attn_mma(
    const float* __restrict__ qkv,   // [BS, 3*NX]
    const float* __restrict__ ekv,   // [BP, 2*NX]
    const float* __restrict__ Mmask, // [B, P]
    const float* __restrict__ amask, // [B,1,1,S]
    float* __restrict__ out)         // [BS, NX]
{
    extern __shared__ float sm[];
    float* Ks = sm;                          // [64][68]
    float* Vs = sm + 64 * KSTRIDE;           // [64][68]
    float* Ps = sm + 2 * 64 * KSTRIDE;       // [8][16][68]
    float* Cb = Ps + 8 * 16 * KSTRIDE;       // [64]
    uint32_t* Ksu = (uint32_t*)Ks;
    uint32_t* Vsu = (uint32_t*)Vs;
    uint32_t* Qtu = (uint32_t*)sm;           // Q staged over Ks+Vs: [128][68]

    const int bh = blockIdx.y;
    const int b = bh >> 4, h = bh & 15;
    const int q0 = blockIdx.x * 128;
    const int tid = threadIdx.x;
    const int w = tid >> 5;
    const int lane = tid & 31;
    const int gr = lane >> 2;
    const int tg = lane & 3;

    // ---- Stage Q (scaled 1/8, tf32-rounded) into Qtmp [128][68] ----
#pragma unroll
    for (int it = 0; it < 8; it++) {
        const int fid = tid + it * 256;
        const int r = fid >> 4;
        const int c4 = (fid & 15) * 4;
        const float4 q = *(const float4*)(
            qkv + (size_t)(b * S_ + q0 + r) * (3 * NX_) + h * DH_ + c4);
        uint32_t* d = Qtu + r * KSTRIDE + c4;
        d[0] = f2tf32(q.x * 0.125f);
        d[1] = f2tf32(q.y * 0.125f);
        d[2] = f2tf32(q.z * 0.125f);
        d[3] = f2tf32(q.w * 0.125f);
    }
    __syncthreads();

    uint32_t aQ[8][4];
    {
        const int r0 = 16 * w + gr;
#pragma unroll
        for (int kf = 0; kf < 8; kf++) {
            aQ[kf][0] = Qtu[r0 * KSTRIDE + 8 * kf + tg];
            aQ[kf][1] = Qtu[(r0 + 8) * KSTRIDE + 8 * kf + tg];
            aQ[kf][2] = Qtu[r0 * KSTRIDE + 8 * kf + tg + 4];
            aQ[kf][3] = Qtu[(r0 + 8) * KSTRIDE + 8 * kf + tg + 4];
        }
    }

    float m0 = -1e30f, m1 = -1e30f, l0 = 0.f, l1 = 0.f;
    float o[8][4];
#pragma unroll
    for (int nf = 0; nf < 8; nf++)
#pragma unroll
        for (int j = 0; j < 4; j++) o[nf][j] = 0.f;

    uint32_t* Pswu = (uint32_t*)(Ps + w * 16 * KSTRIDE);
    const int r0g = q0 + 16 * w + gr;
    const int r1g = r0g + 8;
    const int ntiles = 2 * blockIdx.x + 4;

    for (int kt = 0; kt < ntiles; kt++) {
        const int t0k = kt * 64;
        __syncthreads();

#pragma unroll
        for (int it = 0; it < 4; it++) {
            const int fid = tid + it * 256;
            const int t = fid >> 4;
            const int c4 = (fid & 15) * 4;
            const int tg_ = t0k + t;
            const float* kp;
            const float* vp;
            if (tg_ < P_) {
                const float* e = ekv + (size_t)(b * P_ + tg_) * (2 * NX_) + h * DH_;
                kp = e;
                vp = e + NX_;
            } else {
                const float* s = qkv + (size_t)(b * S_ + tg_ - P_) * (3 * NX_) + h * DH_;
                kp = s + NX_;
                vp = s + 2 * NX_;
            }
            const float4 kv = *(const float4*)(kp + c4);
            const float4 vv = *(const float4*)(vp + c4);
            uint32_t* kd = Ksu + t * KSTRIDE + c4;
            kd[0] = f2tf32(kv.x); kd[1] = f2tf32(kv.y);
            kd[2] = f2tf32(kv.z); kd[3] = f2tf32(kv.w);
            uint32_t* vd = Vsu + t * KSTRIDE + c4;
            vd[0] = f2tf32(vv.x); vd[1] = f2tf32(vv.y);
            vd[2] = f2tf32(vv.z); vd[3] = f2tf32(vv.w);
        }
        if (tid < 64) {
            const int t = t0k + tid;
            Cb[tid] = (t < P_) ? (1.f - Mmask[b * P_ + t]) * -10000.f
                               : amask[b * S_ + (t - P_)];
        }
        __syncthreads();

        float s[8][4];
#pragma unroll
        for (int nf = 0; nf < 8; nf++)
#pragma unroll
            for (int j = 0; j < 4; j++) s[nf][j] = 0.f;

#pragma unroll
        for (int kf = 0; kf < 8; kf++) {
#pragma unroll
            for (int nf = 0; nf < 8; nf++) {
                const uint32_t kb0 = Ksu[(8 * nf + gr) * KSTRIDE + 8 * kf + tg];
                const uint32_t kb1 = Ksu[(8 * nf + gr) * KSTRIDE + 8 * kf + tg + 4];
                mma_tf32(s[nf], aQ[kf], kb0, kb1);
            }
        }

        float mx0 = -1e30f, mx1 = -1e30f;
#pragma unroll
        for (int nf = 0; nf < 8; nf++) {
            const int tc = t0k + 8 * nf + 2 * tg;
            const float cb0 = Cb[8 * nf + 2 * tg];
            const float cb1 = Cb[8 * nf + 2 * tg + 1];
            const int ts0 = tc - P_;
            const int ts1 = ts0 + 1;
            const float l00 = (ts0 <= r0g ? s[nf][0] : -10000.f) + cb0;
            const float l01 = (ts1 <= r0g ? s[nf][1] : -10000.f) + cb1;
            const float l10 = (ts0 <= r1g ? s[nf][2] : -10000.f) + cb0;
            const float l11 = (ts1 <= r1g ? s[nf][3] : -10000.f) + cb1;
            s[nf][0] = l00; s[nf][1] = l01; s[nf][2] = l10; s[nf][3] = l11;
            mx0 = fmaxf(mx0, fmaxf(l00, l01));
            mx1 = fmaxf(mx1, fmaxf(l10, l11));
        }
        mx0 = fmaxf(mx0, __shfl_xor_sync(0xffffffffu, mx0, 1));
        mx0 = fmaxf(mx0, __shfl_xor_sync(0xffffffffu, mx0, 2));
        mx1 = fmaxf(mx1, __shfl_xor_sync(0xffffffffu, mx1, 1));
        mx1 = fmaxf(mx1, __shfl_xor_sync(0xffffffffu, mx1, 2));

        const float nm0 = fmaxf(m0, mx0);
        const float nm1 = fmaxf(m1, mx1);
        const float al0 = __expf(m0 - nm0);
        const float al1 = __expf(m1 - nm1);
        float ps0 = 0.f, ps1 = 0.f;
#pragma unroll
        for (int nf = 0; nf < 8; nf++) {
            const float p00 = __expf(s[nf][0] - nm0);
            const float p01 = __expf(s[nf][1] - nm0);
            const float p10 = __expf(s[nf][2] - nm1);
            const float p11 = __expf(s[nf][3] - nm1);
            ps0 += p00 + p01;
            ps1 += p10 + p11;
            Pswu[gr * KSTRIDE + 8 * nf + 2 * tg]           = f2tf32(p00);
            Pswu[gr * KSTRIDE + 8 * nf + 2 * tg + 1]       = f2tf32(p01);
            Pswu[(gr + 8) * KSTRIDE + 8 * nf + 2 * tg]     = f2tf32(p10);
            Pswu[(gr + 8) * KSTRIDE + 8 * nf + 2 * tg + 1] = f2tf32(p11);
        }
        ps0 += __shfl_xor_sync(0xffffffffu, ps0, 1);
        ps0 += __shfl_xor_sync(0xffffffffu, ps0, 2);
        ps1 += __shfl_xor_sync(0xffffffffu, ps1, 1);
        ps1 += __shfl_xor_sync(0xffffffffu, ps1, 2);
        l0 = l0 * al0 + ps0;
        l1 = l1 * al1 + ps1;
        m0 = nm0; m1 = nm1;

#pragma unroll
        for (int nf = 0; nf < 8; nf++) {
            o[nf][0] *= al0; o[nf][1] *= al0;
            o[nf][2] *= al1; o[nf][3] *= al1;
        }
        __syncwarp();

#pragma unroll
        for (int kf = 0; kf < 8; kf++) {
            uint32_t aP[4];
            aP[0] = Pswu[gr * KSTRIDE + 8 * kf + tg];
            aP[1] = Pswu[(gr + 8) * KSTRIDE + 8 * kf + tg];
            aP[2] = Pswu[gr * KSTRIDE + 8 * kf + tg + 4];
            aP[3] = Pswu[(gr + 8) * KSTRIDE + 8 * kf + tg + 4];
#pragma unroll
            for (int nf = 0; nf < 8; nf++) {
                const uint32_t vb0 = Vsu[(8 * kf + tg) * KSTRIDE + 8 * nf + gr];
                const uint32_t vb1 = Vsu[(8 * kf + tg + 4) * KSTRIDE + 8 * nf + gr];
                mma_tf32(o[nf], aP, vb0, vb1);
            }
        }
    }

    const float inv0 = 1.f / l0;
    const float inv1 = 1.f / l1;
#pragma unroll
    for (int nf = 0; nf < 8; nf++) {
        const size_t base0 = (size_t)(b * S_ + r0g) * NX_ + h * DH_ + 8 * nf + 2 * tg;
        const size_t base1 = (size_t)(b * S_ + r1g) * NX_ + h * DH_ + 8 * nf + 2 * tg;
        float2 v0, v1;
        v0.x = o[nf][0] * inv0; v0.y = o[nf][1] * inv0;
        v1.x = o[nf][2] * inv1; v1.y = o[nf][3] * inv1;
        *(float2*)(out + base0) = v0;
        *(float2*)(out + base1) = v1;
    }
}

// ----------------------------------------------------------------------------
// Launch
// ----------------------------------------------------------------------------
extern "C" void kernel_launch(void* const* d_in, const int* in_sizes, int n_in,
                              void* d_out, int out_size)
{
    const float* x      = (const float*)d_in[0];
    const float* M      = (const float*)d_in[1];
    const float* Mmask  = (const float*)d_in[2];
    const float* amask  = (const float*)d_in[3];
    const float* W_attn = (const float*)d_in[4];
    const float* b_attn = (const float*)d_in[5];
    const float* W_mem  = (const float*)d_in[6];
    const float* b_mem  = (const float*)d_in[7];
    const float* W_proj = (const float*)d_in[8];
    const float* b_proj = (const float*)d_in[9];
    float* out = (float*)d_out;

    float* qkv; cudaGetSymbolAddress((void**)&qkv, g_qkv);
    float* ekv; cudaGetSymbolAddress((void**)&ekv, g_ekv);
    float* a;   cudaGetSymbolAddress((void**)&a,   g_a);

    cudaFuncSetAttribute(attn_mma, cudaFuncAttributeMaxDynamicSharedMemorySize,
                         ATTN_SMEM);

    // 1) qkv = x @ W_attn + b_attn
    {
        dim3 grid(3 * NX_ / 128, BS_ / 128);
        tf32_gemm_bias<<<grid, 256>>>(x, W_attn, b_attn, qkv, BS_, 3 * NX_, NX_);
    }
    // 2) ekv = M @ W_mem + b_mem
    {
        dim3 grid(2 * NX_ / 128, BP_ / 128);
        tf32_gemm_bias<<<grid, 256>>>(M, W_mem, b_mem, ekv, BP_, 2 * NX_, NX_);
    }
    // 3) flash attention (tensor cores) -> a
    {
        dim3 grid(S_ / 128, B_ * H_);
        attn_mma<<<grid, 256, ATTN_SMEM>>>(qkv, ekv, Mmask, amask, a);
    }
    // 4) out = a @ W_proj + b_proj
    {
        dim3 grid(NX_ / 128, BS_ / 128);
        tf32_gemm_bias<<<grid, 256>>>(a, W_proj, b_proj, out, BS_, NX_, NX_);
    }
}

// round 5
// speedup vs baseline: 5.0879x; 1.0042x over previous
#include <cuda_runtime.h>
#include <cuda_bf16.h>
#include <cstdint>

// Problem constants
#define B_   4
#define S_   1024
#define P_   128
#define NX_  1024
#define H_   16
#define DH_  64
#define T_   (P_ + S_)      // 1152
#define BS_  (B_ * S_)      // 4096
#define BP_  (B_ * P_)      // 512

// Scratch (static device globals; no allocation allowed)
__device__ float g_qkv[(size_t)BS_ * 3 * NX_];   // [4096, 3072]
__device__ float g_ekv[(size_t)BP_ * 2 * NX_];   // [512, 2048]
__device__ float g_a  [(size_t)BS_ * NX_];       // [4096, 1024]

// ----------------------------------------------------------------------------
// Common MMA helpers
// ----------------------------------------------------------------------------
__device__ __forceinline__ uint32_t f2tf32(float x) {
    uint32_t u;
    asm("cvt.rna.tf32.f32 %0, %1;" : "=r"(u) : "f"(x));
    return u;
}

__device__ __forceinline__ void mma_tf32(float c[4], const uint32_t a[4],
                                         uint32_t b0, uint32_t b1) {
    asm volatile(
        "mma.sync.aligned.m16n8k8.row.col.f32.tf32.tf32.f32 "
        "{%0,%1,%2,%3}, {%4,%5,%6,%7}, {%8,%9}, {%0,%1,%2,%3};"
        : "+f"(c[0]), "+f"(c[1]), "+f"(c[2]), "+f"(c[3])
        : "r"(a[0]), "r"(a[1]), "r"(a[2]), "r"(a[3]), "r"(b0), "r"(b1));
}

__device__ __forceinline__ void ldsm_x4(uint32_t& r0, uint32_t& r1,
                                        uint32_t& r2, uint32_t& r3,
                                        const void* p) {
    uint32_t a = (uint32_t)__cvta_generic_to_shared(p);
    asm volatile("ldmatrix.sync.aligned.m8n8.x4.shared.b16 {%0,%1,%2,%3}, [%4];"
                 : "=r"(r0), "=r"(r1), "=r"(r2), "=r"(r3) : "r"(a));
}

// ----------------------------------------------------------------------------
// tf32 tensor-core GEMM, double-buffered: C[M,N] = A[M,K] @ B[K,N] + bias[N]
// Block 128x128, 16 warps (4M x 4N), warp tile m32 x n32, K-chunk 32,
// 2-stage smem pipeline, one __syncthreads per chunk.
// smem: per stage As [m=128][k=32] stride 36, Bs [n=128][k=32] stride 36.
// Requires M%128==0, N%128==0, K%32==0.
// ----------------------------------------------------------------------------
#define GST 36
#define GEMM_STAGE (128 * GST)
#define GEMM_SMEM (4 * GEMM_STAGE * 4)   // 2 stages x (As+Bs) x 4B = 73728

__global__ __launch_bounds__(512, 1) void tf32_gemm_bias(
    const float* __restrict__ A, const float* __restrict__ B,
    const float* __restrict__ bias, float* __restrict__ C,
    int M, int N, int K)
{
    extern __shared__ uint32_t smg[];
    // layout: [stage0 As][stage0 Bs][stage1 As][stage1 Bs]

    const int tid = threadIdx.x;
    const int w = tid >> 5, lane = tid & 31;
    const int gr = lane >> 2, tg = lane & 3;
    const int m0w = (w & 3) * 32;
    const int n0w = (w >> 2) * 32;

    const int lq = lane >> 3;
    const int lr = lane & 7;
    const int a_row = lr + ((lq & 1) << 3);
    const int a_col = (lq >> 1) << 2;
    const int b_row = lr + ((lq >> 1) << 3);
    const int b_col = (lq & 1) << 2;

    const float* Ag = A + (size_t)(blockIdx.y * 128) * K;
    const float* Bg = B + blockIdx.x * 128;

    // A staging: fid -> (row, c4)
    const int a_srow0 = tid >> 3;            // + 64*it
    const int a_sc4 = (tid & 7) << 2;
    // B staging: fid -> (kr, bc4, kgrp)
    const int b_kr = tid & 7;
    const int b_c4 = ((tid >> 3) & 31) << 2;
    const int b_kg0 = tid >> 8;              // 0..1 ; +2*it

    float c[2][4][4];
#pragma unroll
    for (int mi = 0; mi < 2; mi++)
#pragma unroll
        for (int nf = 0; nf < 4; nf++)
#pragma unroll
            for (int j = 0; j < 4; j++) c[mi][nf][j] = 0.f;

    const int nk = K >> 5;
    float4 ra[2], rb[2];

    // Load chunk 0
#pragma unroll
    for (int it = 0; it < 2; it++) {
        ra[it] = *(const float4*)(Ag + (size_t)(a_srow0 + 64 * it) * K + a_sc4);
        rb[it] = *(const float4*)(Bg + (size_t)((b_kg0 + 2 * it) * 8 + b_kr) * N + b_c4);
    }

    for (int kc = 0; kc < nk; kc++) {
        uint32_t* As = smg + (kc & 1) * 2 * GEMM_STAGE;
        uint32_t* Bs = As + GEMM_STAGE;

        // Store staged chunk (tf32-rounded)
#pragma unroll
        for (int it = 0; it < 2; it++) {
            uint4 ua;
            ua.x = f2tf32(ra[it].x); ua.y = f2tf32(ra[it].y);
            ua.z = f2tf32(ra[it].z); ua.w = f2tf32(ra[it].w);
            *(uint4*)(As + (a_srow0 + 64 * it) * GST + a_sc4) = ua;
            const int kr = (b_kg0 + 2 * it) * 8 + b_kr;
            Bs[(b_c4 + 0) * GST + kr] = f2tf32(rb[it].x);
            Bs[(b_c4 + 1) * GST + kr] = f2tf32(rb[it].y);
            Bs[(b_c4 + 2) * GST + kr] = f2tf32(rb[it].z);
            Bs[(b_c4 + 3) * GST + kr] = f2tf32(rb[it].w);
        }
        __syncthreads();

        // Prefetch next chunk (overlaps the MMAs below)
        if (kc + 1 < nk) {
            const int k0 = (kc + 1) << 5;
#pragma unroll
            for (int it = 0; it < 2; it++) {
                ra[it] = *(const float4*)(Ag + (size_t)(a_srow0 + 64 * it) * K + k0 + a_sc4);
                rb[it] = *(const float4*)(Bg + (size_t)(k0 + (b_kg0 + 2 * it) * 8 + b_kr) * N + b_c4);
            }
        }

        // Compute: 4 kf x (2 a-ldsm + 2 b-ldsm + 8 mma)
#pragma unroll
        for (int kf = 0; kf < 4; kf++) {
            const int kb = kf << 3;
            uint32_t a0[4], a1[4];
            ldsm_x4(a0[0], a0[1], a0[2], a0[3],
                    As + (m0w + a_row) * GST + kb + a_col);
            ldsm_x4(a1[0], a1[1], a1[2], a1[3],
                    As + (m0w + 16 + a_row) * GST + kb + a_col);
#pragma unroll
            for (int p = 0; p < 2; p++) {
                uint32_t b0, b1, b2, b3;
                ldsm_x4(b0, b1, b2, b3,
                        Bs + (n0w + 16 * p + b_row) * GST + kb + b_col);
                mma_tf32(c[0][2 * p],     a0, b0, b1);
                mma_tf32(c[1][2 * p],     a1, b0, b1);
                mma_tf32(c[0][2 * p + 1], a0, b2, b3);
                mma_tf32(c[1][2 * p + 1], a1, b2, b3);
            }
        }
    }

    // Epilogue with bias
#pragma unroll
    for (int nf = 0; nf < 4; nf++) {
        const int col = blockIdx.x * 128 + n0w + 8 * nf + 2 * tg;
        const float bb0 = bias[col];
        const float bb1 = bias[col + 1];
#pragma unroll
        for (int mi = 0; mi < 2; mi++) {
            const size_t r0 = (size_t)(blockIdx.y * 128 + m0w + 16 * mi + gr);
            float2 v0, v1;
            v0.x = c[mi][nf][0] + bb0; v0.y = c[mi][nf][1] + bb1;
            v1.x = c[mi][nf][2] + bb0; v1.y = c[mi][nf][3] + bb1;
            *(float2*)(C + r0 * N + col)       = v0;
            *(float2*)(C + (r0 + 8) * N + col) = v1;
        }
    }
}

// ----------------------------------------------------------------------------
// Flash attention with tf32 tensor cores (unchanged from R4).
// ----------------------------------------------------------------------------
#define KSTRIDE 68
#define ATTN_SMEM ((2 * 64 * KSTRIDE + 8 * 16 * KSTRIDE + 64) * 4)

__global__ __launch_bounds__(256) void attn_mma(
    const float* __restrict__ qkv,   // [BS, 3*NX]
    const float* __restrict__ ekv,   // [BP, 2*NX]
    const float* __restrict__ Mmask, // [B, P]
    const float* __restrict__ amask, // [B,1,1,S]
    float* __restrict__ out)         // [BS, NX]
{
    extern __shared__ float sm[];
    float* Ks = sm;                          // [64][68]
    float* Vs = sm + 64 * KSTRIDE;           // [64][68]
    float* Ps = sm + 2 * 64 * KSTRIDE;       // [8][16][68]
    float* Cb = Ps + 8 * 16 * KSTRIDE;       // [64]
    uint32_t* Ksu = (uint32_t*)Ks;
    uint32_t* Vsu = (uint32_t*)Vs;
    uint32_t* Qtu = (uint32_t*)sm;           // Q staged over Ks+Vs: [128][68]

    const int bh = blockIdx.y;
    const int b = bh >> 4, h = bh & 15;
    const int q0 = blockIdx.x * 128;
    const int tid = threadIdx.x;
    const int w = tid >> 5;
    const int lane = tid & 31;
    const int gr = lane >> 2;
    const int tg = lane & 3;

    // ---- Stage Q (scaled 1/8, tf32-rounded) into Qtmp [128][68] ----
#pragma unroll
    for (int it = 0; it < 8; it++) {
        const int fid = tid + it * 256;
        const int r = fid >> 4;
        const int c4 = (fid & 15) * 4;
        const float4 q = *(const float4*)(
            qkv + (size_t)(b * S_ + q0 + r) * (3 * NX_) + h * DH_ + c4);
        uint32_t* d = Qtu + r * KSTRIDE + c4;
        d[0] = f2tf32(q.x * 0.125f);
        d[1] = f2tf32(q.y * 0.125f);
        d[2] = f2tf32(q.z * 0.125f);
        d[3] = f2tf32(q.w * 0.125f);
    }
    __syncthreads();

    uint32_t aQ[8][4];
    {
        const int r0 = 16 * w + gr;
#pragma unroll
        for (int kf = 0; kf < 8; kf++) {
            aQ[kf][0] = Qtu[r0 * KSTRIDE + 8 * kf + tg];
            aQ[kf][1] = Qtu[(r0 + 8) * KSTRIDE + 8 * kf + tg];
            aQ[kf][2] = Qtu[r0 * KSTRIDE + 8 * kf + tg + 4];
            aQ[kf][3] = Qtu[(r0 + 8) * KSTRIDE + 8 * kf + tg + 4];
        }
    }

    float m0 = -1e30f, m1 = -1e30f, l0 = 0.f, l1 = 0.f;
    float o[8][4];
#pragma unroll
    for (int nf = 0; nf < 8; nf++)
#pragma unroll
        for (int j = 0; j < 4; j++) o[nf][j] = 0.f;

    uint32_t* Pswu = (uint32_t*)(Ps + w * 16 * KSTRIDE);
    const int r0g = q0 + 16 * w + gr;
    const int r1g = r0g + 8;
    const int ntiles = 2 * blockIdx.x + 4;

    for (int kt = 0; kt < ntiles; kt++) {
        const int t0k = kt * 64;
        __syncthreads();

#pragma unroll
        for (int it = 0; it < 4; it++) {
            const int fid = tid + it * 256;
            const int t = fid >> 4;
            const int c4 = (fid & 15) * 4;
            const int tg_ = t0k + t;
            const float* kp;
            const float* vp;
            if (tg_ < P_) {
                const float* e = ekv + (size_t)(b * P_ + tg_) * (2 * NX_) + h * DH_;
                kp = e;
                vp = e + NX_;
            } else {
                const float* s = qkv + (size_t)(b * S_ + tg_ - P_) * (3 * NX_) + h * DH_;
                kp = s + NX_;
                vp = s + 2 * NX_;
            }
            const float4 kv = *(const float4*)(kp + c4);
            const float4 vv = *(const float4*)(vp + c4);
            uint32_t* kd = Ksu + t * KSTRIDE + c4;
            kd[0] = f2tf32(kv.x); kd[1] = f2tf32(kv.y);
            kd[2] = f2tf32(kv.z); kd[3] = f2tf32(kv.w);
            uint32_t* vd = Vsu + t * KSTRIDE + c4;
            vd[0] = f2tf32(vv.x); vd[1] = f2tf32(vv.y);
            vd[2] = f2tf32(vv.z); vd[3] = f2tf32(vv.w);
        }
        if (tid < 64) {
            const int t = t0k + tid;
            Cb[tid] = (t < P_) ? (1.f - Mmask[b * P_ + t]) * -10000.f
                               : amask[b * S_ + (t - P_)];
        }
        __syncthreads();

        float s[8][4];
#pragma unroll
        for (int nf = 0; nf < 8; nf++)
#pragma unroll
            for (int j = 0; j < 4; j++) s[nf][j] = 0.f;

#pragma unroll
        for (int kf = 0; kf < 8; kf++) {
#pragma unroll
            for (int nf = 0; nf < 8; nf++) {
                const uint32_t kb0 = Ksu[(8 * nf + gr) * KSTRIDE + 8 * kf + tg];
                const uint32_t kb1 = Ksu[(8 * nf + gr) * KSTRIDE + 8 * kf + tg + 4];
                mma_tf32(s[nf], aQ[kf], kb0, kb1);
            }
        }

        float mx0 = -1e30f, mx1 = -1e30f;
#pragma unroll
        for (int nf = 0; nf < 8; nf++) {
            const int tc = t0k + 8 * nf + 2 * tg;
            const float cb0 = Cb[8 * nf + 2 * tg];
            const float cb1 = Cb[8 * nf + 2 * tg + 1];
            const int ts0 = tc - P_;
            const int ts1 = ts0 + 1;
            const float l00 = (ts0 <= r0g ? s[nf][0] : -10000.f) + cb0;
            const float l01 = (ts1 <= r0g ? s[nf][1] : -10000.f) + cb1;
            const float l10 = (ts0 <= r1g ? s[nf][2] : -10000.f) + cb0;
            const float l11 = (ts1 <= r1g ? s[nf][3] : -10000.f) + cb1;
            s[nf][0] = l00; s[nf][1] = l01; s[nf][2] = l10; s[nf][3] = l11;
            mx0 = fmaxf(mx0, fmaxf(l00, l01));
            mx1 = fmaxf(mx1, fmaxf(l10, l11));
        }
        mx0 = fmaxf(mx0, __shfl_xor_sync(0xffffffffu, mx0, 1));
        mx0 = fmaxf(mx0, __shfl_xor_sync(0xffffffffu, mx0, 2));
        mx1 = fmaxf(mx1, __shfl_xor_sync(0xffffffffu, mx1, 1));
        mx1 = fmaxf(mx1, __shfl_xor_sync(0xffffffffu, mx1, 2));

        const float nm0 = fmaxf(m0, mx0);
        const float nm1 = fmaxf(m1, mx1);
        const float al0 = __expf(m0 - nm0);
        const float al1 = __expf(m1 - nm1);
        float ps0 = 0.f, ps1 = 0.f;
#pragma unroll
        for (int nf = 0; nf < 8; nf++) {
            const float p00 = __expf(s[nf][0] - nm0);
            const float p01 = __expf(s[nf][1] - nm0);
            const float p10 = __expf(s[nf][2] - nm1);
            const float p11 = __expf(s[nf][3] - nm1);
            ps0 += p00 + p01;
            ps1 += p10 + p11;
            Pswu[gr * KSTRIDE + 8 * nf + 2 * tg]           = f2tf32(p00);
            Pswu[gr * KSTRIDE + 8 * nf + 2 * tg + 1]       = f2tf32(p01);
            Pswu[(gr + 8) * KSTRIDE + 8 * nf + 2 * tg]     = f2tf32(p10);
            Pswu[(gr + 8) * KSTRIDE + 8 * nf + 2 * tg + 1] = f2tf32(p11);
        }
        ps0 += __shfl_xor_sync(0xffffffffu, ps0, 1);
        ps0 += __shfl_xor_sync(0xffffffffu, ps0, 2);
        ps1 += __shfl_xor_sync(0xffffffffu, ps1, 1);
        ps1 += __shfl_xor_sync(0xffffffffu, ps1, 2);
        l0 = l0 * al0 + ps0;
        l1 = l1 * al1 + ps1;
        m0 = nm0; m1 = nm1;

#pragma unroll
        for (int nf = 0; nf < 8; nf++) {
            o[nf][0] *= al0; o[nf][1] *= al0;
            o[nf][2] *= al1; o[nf][3] *= al1;
        }
        __syncwarp();

#pragma unroll
        for (int kf = 0; kf < 8; kf++) {
            uint32_t aP[4];
            aP[0] = Pswu[gr * KSTRIDE + 8 * kf + tg];
            aP[1] = Pswu[(gr + 8) * KSTRIDE + 8 * kf + tg];
            aP[2] = Pswu[gr * KSTRIDE + 8 * kf + tg + 4];
            aP[3] = Pswu[(gr + 8) * KSTRIDE + 8 * kf + tg + 4];
#pragma unroll
            for (int nf = 0; nf < 8; nf++) {
                const uint32_t vb0 = Vsu[(8 * kf + tg) * KSTRIDE + 8 * nf + gr];
                const uint32_t vb1 = Vsu[(8 * kf + tg + 4) * KSTRIDE + 8 * nf + gr];
                mma_tf32(o[nf], aP, vb0, vb1);
            }
        }
    }

    const float inv0 = 1.f / l0;
    const float inv1 = 1.f / l1;
#pragma unroll
    for (int nf = 0; nf < 8; nf++) {
        const size_t base0 = (size_t)(b * S_ + r0g) * NX_ + h * DH_ + 8 * nf + 2 * tg;
        const size_t base1 = (size_t)(b * S_ + r1g) * NX_ + h * DH_ + 8 * nf + 2 * tg;
        float2 v0, v1;
        v0.x = o[nf][0] * inv0; v0.y = o[nf][1] * inv0;
        v1.x = o[nf][2] * inv1; v1.y = o[nf][3] * inv1;
        *(float2*)(out + base0) = v0;
        *(float2*)(out + base1) = v1;
    }
}

// ----------------------------------------------------------------------------
// Launch
// ----------------------------------------------------------------------------
extern "C" void kernel_launch(void* const* d_in, const int* in_sizes, int n_in,
                              void* d_out, int out_size)
{
    const float* x      = (const float*)d_in[0];
    const float* M      = (const float*)d_in[1];
    const float* Mmask  = (const float*)d_in[2];
    const float* amask  = (const float*)d_in[3];
    const float* W_attn = (const float*)d_in[4];
    const float* b_attn = (const float*)d_in[5];
    const float* W_mem  = (const float*)d_in[6];
    const float* b_mem  = (const float*)d_in[7];
    const float* W_proj = (const float*)d_in[8];
    const float* b_proj = (const float*)d_in[9];
    float* out = (float*)d_out;

    float* qkv; cudaGetSymbolAddress((void**)&qkv, g_qkv);
    float* ekv; cudaGetSymbolAddress((void**)&ekv, g_ekv);
    float* a;   cudaGetSymbolAddress((void**)&a,   g_a);

    cudaFuncSetAttribute(tf32_gemm_bias, cudaFuncAttributeMaxDynamicSharedMemorySize,
                         GEMM_SMEM);
    cudaFuncSetAttribute(attn_mma, cudaFuncAttributeMaxDynamicSharedMemorySize,
                         ATTN_SMEM);

    // 1) qkv = x @ W_attn + b_attn
    {
        dim3 grid(3 * NX_ / 128, BS_ / 128);
        tf32_gemm_bias<<<grid, 512, GEMM_SMEM>>>(x, W_attn, b_attn, qkv, BS_, 3 * NX_, NX_);
    }
    // 2) ekv = M @ W_mem + b_mem
    {
        dim3 grid(2 * NX_ / 128, BP_ / 128);
        tf32_gemm_bias<<<grid, 512, GEMM_SMEM>>>(M, W_mem, b_mem, ekv, BP_, 2 * NX_, NX_);
    }
    // 3) flash attention (tensor cores) -> a
    {
        dim3 grid(S_ / 128, B_ * H_);
        attn_mma<<<grid, 256, ATTN_SMEM>>>(qkv, ekv, Mmask, amask, a);
    }
    // 4) out = a @ W_proj + b_proj
    {
        dim3 grid(NX_ / 128, BS_ / 128);
        tf32_gemm_bias<<<grid, 512, GEMM_SMEM>>>(a, W_proj, b_proj, out, BS_, NX_, NX_);
    }
}

// round 6
// speedup vs baseline: 5.2849x; 1.0387x over previous
#include <cuda_runtime.h>
#include <cuda_bf16.h>
#include <cstdint>

// Problem constants
#define B_   4
#define S_   1024
#define P_   128
#define NX_  1024
#define H_   16
#define DH_  64
#define T_   (P_ + S_)      // 1152
#define BS_  (B_ * S_)      // 4096
#define BP_  (B_ * P_)      // 512

// Scratch (static device globals; no allocation allowed)
__device__ float g_qkv[(size_t)BS_ * 3 * NX_];   // [4096, 3072]
__device__ float g_ekv[(size_t)BP_ * 2 * NX_];   // [512, 2048]
__device__ float g_a  [(size_t)BS_ * NX_];       // [4096, 1024]

// ----------------------------------------------------------------------------
// Common MMA helpers
// ----------------------------------------------------------------------------
__device__ __forceinline__ uint32_t f2tf32(float x) {
    uint32_t u;
    asm("cvt.rna.tf32.f32 %0, %1;" : "=r"(u) : "f"(x));
    return u;
}

__device__ __forceinline__ void mma_tf32(float c[4], const uint32_t a[4],
                                         uint32_t b0, uint32_t b1) {
    asm volatile(
        "mma.sync.aligned.m16n8k8.row.col.f32.tf32.tf32.f32 "
        "{%0,%1,%2,%3}, {%4,%5,%6,%7}, {%8,%9}, {%0,%1,%2,%3};"
        : "+f"(c[0]), "+f"(c[1]), "+f"(c[2]), "+f"(c[3])
        : "r"(a[0]), "r"(a[1]), "r"(a[2]), "r"(a[3]), "r"(b0), "r"(b1));
}

__device__ __forceinline__ void ldsm_x4(uint32_t& r0, uint32_t& r1,
                                        uint32_t& r2, uint32_t& r3,
                                        const void* p) {
    uint32_t a = (uint32_t)__cvta_generic_to_shared(p);
    asm volatile("ldmatrix.sync.aligned.m8n8.x4.shared.b16 {%0,%1,%2,%3}, [%4];"
                 : "=r"(r0), "=r"(r1), "=r"(r2), "=r"(r3) : "r"(a));
}

// ----------------------------------------------------------------------------
// tf32 tensor-core GEMM, double-buffered: C[M,N] = A[M,K] @ B[K,N] + bias[N]
// Block 128x128, 8 warps (2M x 4N), warp tile m64 x n32, K-chunk 32,
// 2-stage smem pipeline, one __syncthreads per chunk, 256 threads.
// smem: per stage As [m=128][k=32] stride 36, Bs [n=128][k=32] stride 36.
// Requires M%128==0, N%128==0, K%32==0.
// ----------------------------------------------------------------------------
#define GST 36
#define GEMM_STAGE (128 * GST)
#define GEMM_SMEM (4 * GEMM_STAGE * 4)   // 2 stages x (As+Bs) x 4B = 73728

__global__ __launch_bounds__(256, 1) void tf32_gemm_bias(
    const float* __restrict__ A, const float* __restrict__ B,
    const float* __restrict__ bias, float* __restrict__ C,
    int M, int N, int K)
{
    extern __shared__ uint32_t smg[];
    // layout: [stage0 As][stage0 Bs][stage1 As][stage1 Bs]

    const int tid = threadIdx.x;
    const int w = tid >> 5, lane = tid & 31;
    const int gr = lane >> 2, tg = lane & 3;
    const int m0w = (w & 1) * 64;     // 2 M-tiles of 64
    const int n0w = (w >> 1) * 32;    // 4 N-tiles of 32

    const int lq = lane >> 3;
    const int lr = lane & 7;
    const int a_row = lr + ((lq & 1) << 3);
    const int a_col = (lq >> 1) << 2;
    const int b_row = lr + ((lq >> 1) << 3);
    const int b_col = (lq & 1) << 2;

    const float* Ag = A + (size_t)(blockIdx.y * 128) * K;
    const float* Bg = B + blockIdx.x * 128;

    // A staging: 128 rows x 8 float4; 256 threads x 4 iters
    const int a_srow0 = tid >> 3;            // 0..31, +32*it
    const int a_sc4 = (tid & 7) << 2;
    // B staging: k-row = 8*it + (tid&7), n-col4 = ((tid>>3)&31)<<2
    const int b_kr = tid & 7;
    const int b_c4 = ((tid >> 3) & 31) << 2;

    float c[4][4][4];
#pragma unroll
    for (int mi = 0; mi < 4; mi++)
#pragma unroll
        for (int nf = 0; nf < 4; nf++)
#pragma unroll
            for (int j = 0; j < 4; j++) c[mi][nf][j] = 0.f;

    const int nk = K >> 5;
    float4 ra[4], rb[4];

    // Load chunk 0
#pragma unroll
    for (int it = 0; it < 4; it++) {
        ra[it] = *(const float4*)(Ag + (size_t)(a_srow0 + 32 * it) * K + a_sc4);
        rb[it] = *(const float4*)(Bg + (size_t)(it * 8 + b_kr) * N + b_c4);
    }

    for (int kc = 0; kc < nk; kc++) {
        uint32_t* As = smg + (kc & 1) * 2 * GEMM_STAGE;
        uint32_t* Bs = As + GEMM_STAGE;

        // Store staged chunk (tf32-rounded)
#pragma unroll
        for (int it = 0; it < 4; it++) {
            uint4 ua;
            ua.x = f2tf32(ra[it].x); ua.y = f2tf32(ra[it].y);
            ua.z = f2tf32(ra[it].z); ua.w = f2tf32(ra[it].w);
            *(uint4*)(As + (a_srow0 + 32 * it) * GST + a_sc4) = ua;
            const int kr = it * 8 + b_kr;
            Bs[(b_c4 + 0) * GST + kr] = f2tf32(rb[it].x);
            Bs[(b_c4 + 1) * GST + kr] = f2tf32(rb[it].y);
            Bs[(b_c4 + 2) * GST + kr] = f2tf32(rb[it].z);
            Bs[(b_c4 + 3) * GST + kr] = f2tf32(rb[it].w);
        }
        __syncthreads();

        // Prefetch next chunk (overlaps the MMAs below)
        if (kc + 1 < nk) {
            const int k0 = (kc + 1) << 5;
#pragma unroll
            for (int it = 0; it < 4; it++) {
                ra[it] = *(const float4*)(Ag + (size_t)(a_srow0 + 32 * it) * K + k0 + a_sc4);
                rb[it] = *(const float4*)(Bg + (size_t)(k0 + it * 8 + b_kr) * N + b_c4);
            }
        }

        // Compute: 4 kf x (4 a-ldsm + 2 b-ldsm + 16 mma)
#pragma unroll
        for (int kf = 0; kf < 4; kf++) {
            const int kb = kf << 3;
            uint32_t a[4][4];
#pragma unroll
            for (int mi = 0; mi < 4; mi++)
                ldsm_x4(a[mi][0], a[mi][1], a[mi][2], a[mi][3],
                        As + (m0w + 16 * mi + a_row) * GST + kb + a_col);
#pragma unroll
            for (int p = 0; p < 2; p++) {
                uint32_t b0, b1, b2, b3;
                ldsm_x4(b0, b1, b2, b3,
                        Bs + (n0w + 16 * p + b_row) * GST + kb + b_col);
#pragma unroll
                for (int mi = 0; mi < 4; mi++) {
                    mma_tf32(c[mi][2 * p],     a[mi], b0, b1);
                    mma_tf32(c[mi][2 * p + 1], a[mi], b2, b3);
                }
            }
        }
    }

    // Epilogue with bias
#pragma unroll
    for (int nf = 0; nf < 4; nf++) {
        const int col = blockIdx.x * 128 + n0w + 8 * nf + 2 * tg;
        const float bb0 = bias[col];
        const float bb1 = bias[col + 1];
#pragma unroll
        for (int mi = 0; mi < 4; mi++) {
            const size_t r0 = (size_t)(blockIdx.y * 128 + m0w + 16 * mi + gr);
            float2 v0, v1;
            v0.x = c[mi][nf][0] + bb0; v0.y = c[mi][nf][1] + bb1;
            v1.x = c[mi][nf][2] + bb0; v1.y = c[mi][nf][3] + bb1;
            *(float2*)(C + r0 * N + col)       = v0;
            *(float2*)(C + (r0 + 8) * N + col) = v1;
        }
    }
}

// ----------------------------------------------------------------------------
// Flash attention with tf32 tensor cores (unchanged from R5).
// ----------------------------------------------------------------------------
#define KSTRIDE 68
#define ATTN_SMEM ((2 * 64 * KSTRIDE + 8 * 16 * KSTRIDE + 64) * 4)

__global__ __launch_bounds__(256) void attn_mma(
    const float* __restrict__ qkv,   // [BS, 3*NX]
    const float* __restrict__ ekv,   // [BP, 2*NX]
    const float* __restrict__ Mmask, // [B, P]
    const float* __restrict__ amask, // [B,1,1,S]
    float* __restrict__ out)         // [BS, NX]
{
    extern __shared__ float sm[];
    float* Ks = sm;                          // [64][68]
    float* Vs = sm + 64 * KSTRIDE;           // [64][68]
    float* Ps = sm + 2 * 64 * KSTRIDE;       // [8][16][68]
    float* Cb = Ps + 8 * 16 * KSTRIDE;       // [64]
    uint32_t* Ksu = (uint32_t*)Ks;
    uint32_t* Vsu = (uint32_t*)Vs;
    uint32_t* Qtu = (uint32_t*)sm;           // Q staged over Ks+Vs: [128][68]

    const int bh = blockIdx.y;
    const int b = bh >> 4, h = bh & 15;
    const int q0 = blockIdx.x * 128;
    const int tid = threadIdx.x;
    const int w = tid >> 5;
    const int lane = tid & 31;
    const int gr = lane >> 2;
    const int tg = lane & 3;

    // ---- Stage Q (scaled 1/8, tf32-rounded) into Qtmp [128][68] ----
#pragma unroll
    for (int it = 0; it < 8; it++) {
        const int fid = tid + it * 256;
        const int r = fid >> 4;
        const int c4 = (fid & 15) * 4;
        const float4 q = *(const float4*)(
            qkv + (size_t)(b * S_ + q0 + r) * (3 * NX_) + h * DH_ + c4);
        uint32_t* d = Qtu + r * KSTRIDE + c4;
        d[0] = f2tf32(q.x * 0.125f);
        d[1] = f2tf32(q.y * 0.125f);
        d[2] = f2tf32(q.z * 0.125f);
        d[3] = f2tf32(q.w * 0.125f);
    }
    __syncthreads();

    uint32_t aQ[8][4];
    {
        const int r0 = 16 * w + gr;
#pragma unroll
        for (int kf = 0; kf < 8; kf++) {
            aQ[kf][0] = Qtu[r0 * KSTRIDE + 8 * kf + tg];
            aQ[kf][1] = Qtu[(r0 + 8) * KSTRIDE + 8 * kf + tg];
            aQ[kf][2] = Qtu[r0 * KSTRIDE + 8 * kf + tg + 4];
            aQ[kf][3] = Qtu[(r0 + 8) * KSTRIDE + 8 * kf + tg + 4];
        }
    }

    float m0 = -1e30f, m1 = -1e30f, l0 = 0.f, l1 = 0.f;
    float o[8][4];
#pragma unroll
    for (int nf = 0; nf < 8; nf++)
#pragma unroll
        for (int j = 0; j < 4; j++) o[nf][j] = 0.f;

    uint32_t* Pswu = (uint32_t*)(Ps + w * 16 * KSTRIDE);
    const int r0g = q0 + 16 * w + gr;
    const int r1g = r0g + 8;
    const int ntiles = 2 * blockIdx.x + 4;

    for (int kt = 0; kt < ntiles; kt++) {
        const int t0k = kt * 64;
        __syncthreads();

#pragma unroll
        for (int it = 0; it < 4; it++) {
            const int fid = tid + it * 256;
            const int t = fid >> 4;
            const int c4 = (fid & 15) * 4;
            const int tg_ = t0k + t;
            const float* kp;
            const float* vp;
            if (tg_ < P_) {
                const float* e = ekv + (size_t)(b * P_ + tg_) * (2 * NX_) + h * DH_;
                kp = e;
                vp = e + NX_;
            } else {
                const float* s = qkv + (size_t)(b * S_ + tg_ - P_) * (3 * NX_) + h * DH_;
                kp = s + NX_;
                vp = s + 2 * NX_;
            }
            const float4 kv = *(const float4*)(kp + c4);
            const float4 vv = *(const float4*)(vp + c4);
            uint32_t* kd = Ksu + t * KSTRIDE + c4;
            kd[0] = f2tf32(kv.x); kd[1] = f2tf32(kv.y);
            kd[2] = f2tf32(kv.z); kd[3] = f2tf32(kv.w);
            uint32_t* vd = Vsu + t * KSTRIDE + c4;
            vd[0] = f2tf32(vv.x); vd[1] = f2tf32(vv.y);
            vd[2] = f2tf32(vv.z); vd[3] = f2tf32(vv.w);
        }
        if (tid < 64) {
            const int t = t0k + tid;
            Cb[tid] = (t < P_) ? (1.f - Mmask[b * P_ + t]) * -10000.f
                               : amask[b * S_ + (t - P_)];
        }
        __syncthreads();

        float s[8][4];
#pragma unroll
        for (int nf = 0; nf < 8; nf++)
#pragma unroll
            for (int j = 0; j < 4; j++) s[nf][j] = 0.f;

#pragma unroll
        for (int kf = 0; kf < 8; kf++) {
#pragma unroll
            for (int nf = 0; nf < 8; nf++) {
                const uint32_t kb0 = Ksu[(8 * nf + gr) * KSTRIDE + 8 * kf + tg];
                const uint32_t kb1 = Ksu[(8 * nf + gr) * KSTRIDE + 8 * kf + tg + 4];
                mma_tf32(s[nf], aQ[kf], kb0, kb1);
            }
        }

        float mx0 = -1e30f, mx1 = -1e30f;
#pragma unroll
        for (int nf = 0; nf < 8; nf++) {
            const int tc = t0k + 8 * nf + 2 * tg;
            const float cb0 = Cb[8 * nf + 2 * tg];
            const float cb1 = Cb[8 * nf + 2 * tg + 1];
            const int ts0 = tc - P_;
            const int ts1 = ts0 + 1;
            const float l00 = (ts0 <= r0g ? s[nf][0] : -10000.f) + cb0;
            const float l01 = (ts1 <= r0g ? s[nf][1] : -10000.f) + cb1;
            const float l10 = (ts0 <= r1g ? s[nf][2] : -10000.f) + cb0;
            const float l11 = (ts1 <= r1g ? s[nf][3] : -10000.f) + cb1;
            s[nf][0] = l00; s[nf][1] = l01; s[nf][2] = l10; s[nf][3] = l11;
            mx0 = fmaxf(mx0, fmaxf(l00, l01));
            mx1 = fmaxf(mx1, fmaxf(l10, l11));
        }
        mx0 = fmaxf(mx0, __shfl_xor_sync(0xffffffffu, mx0, 1));
        mx0 = fmaxf(mx0, __shfl_xor_sync(0xffffffffu, mx0, 2));
        mx1 = fmaxf(mx1, __shfl_xor_sync(0xffffffffu, mx1, 1));
        mx1 = fmaxf(mx1, __shfl_xor_sync(0xffffffffu, mx1, 2));

        const float nm0 = fmaxf(m0, mx0);
        const float nm1 = fmaxf(m1, mx1);
        const float al0 = __expf(m0 - nm0);
        const float al1 = __expf(m1 - nm1);
        float ps0 = 0.f, ps1 = 0.f;
#pragma unroll
        for (int nf = 0; nf < 8; nf++) {
            const float p00 = __expf(s[nf][0] - nm0);
            const float p01 = __expf(s[nf][1] - nm0);
            const float p10 = __expf(s[nf][2] - nm1);
            const float p11 = __expf(s[nf][3] - nm1);
            ps0 += p00 + p01;
            ps1 += p10 + p11;
            Pswu[gr * KSTRIDE + 8 * nf + 2 * tg]           = f2tf32(p00);
            Pswu[gr * KSTRIDE + 8 * nf + 2 * tg + 1]       = f2tf32(p01);
            Pswu[(gr + 8) * KSTRIDE + 8 * nf + 2 * tg]     = f2tf32(p10);
            Pswu[(gr + 8) * KSTRIDE + 8 * nf + 2 * tg + 1] = f2tf32(p11);
        }
        ps0 += __shfl_xor_sync(0xffffffffu, ps0, 1);
        ps0 += __shfl_xor_sync(0xffffffffu, ps0, 2);
        ps1 += __shfl_xor_sync(0xffffffffu, ps1, 1);
        ps1 += __shfl_xor_sync(0xffffffffu, ps1, 2);
        l0 = l0 * al0 + ps0;
        l1 = l1 * al1 + ps1;
        m0 = nm0; m1 = nm1;

#pragma unroll
        for (int nf = 0; nf < 8; nf++) {
            o[nf][0] *= al0; o[nf][1] *= al0;
            o[nf][2] *= al1; o[nf][3] *= al1;
        }
        __syncwarp();

#pragma unroll
        for (int kf = 0; kf < 8; kf++) {
            uint32_t aP[4];
            aP[0] = Pswu[gr * KSTRIDE + 8 * kf + tg];
            aP[1] = Pswu[(gr + 8) * KSTRIDE + 8 * kf + tg];
            aP[2] = Pswu[gr * KSTRIDE + 8 * kf + tg + 4];
            aP[3] = Pswu[(gr + 8) * KSTRIDE + 8 * kf + tg + 4];
#pragma unroll
            for (int nf = 0; nf < 8; nf++) {
                const uint32_t vb0 = Vsu[(8 * kf + tg) * KSTRIDE + 8 * nf + gr];
                const uint32_t vb1 = Vsu[(8 * kf + tg + 4) * KSTRIDE + 8 * nf + gr];
                mma_tf32(o[nf], aP, vb0, vb1);
            }
        }
    }

    const float inv0 = 1.f / l0;
    const float inv1 = 1.f / l1;
#pragma unroll
    for (int nf = 0; nf < 8; nf++) {
        const size_t base0 = (size_t)(b * S_ + r0g) * NX_ + h * DH_ + 8 * nf + 2 * tg;
        const size_t base1 = (size_t)(b * S_ + r1g) * NX_ + h * DH_ + 8 * nf + 2 * tg;
        float2 v0, v1;
        v0.x = o[nf][0] * inv0; v0.y = o[nf][1] * inv0;
        v1.x = o[nf][2] * inv1; v1.y = o[nf][3] * inv1;
        *(float2*)(out + base0) = v0;
        *(float2*)(out + base1) = v1;
    }
}

// ----------------------------------------------------------------------------
// Launch
// ----------------------------------------------------------------------------
extern "C" void kernel_launch(void* const* d_in, const int* in_sizes, int n_in,
                              void* d_out, int out_size)
{
    const float* x      = (const float*)d_in[0];
    const float* M      = (const float*)d_in[1];
    const float* Mmask  = (const float*)d_in[2];
    const float* amask  = (const float*)d_in[3];
    const float* W_attn = (const float*)d_in[4];
    const float* b_attn = (const float*)d_in[5];
    const float* W_mem  = (const float*)d_in[6];
    const float* b_mem  = (const float*)d_in[7];
    const float* W_proj = (const float*)d_in[8];
    const float* b_proj = (const float*)d_in[9];
    float* out = (float*)d_out;

    float* qkv; cudaGetSymbolAddress((void**)&qkv, g_qkv);
    float* ekv; cudaGetSymbolAddress((void**)&ekv, g_ekv);
    float* a;   cudaGetSymbolAddress((void**)&a,   g_a);

    cudaFuncSetAttribute(tf32_gemm_bias, cudaFuncAttributeMaxDynamicSharedMemorySize,
                         GEMM_SMEM);
    cudaFuncSetAttribute(attn_mma, cudaFuncAttributeMaxDynamicSharedMemorySize,
                         ATTN_SMEM);

    // 1) qkv = x @ W_attn + b_attn
    {
        dim3 grid(3 * NX_ / 128, BS_ / 128);
        tf32_gemm_bias<<<grid, 256, GEMM_SMEM>>>(x, W_attn, b_attn, qkv, BS_, 3 * NX_, NX_);
    }
    // 2) ekv = M @ W_mem + b_mem
    {
        dim3 grid(2 * NX_ / 128, BP_ / 128);
        tf32_gemm_bias<<<grid, 256, GEMM_SMEM>>>(M, W_mem, b_mem, ekv, BP_, 2 * NX_, NX_);
    }
    // 3) flash attention (tensor cores) -> a
    {
        dim3 grid(S_ / 128, B_ * H_);
        attn_mma<<<grid, 256, ATTN_SMEM>>>(qkv, ekv, Mmask, amask, a);
    }
    // 4) out = a @ W_proj + b_proj
    {
        dim3 grid(NX_ / 128, BS_ / 128);
        tf32_gemm_bias<<<grid, 256, GEMM_SMEM>>>(a, W_proj, b_proj, out, BS_, NX_, NX_);
    }
}

// round 7
// speedup vs baseline: 5.9393x; 1.1238x over previous
#include <cuda_runtime.h>
#include <cuda_bf16.h>
#include <cstdint>

// Problem constants
#define B_   4
#define S_   1024
#define P_   128
#define NX_  1024
#define H_   16
#define DH_  64
#define T_   (P_ + S_)      // 1152
#define BS_  (B_ * S_)      // 4096
#define BP_  (B_ * P_)      // 512

// Scratch (static device globals; no allocation allowed)
__device__ float g_qkv[(size_t)BS_ * 3 * NX_];   // [4096, 3072]
__device__ float g_ekv[(size_t)BP_ * 2 * NX_];   // [512, 2048]
__device__ float g_a  [(size_t)BS_ * NX_];       // [4096, 1024]

// ----------------------------------------------------------------------------
// Common MMA helpers
// ----------------------------------------------------------------------------
__device__ __forceinline__ uint32_t f2tf32(float x) {
    uint32_t u;
    asm("cvt.rna.tf32.f32 %0, %1;" : "=r"(u) : "f"(x));
    return u;
}

__device__ __forceinline__ void mma_tf32(float c[4], const uint32_t a[4],
                                         uint32_t b0, uint32_t b1) {
    asm volatile(
        "mma.sync.aligned.m16n8k8.row.col.f32.tf32.tf32.f32 "
        "{%0,%1,%2,%3}, {%4,%5,%6,%7}, {%8,%9}, {%0,%1,%2,%3};"
        : "+f"(c[0]), "+f"(c[1]), "+f"(c[2]), "+f"(c[3])
        : "r"(a[0]), "r"(a[1]), "r"(a[2]), "r"(a[3]), "r"(b0), "r"(b1));
}

__device__ __forceinline__ void ldsm_x4(uint32_t& r0, uint32_t& r1,
                                        uint32_t& r2, uint32_t& r3,
                                        const void* p) {
    uint32_t a = (uint32_t)__cvta_generic_to_shared(p);
    asm volatile("ldmatrix.sync.aligned.m8n8.x4.shared.b16 {%0,%1,%2,%3}, [%4];"
                 : "=r"(r0), "=r"(r1), "=r"(r2), "=r"(r3) : "r"(a));
}

// ----------------------------------------------------------------------------
// tf32 tensor-core GEMM: C[M,N] = A[M,K] @ B[K,N] + bias[N]
// Block 128(M) x 256(N), 8 warps (2M x 4N), warp tile m64 x n64, K-chunk 16,
// double-buffered, 256 threads.
// As [m=128][k=16] stride 20  (ldsm rows at 20r mod 32: all distinct)
// Bs [k=16][n=256] stride 264 (STS conflict-free; B-frag LDS banks 8*tg+gr)
// Requires M%128==0, N%256==0, K%16==0.
// ----------------------------------------------------------------------------
#define AST 20
#define BST 264
#define A_WORDS (128 * AST)                 // 2560
#define B_WORDS (16 * BST)                  // 4224
#define SSTRIDE (A_WORDS + B_WORDS)         // 6784 words / stage
#define GEMM_SMEM (2 * SSTRIDE * 4)         // 54272 bytes

__global__ __launch_bounds__(256, 1) void tf32_gemm_bias(
    const float* __restrict__ A, const float* __restrict__ B,
    const float* __restrict__ bias, float* __restrict__ C,
    int M, int N, int K)
{
    extern __shared__ uint32_t smg[];

    const int tid = threadIdx.x;
    const int w = tid >> 5, lane = tid & 31;
    const int gr = lane >> 2, tg = lane & 3;
    const int m0w = (w & 1) * 64;     // 2 M-tiles of 64
    const int n0w = (w >> 1) * 64;    // 4 N-tiles of 64

    const int lq = lane >> 3;
    const int lr = lane & 7;
    const int a_row = lr + ((lq & 1) << 3);
    const int a_col = (lq >> 1) << 2;

    const float* Ag = A + (size_t)(blockIdx.y * 128) * K;
    const float* Bg = B + blockIdx.x * 256;

    // A staging: 128 rows x 4 float4; 2 iters
    const int a_srow = tid >> 2;             // 0..63, +64*it
    const int a_sc4 = (tid & 3) << 2;        // 0,4,8,12
    // B staging: 16 k-rows x 64 float4; 4 iters
    const int b_kr0 = tid >> 6;              // 0..3, +4*it
    const int b_c4 = (tid & 63) << 2;        // 0..252

    float c[4][8][4];
#pragma unroll
    for (int mi = 0; mi < 4; mi++)
#pragma unroll
        for (int nf = 0; nf < 8; nf++)
#pragma unroll
            for (int j = 0; j < 4; j++) c[mi][nf][j] = 0.f;

    const int nk = K >> 4;
    float4 ra[2], rb[4];

    // Load chunk 0
#pragma unroll
    for (int it = 0; it < 2; it++)
        ra[it] = *(const float4*)(Ag + (size_t)(a_srow + 64 * it) * K + a_sc4);
#pragma unroll
    for (int it = 0; it < 4; it++)
        rb[it] = *(const float4*)(Bg + (size_t)(b_kr0 + 4 * it) * N + b_c4);

    for (int kc = 0; kc < nk; kc++) {
        uint32_t* As = smg + (kc & 1) * SSTRIDE;
        uint32_t* Bs = As + A_WORDS;

        // Store staged chunk (tf32-rounded); conflict-free STS patterns
#pragma unroll
        for (int it = 0; it < 2; it++) {
            uint4 ua;
            ua.x = f2tf32(ra[it].x); ua.y = f2tf32(ra[it].y);
            ua.z = f2tf32(ra[it].z); ua.w = f2tf32(ra[it].w);
            *(uint4*)(As + (a_srow + 64 * it) * AST + a_sc4) = ua;
        }
#pragma unroll
        for (int it = 0; it < 4; it++) {
            uint4 ub;
            ub.x = f2tf32(rb[it].x); ub.y = f2tf32(rb[it].y);
            ub.z = f2tf32(rb[it].z); ub.w = f2tf32(rb[it].w);
            *(uint4*)(Bs + (b_kr0 + 4 * it) * BST + b_c4) = ub;
        }
        __syncthreads();

        // Prefetch next chunk (overlaps the MMAs below)
        if (kc + 1 < nk) {
            const int k0 = (kc + 1) << 4;
#pragma unroll
            for (int it = 0; it < 2; it++)
                ra[it] = *(const float4*)(Ag + (size_t)(a_srow + 64 * it) * K + k0 + a_sc4);
#pragma unroll
            for (int it = 0; it < 4; it++)
                rb[it] = *(const float4*)(Bg + (size_t)(k0 + b_kr0 + 4 * it) * N + b_c4);
        }

        // Compute: 2 kf x (4 a-ldsm + 16 b-LDS-pairs + 32 mma)
#pragma unroll
        for (int kf = 0; kf < 2; kf++) {
            const int kb = kf << 3;
            uint32_t a[4][4];
#pragma unroll
            for (int mi = 0; mi < 4; mi++)
                ldsm_x4(a[mi][0], a[mi][1], a[mi][2], a[mi][3],
                        As + (m0w + 16 * mi + a_row) * AST + kb + a_col);
            const uint32_t* b0p = Bs + (kb + tg) * BST + n0w + gr;
            const uint32_t* b1p = b0p + 4 * BST;
#pragma unroll
            for (int nf = 0; nf < 8; nf++) {
                const uint32_t b0 = b0p[8 * nf];
                const uint32_t b1 = b1p[8 * nf];
#pragma unroll
                for (int mi = 0; mi < 4; mi++)
                    mma_tf32(c[mi][nf], a[mi], b0, b1);
            }
        }
    }

    // Epilogue with bias
#pragma unroll
    for (int nf = 0; nf < 8; nf++) {
        const int col = blockIdx.x * 256 + n0w + 8 * nf + 2 * tg;
        const float bb0 = bias[col];
        const float bb1 = bias[col + 1];
#pragma unroll
        for (int mi = 0; mi < 4; mi++) {
            const size_t r0 = (size_t)(blockIdx.y * 128 + m0w + 16 * mi + gr);
            float2 v0, v1;
            v0.x = c[mi][nf][0] + bb0; v0.y = c[mi][nf][1] + bb1;
            v1.x = c[mi][nf][2] + bb0; v1.y = c[mi][nf][3] + bb1;
            *(float2*)(C + r0 * N + col)       = v0;
            *(float2*)(C + (r0 + 8) * N + col) = v1;
        }
    }
}

// ----------------------------------------------------------------------------
// Flash attention with tf32 tensor cores (unchanged from R6).
// ----------------------------------------------------------------------------
#define KSTRIDE 68
#define ATTN_SMEM ((2 * 64 * KSTRIDE + 8 * 16 * KSTRIDE + 64) * 4)

__global__ __launch_bounds__(256) void attn_mma(
    const float* __restrict__ qkv,   // [BS, 3*NX]
    const float* __restrict__ ekv,   // [BP, 2*NX]
    const float* __restrict__ Mmask, // [B, P]
    const float* __restrict__ amask, // [B,1,1,S]
    float* __restrict__ out)         // [BS, NX]
{
    extern __shared__ float sm[];
    float* Ks = sm;                          // [64][68]
    float* Vs = sm + 64 * KSTRIDE;           // [64][68]
    float* Ps = sm + 2 * 64 * KSTRIDE;       // [8][16][68]
    float* Cb = Ps + 8 * 16 * KSTRIDE;       // [64]
    uint32_t* Ksu = (uint32_t*)Ks;
    uint32_t* Vsu = (uint32_t*)Vs;
    uint32_t* Qtu = (uint32_t*)sm;           // Q staged over Ks+Vs: [128][68]

    const int bh = blockIdx.y;
    const int b = bh >> 4, h = bh & 15;
    const int q0 = blockIdx.x * 128;
    const int tid = threadIdx.x;
    const int w = tid >> 5;
    const int lane = tid & 31;
    const int gr = lane >> 2;
    const int tg = lane & 3;

    // ---- Stage Q (scaled 1/8, tf32-rounded) into Qtmp [128][68] ----
#pragma unroll
    for (int it = 0; it < 8; it++) {
        const int fid = tid + it * 256;
        const int r = fid >> 4;
        const int c4 = (fid & 15) * 4;
        const float4 q = *(const float4*)(
            qkv + (size_t)(b * S_ + q0 + r) * (3 * NX_) + h * DH_ + c4);
        uint32_t* d = Qtu + r * KSTRIDE + c4;
        d[0] = f2tf32(q.x * 0.125f);
        d[1] = f2tf32(q.y * 0.125f);
        d[2] = f2tf32(q.z * 0.125f);
        d[3] = f2tf32(q.w * 0.125f);
    }
    __syncthreads();

    uint32_t aQ[8][4];
    {
        const int r0 = 16 * w + gr;
#pragma unroll
        for (int kf = 0; kf < 8; kf++) {
            aQ[kf][0] = Qtu[r0 * KSTRIDE + 8 * kf + tg];
            aQ[kf][1] = Qtu[(r0 + 8) * KSTRIDE + 8 * kf + tg];
            aQ[kf][2] = Qtu[r0 * KSTRIDE + 8 * kf + tg + 4];
            aQ[kf][3] = Qtu[(r0 + 8) * KSTRIDE + 8 * kf + tg + 4];
        }
    }

    float m0 = -1e30f, m1 = -1e30f, l0 = 0.f, l1 = 0.f;
    float o[8][4];
#pragma unroll
    for (int nf = 0; nf < 8; nf++)
#pragma unroll
        for (int j = 0; j < 4; j++) o[nf][j] = 0.f;

    uint32_t* Pswu = (uint32_t*)(Ps + w * 16 * KSTRIDE);
    const int r0g = q0 + 16 * w + gr;
    const int r1g = r0g + 8;
    const int ntiles = 2 * blockIdx.x + 4;

    for (int kt = 0; kt < ntiles; kt++) {
        const int t0k = kt * 64;
        __syncthreads();

#pragma unroll
        for (int it = 0; it < 4; it++) {
            const int fid = tid + it * 256;
            const int t = fid >> 4;
            const int c4 = (fid & 15) * 4;
            const int tg_ = t0k + t;
            const float* kp;
            const float* vp;
            if (tg_ < P_) {
                const float* e = ekv + (size_t)(b * P_ + tg_) * (2 * NX_) + h * DH_;
                kp = e;
                vp = e + NX_;
            } else {
                const float* s = qkv + (size_t)(b * S_ + tg_ - P_) * (3 * NX_) + h * DH_;
                kp = s + NX_;
                vp = s + 2 * NX_;
            }
            const float4 kv = *(const float4*)(kp + c4);
            const float4 vv = *(const float4*)(vp + c4);
            uint32_t* kd = Ksu + t * KSTRIDE + c4;
            kd[0] = f2tf32(kv.x); kd[1] = f2tf32(kv.y);
            kd[2] = f2tf32(kv.z); kd[3] = f2tf32(kv.w);
            uint32_t* vd = Vsu + t * KSTRIDE + c4;
            vd[0] = f2tf32(vv.x); vd[1] = f2tf32(vv.y);
            vd[2] = f2tf32(vv.z); vd[3] = f2tf32(vv.w);
        }
        if (tid < 64) {
            const int t = t0k + tid;
            Cb[tid] = (t < P_) ? (1.f - Mmask[b * P_ + t]) * -10000.f
                               : amask[b * S_ + (t - P_)];
        }
        __syncthreads();

        float s[8][4];
#pragma unroll
        for (int nf = 0; nf < 8; nf++)
#pragma unroll
            for (int j = 0; j < 4; j++) s[nf][j] = 0.f;

#pragma unroll
        for (int kf = 0; kf < 8; kf++) {
#pragma unroll
            for (int nf = 0; nf < 8; nf++) {
                const uint32_t kb0 = Ksu[(8 * nf + gr) * KSTRIDE + 8 * kf + tg];
                const uint32_t kb1 = Ksu[(8 * nf + gr) * KSTRIDE + 8 * kf + tg + 4];
                mma_tf32(s[nf], aQ[kf], kb0, kb1);
            }
        }

        float mx0 = -1e30f, mx1 = -1e30f;
#pragma unroll
        for (int nf = 0; nf < 8; nf++) {
            const int tc = t0k + 8 * nf + 2 * tg;
            const float cb0 = Cb[8 * nf + 2 * tg];
            const float cb1 = Cb[8 * nf + 2 * tg + 1];
            const int ts0 = tc - P_;
            const int ts1 = ts0 + 1;
            const float l00 = (ts0 <= r0g ? s[nf][0] : -10000.f) + cb0;
            const float l01 = (ts1 <= r0g ? s[nf][1] : -10000.f) + cb1;
            const float l10 = (ts0 <= r1g ? s[nf][2] : -10000.f) + cb0;
            const float l11 = (ts1 <= r1g ? s[nf][3] : -10000.f) + cb1;
            s[nf][0] = l00; s[nf][1] = l01; s[nf][2] = l10; s[nf][3] = l11;
            mx0 = fmaxf(mx0, fmaxf(l00, l01));
            mx1 = fmaxf(mx1, fmaxf(l10, l11));
        }
        mx0 = fmaxf(mx0, __shfl_xor_sync(0xffffffffu, mx0, 1));
        mx0 = fmaxf(mx0, __shfl_xor_sync(0xffffffffu, mx0, 2));
        mx1 = fmaxf(mx1, __shfl_xor_sync(0xffffffffu, mx1, 1));
        mx1 = fmaxf(mx1, __shfl_xor_sync(0xffffffffu, mx1, 2));

        const float nm0 = fmaxf(m0, mx0);
        const float nm1 = fmaxf(m1, mx1);
        const float al0 = __expf(m0 - nm0);
        const float al1 = __expf(m1 - nm1);
        float ps0 = 0.f, ps1 = 0.f;
#pragma unroll
        for (int nf = 0; nf < 8; nf++) {
            const float p00 = __expf(s[nf][0] - nm0);
            const float p01 = __expf(s[nf][1] - nm0);
            const float p10 = __expf(s[nf][2] - nm1);
            const float p11 = __expf(s[nf][3] - nm1);
            ps0 += p00 + p01;
            ps1 += p10 + p11;
            Pswu[gr * KSTRIDE + 8 * nf + 2 * tg]           = f2tf32(p00);
            Pswu[gr * KSTRIDE + 8 * nf + 2 * tg + 1]       = f2tf32(p01);
            Pswu[(gr + 8) * KSTRIDE + 8 * nf + 2 * tg]     = f2tf32(p10);
            Pswu[(gr + 8) * KSTRIDE + 8 * nf + 2 * tg + 1] = f2tf32(p11);
        }
        ps0 += __shfl_xor_sync(0xffffffffu, ps0, 1);
        ps0 += __shfl_xor_sync(0xffffffffu, ps0, 2);
        ps1 += __shfl_xor_sync(0xffffffffu, ps1, 1);
        ps1 += __shfl_xor_sync(0xffffffffu, ps1, 2);
        l0 = l0 * al0 + ps0;
        l1 = l1 * al1 + ps1;
        m0 = nm0; m1 = nm1;

#pragma unroll
        for (int nf = 0; nf < 8; nf++) {
            o[nf][0] *= al0; o[nf][1] *= al0;
            o[nf][2] *= al1; o[nf][3] *= al1;
        }
        __syncwarp();

#pragma unroll
        for (int kf = 0; kf < 8; kf++) {
            uint32_t aP[4];
            aP[0] = Pswu[gr * KSTRIDE + 8 * kf + tg];
            aP[1] = Pswu[(gr + 8) * KSTRIDE + 8 * kf + tg];
            aP[2] = Pswu[gr * KSTRIDE + 8 * kf + tg + 4];
            aP[3] = Pswu[(gr + 8) * KSTRIDE + 8 * kf + tg + 4];
#pragma unroll
            for (int nf = 0; nf < 8; nf++) {
                const uint32_t vb0 = Vsu[(8 * kf + tg) * KSTRIDE + 8 * nf + gr];
                const uint32_t vb1 = Vsu[(8 * kf + tg + 4) * KSTRIDE + 8 * nf + gr];
                mma_tf32(o[nf], aP, vb0, vb1);
            }
        }
    }

    const float inv0 = 1.f / l0;
    const float inv1 = 1.f / l1;
#pragma unroll
    for (int nf = 0; nf < 8; nf++) {
        const size_t base0 = (size_t)(b * S_ + r0g) * NX_ + h * DH_ + 8 * nf + 2 * tg;
        const size_t base1 = (size_t)(b * S_ + r1g) * NX_ + h * DH_ + 8 * nf + 2 * tg;
        float2 v0, v1;
        v0.x = o[nf][0] * inv0; v0.y = o[nf][1] * inv0;
        v1.x = o[nf][2] * inv1; v1.y = o[nf][3] * inv1;
        *(float2*)(out + base0) = v0;
        *(float2*)(out + base1) = v1;
    }
}

// ----------------------------------------------------------------------------
// Launch
// ----------------------------------------------------------------------------
extern "C" void kernel_launch(void* const* d_in, const int* in_sizes, int n_in,
                              void* d_out, int out_size)
{
    const float* x      = (const float*)d_in[0];
    const float* M      = (const float*)d_in[1];
    const float* Mmask  = (const float*)d_in[2];
    const float* amask  = (const float*)d_in[3];
    const float* W_attn = (const float*)d_in[4];
    const float* b_attn = (const float*)d_in[5];
    const float* W_mem  = (const float*)d_in[6];
    const float* b_mem  = (const float*)d_in[7];
    const float* W_proj = (const float*)d_in[8];
    const float* b_proj = (const float*)d_in[9];
    float* out = (float*)d_out;

    float* qkv; cudaGetSymbolAddress((void**)&qkv, g_qkv);
    float* ekv; cudaGetSymbolAddress((void**)&ekv, g_ekv);
    float* a;   cudaGetSymbolAddress((void**)&a,   g_a);

    cudaFuncSetAttribute(tf32_gemm_bias, cudaFuncAttributeMaxDynamicSharedMemorySize,
                         GEMM_SMEM);
    cudaFuncSetAttribute(attn_mma, cudaFuncAttributeMaxDynamicSharedMemorySize,
                         ATTN_SMEM);

    // 1) qkv = x @ W_attn + b_attn
    {
        dim3 grid(3 * NX_ / 256, BS_ / 128);
        tf32_gemm_bias<<<grid, 256, GEMM_SMEM>>>(x, W_attn, b_attn, qkv, BS_, 3 * NX_, NX_);
    }
    // 2) ekv = M @ W_mem + b_mem
    {
        dim3 grid(2 * NX_ / 256, BP_ / 128);
        tf32_gemm_bias<<<grid, 256, GEMM_SMEM>>>(M, W_mem, b_mem, ekv, BP_, 2 * NX_, NX_);
    }
    // 3) flash attention (tensor cores) -> a
    {
        dim3 grid(S_ / 128, B_ * H_);
        attn_mma<<<grid, 256, ATTN_SMEM>>>(qkv, ekv, Mmask, amask, a);
    }
    // 4) out = a @ W_proj + b_proj
    {
        dim3 grid(NX_ / 256, BS_ / 128);
        tf32_gemm_bias<<<grid, 256, GEMM_SMEM>>>(a, W_proj, b_proj, out, BS_, NX_, NX_);
    }
}

// round 8
// speedup vs baseline: 6.5210x; 1.0979x over previous
#include <cuda_runtime.h>
#include <cuda_bf16.h>
#include <cstdint>

// Problem constants
#define B_   4
#define S_   1024
#define P_   128
#define NX_  1024
#define H_   16
#define DH_  64
#define T_   (P_ + S_)      // 1152
#define BS_  (B_ * S_)      // 4096
#define BP_  (B_ * P_)      // 512

// Scratch (static device globals; no allocation allowed)
__device__ float g_qkv[(size_t)BS_ * 3 * NX_];   // [4096, 3072]
__device__ float g_ekv[(size_t)BP_ * 2 * NX_];   // [512, 2048]
__device__ float g_a  [(size_t)BS_ * NX_];       // [4096, 1024]

// ----------------------------------------------------------------------------
// Common MMA helpers
// ----------------------------------------------------------------------------
__device__ __forceinline__ uint32_t f2tf32(float x) {
    uint32_t u;
    asm("cvt.rna.tf32.f32 %0, %1;" : "=r"(u) : "f"(x));
    return u;
}

__device__ __forceinline__ void mma_tf32(float c[4], const uint32_t a[4],
                                         uint32_t b0, uint32_t b1) {
    asm volatile(
        "mma.sync.aligned.m16n8k8.row.col.f32.tf32.tf32.f32 "
        "{%0,%1,%2,%3}, {%4,%5,%6,%7}, {%8,%9}, {%0,%1,%2,%3};"
        : "+f"(c[0]), "+f"(c[1]), "+f"(c[2]), "+f"(c[3])
        : "r"(a[0]), "r"(a[1]), "r"(a[2]), "r"(a[3]), "r"(b0), "r"(b1));
}

__device__ __forceinline__ void ldsm_x4(uint32_t& r0, uint32_t& r1,
                                        uint32_t& r2, uint32_t& r3,
                                        const void* p) {
    uint32_t a = (uint32_t)__cvta_generic_to_shared(p);
    asm volatile("ldmatrix.sync.aligned.m8n8.x4.shared.b16 {%0,%1,%2,%3}, [%4];"
                 : "=r"(r0), "=r"(r1), "=r"(r2), "=r"(r3) : "r"(a));
}

// ----------------------------------------------------------------------------
// tf32 tensor-core GEMM: C[M,N] = A[M,K] @ B[K,N] + bias[N]   (unchanged R7)
// ----------------------------------------------------------------------------
#define AST 20
#define BST 264
#define A_WORDS (128 * AST)                 // 2560
#define B_WORDS (16 * BST)                  // 4224
#define SSTRIDE (A_WORDS + B_WORDS)         // 6784 words / stage
#define GEMM_SMEM (2 * SSTRIDE * 4)         // 54272 bytes

__global__ __launch_bounds__(256, 1) void tf32_gemm_bias(
    const float* __restrict__ A, const float* __restrict__ B,
    const float* __restrict__ bias, float* __restrict__ C,
    int M, int N, int K)
{
    extern __shared__ uint32_t smg[];

    const int tid = threadIdx.x;
    const int w = tid >> 5, lane = tid & 31;
    const int gr = lane >> 2, tg = lane & 3;
    const int m0w = (w & 1) * 64;
    const int n0w = (w >> 1) * 64;

    const int lq = lane >> 3;
    const int lr = lane & 7;
    const int a_row = lr + ((lq & 1) << 3);
    const int a_col = (lq >> 1) << 2;

    const float* Ag = A + (size_t)(blockIdx.y * 128) * K;
    const float* Bg = B + blockIdx.x * 256;

    const int a_srow = tid >> 2;
    const int a_sc4 = (tid & 3) << 2;
    const int b_kr0 = tid >> 6;
    const int b_c4 = (tid & 63) << 2;

    float c[4][8][4];
#pragma unroll
    for (int mi = 0; mi < 4; mi++)
#pragma unroll
        for (int nf = 0; nf < 8; nf++)
#pragma unroll
            for (int j = 0; j < 4; j++) c[mi][nf][j] = 0.f;

    const int nk = K >> 4;
    float4 ra[2], rb[4];

#pragma unroll
    for (int it = 0; it < 2; it++)
        ra[it] = *(const float4*)(Ag + (size_t)(a_srow + 64 * it) * K + a_sc4);
#pragma unroll
    for (int it = 0; it < 4; it++)
        rb[it] = *(const float4*)(Bg + (size_t)(b_kr0 + 4 * it) * N + b_c4);

    for (int kc = 0; kc < nk; kc++) {
        uint32_t* As = smg + (kc & 1) * SSTRIDE;
        uint32_t* Bs = As + A_WORDS;

#pragma unroll
        for (int it = 0; it < 2; it++) {
            uint4 ua;
            ua.x = f2tf32(ra[it].x); ua.y = f2tf32(ra[it].y);
            ua.z = f2tf32(ra[it].z); ua.w = f2tf32(ra[it].w);
            *(uint4*)(As + (a_srow + 64 * it) * AST + a_sc4) = ua;
        }
#pragma unroll
        for (int it = 0; it < 4; it++) {
            uint4 ub;
            ub.x = f2tf32(rb[it].x); ub.y = f2tf32(rb[it].y);
            ub.z = f2tf32(rb[it].z); ub.w = f2tf32(rb[it].w);
            *(uint4*)(Bs + (b_kr0 + 4 * it) * BST + b_c4) = ub;
        }
        __syncthreads();

        if (kc + 1 < nk) {
            const int k0 = (kc + 1) << 4;
#pragma unroll
            for (int it = 0; it < 2; it++)
                ra[it] = *(const float4*)(Ag + (size_t)(a_srow + 64 * it) * K + k0 + a_sc4);
#pragma unroll
            for (int it = 0; it < 4; it++)
                rb[it] = *(const float4*)(Bg + (size_t)(k0 + b_kr0 + 4 * it) * N + b_c4);
        }

#pragma unroll
        for (int kf = 0; kf < 2; kf++) {
            const int kb = kf << 3;
            uint32_t a[4][4];
#pragma unroll
            for (int mi = 0; mi < 4; mi++)
                ldsm_x4(a[mi][0], a[mi][1], a[mi][2], a[mi][3],
                        As + (m0w + 16 * mi + a_row) * AST + kb + a_col);
            const uint32_t* b0p = Bs + (kb + tg) * BST + n0w + gr;
            const uint32_t* b1p = b0p + 4 * BST;
#pragma unroll
            for (int nf = 0; nf < 8; nf++) {
                const uint32_t b0 = b0p[8 * nf];
                const uint32_t b1 = b1p[8 * nf];
#pragma unroll
                for (int mi = 0; mi < 4; mi++)
                    mma_tf32(c[mi][nf], a[mi], b0, b1);
            }
        }
    }

#pragma unroll
    for (int nf = 0; nf < 8; nf++) {
        const int col = blockIdx.x * 256 + n0w + 8 * nf + 2 * tg;
        const float bb0 = bias[col];
        const float bb1 = bias[col + 1];
#pragma unroll
        for (int mi = 0; mi < 4; mi++) {
            const size_t r0 = (size_t)(blockIdx.y * 128 + m0w + 16 * mi + gr);
            float2 v0, v1;
            v0.x = c[mi][nf][0] + bb0; v0.y = c[mi][nf][1] + bb1;
            v1.x = c[mi][nf][2] + bb0; v1.y = c[mi][nf][3] + bb1;
            *(float2*)(C + r0 * N + col)       = v0;
            *(float2*)(C + (r0 + 8) * N + col) = v1;
        }
    }
}

// ----------------------------------------------------------------------------
// Flash attention with tf32 tensor cores + register prefetch of K/V tiles.
// Block: 128 queries x one (b,h). 8 warps, warp w owns rows 16w..16w+15.
// smem: Ks [64][68], Vs [64][72] (V frag loads conflict-free),
//       Ps [8][16][68], Cb [64]. Q staged once over the Ks+Vs region.
// Next tile's K/V (8 float4/thread) + bias prefetched into registers
// during compute, hiding gmem latency.
// ----------------------------------------------------------------------------
#define KST 68
#define VST 72
#define PST 68
#define VS_OFF  (64 * KST)               // words
#define PS_OFF  (VS_OFF + 64 * VST)
#define CB_OFF  (PS_OFF + 8 * 16 * PST)
#define ATTN_SMEM ((CB_OFF + 64) * 4)    // 70912 bytes

__global__ __launch_bounds__(256) void attn_mma(
    const float* __restrict__ qkv,   // [BS, 3*NX]
    const float* __restrict__ ekv,   // [BP, 2*NX]
    const float* __restrict__ Mmask, // [B, P]
    const float* __restrict__ amask, // [B,1,1,S]
    float* __restrict__ out)         // [BS, NX]
{
    extern __shared__ float sm[];
    uint32_t* Ksu = (uint32_t*)sm;                 // [64][68]
    uint32_t* Vsu = (uint32_t*)(sm + VS_OFF);      // [64][72]
    float*    Ps  = sm + PS_OFF;                   // [8][16][68]
    float*    Cb  = sm + CB_OFF;                   // [64]
    uint32_t* Qtu = (uint32_t*)sm;                 // Q staged over Ks+Vs: [128][68]

    const int bh = blockIdx.y;
    const int b = bh >> 4, h = bh & 15;
    const int q0 = blockIdx.x * 128;
    const int tid = threadIdx.x;
    const int w = tid >> 5;
    const int lane = tid & 31;
    const int gr = lane >> 2;
    const int tg = lane & 3;

    // ---- Stage Q (scaled 1/8, tf32-rounded) into Qtmp [128][68] ----
#pragma unroll
    for (int it = 0; it < 8; it++) {
        const int fid = tid + it * 256;
        const int r = fid >> 4;
        const int c4 = (fid & 15) * 4;
        const float4 q = *(const float4*)(
            qkv + (size_t)(b * S_ + q0 + r) * (3 * NX_) + h * DH_ + c4);
        uint32_t* d = Qtu + r * KST + c4;
        d[0] = f2tf32(q.x * 0.125f);
        d[1] = f2tf32(q.y * 0.125f);
        d[2] = f2tf32(q.z * 0.125f);
        d[3] = f2tf32(q.w * 0.125f);
    }
    __syncthreads();

    uint32_t aQ[8][4];
    {
        const int r0 = 16 * w + gr;
#pragma unroll
        for (int kf = 0; kf < 8; kf++) {
            aQ[kf][0] = Qtu[r0 * KST + 8 * kf + tg];
            aQ[kf][1] = Qtu[(r0 + 8) * KST + 8 * kf + tg];
            aQ[kf][2] = Qtu[r0 * KST + 8 * kf + tg + 4];
            aQ[kf][3] = Qtu[(r0 + 8) * KST + 8 * kf + tg + 4];
        }
    }

    float m0 = -1e30f, m1 = -1e30f, l0 = 0.f, l1 = 0.f;
    float o[8][4];
#pragma unroll
    for (int nf = 0; nf < 8; nf++)
#pragma unroll
        for (int j = 0; j < 4; j++) o[nf][j] = 0.f;

    uint32_t* Pswu = (uint32_t*)(Ps + w * 16 * PST);
    const int r0g = q0 + 16 * w + gr;
    const int r1g = r0g + 8;
    const int ntiles = 2 * blockIdx.x + 4;

    // Staging thread mapping (fixed per thread): 4 iters, fid = tid + 256*it
    const int st_t  = tid >> 4;          // 0..15, +16*it
    const int st_c4 = (tid & 15) * 4;

    // ---- Prefetch tile 0 into registers ----
    float4 pk[4], pv[4];
    float cbv = 0.f;
#pragma unroll
    for (int it = 0; it < 4; it++) {
        const int t = st_t + 16 * it;
        const int tg_ = 0 * 64 + t;
        const float* kp;
        const float* vp;
        if (tg_ < P_) {
            const float* e = ekv + (size_t)(b * P_ + tg_) * (2 * NX_) + h * DH_;
            kp = e; vp = e + NX_;
        } else {
            const float* s = qkv + (size_t)(b * S_ + tg_ - P_) * (3 * NX_) + h * DH_;
            kp = s + NX_; vp = s + 2 * NX_;
        }
        pk[it] = *(const float4*)(kp + st_c4);
        pv[it] = *(const float4*)(vp + st_c4);
    }
    if (tid < 64) {
        const int t = tid;
        cbv = (t < P_) ? (1.f - Mmask[b * P_ + t]) * -10000.f
                       : amask[b * S_ + (t - P_)];
    }

    for (int kt = 0; kt < ntiles; kt++) {
        const int t0k = kt * 64;
        __syncthreads();   // previous compute (and aQ loads) done with Ks/Vs

        // ---- Store prefetched K/V tile (tf32-rounded) and bias ----
#pragma unroll
        for (int it = 0; it < 4; it++) {
            const int t = st_t + 16 * it;
            uint32_t* kd = Ksu + t * KST + st_c4;
            kd[0] = f2tf32(pk[it].x); kd[1] = f2tf32(pk[it].y);
            kd[2] = f2tf32(pk[it].z); kd[3] = f2tf32(pk[it].w);
            uint32_t* vd = Vsu + t * VST + st_c4;
            vd[0] = f2tf32(pv[it].x); vd[1] = f2tf32(pv[it].y);
            vd[2] = f2tf32(pv[it].z); vd[3] = f2tf32(pv[it].w);
        }
        if (tid < 64) Cb[tid] = cbv;
        __syncthreads();

        // ---- Prefetch tile kt+1 (latency hidden behind compute below) ----
        if (kt + 1 < ntiles) {
            const int t1 = t0k + 64;
#pragma unroll
            for (int it = 0; it < 4; it++) {
                const int tg_ = t1 + st_t + 16 * it;
                const float* kp;
                const float* vp;
                if (tg_ < P_) {
                    const float* e = ekv + (size_t)(b * P_ + tg_) * (2 * NX_) + h * DH_;
                    kp = e; vp = e + NX_;
                } else {
                    const float* s = qkv + (size_t)(b * S_ + tg_ - P_) * (3 * NX_) + h * DH_;
                    kp = s + NX_; vp = s + 2 * NX_;
                }
                pk[it] = *(const float4*)(kp + st_c4);
                pv[it] = *(const float4*)(vp + st_c4);
            }
            if (tid < 64) {
                const int t = t1 + tid;
                cbv = (t < P_) ? (1.f - Mmask[b * P_ + t]) * -10000.f
                               : amask[b * S_ + (t - P_)];
            }
        }

        // ---- S = Q @ K^T ----
        float s[8][4];
#pragma unroll
        for (int nf = 0; nf < 8; nf++)
#pragma unroll
            for (int j = 0; j < 4; j++) s[nf][j] = 0.f;

#pragma unroll
        for (int kf = 0; kf < 8; kf++) {
#pragma unroll
            for (int nf = 0; nf < 8; nf++) {
                const uint32_t kb0 = Ksu[(8 * nf + gr) * KST + 8 * kf + tg];
                const uint32_t kb1 = Ksu[(8 * nf + gr) * KST + 8 * kf + tg + 4];
                mma_tf32(s[nf], aQ[kf], kb0, kb1);
            }
        }

        // ---- Mask + online softmax ----
        float mx0 = -1e30f, mx1 = -1e30f;
#pragma unroll
        for (int nf = 0; nf < 8; nf++) {
            const int tc = t0k + 8 * nf + 2 * tg;
            const float cb0 = Cb[8 * nf + 2 * tg];
            const float cb1 = Cb[8 * nf + 2 * tg + 1];
            const int ts0 = tc - P_;
            const int ts1 = ts0 + 1;
            const float l00 = (ts0 <= r0g ? s[nf][0] : -10000.f) + cb0;
            const float l01 = (ts1 <= r0g ? s[nf][1] : -10000.f) + cb1;
            const float l10 = (ts0 <= r1g ? s[nf][2] : -10000.f) + cb0;
            const float l11 = (ts1 <= r1g ? s[nf][3] : -10000.f) + cb1;
            s[nf][0] = l00; s[nf][1] = l01; s[nf][2] = l10; s[nf][3] = l11;
            mx0 = fmaxf(mx0, fmaxf(l00, l01));
            mx1 = fmaxf(mx1, fmaxf(l10, l11));
        }
        mx0 = fmaxf(mx0, __shfl_xor_sync(0xffffffffu, mx0, 1));
        mx0 = fmaxf(mx0, __shfl_xor_sync(0xffffffffu, mx0, 2));
        mx1 = fmaxf(mx1, __shfl_xor_sync(0xffffffffu, mx1, 1));
        mx1 = fmaxf(mx1, __shfl_xor_sync(0xffffffffu, mx1, 2));

        const float nm0 = fmaxf(m0, mx0);
        const float nm1 = fmaxf(m1, mx1);
        const float al0 = __expf(m0 - nm0);
        const float al1 = __expf(m1 - nm1);
        float ps0 = 0.f, ps1 = 0.f;
#pragma unroll
        for (int nf = 0; nf < 8; nf++) {
            const float p00 = __expf(s[nf][0] - nm0);
            const float p01 = __expf(s[nf][1] - nm0);
            const float p10 = __expf(s[nf][2] - nm1);
            const float p11 = __expf(s[nf][3] - nm1);
            ps0 += p00 + p01;
            ps1 += p10 + p11;
            Pswu[gr * PST + 8 * nf + 2 * tg]           = f2tf32(p00);
            Pswu[gr * PST + 8 * nf + 2 * tg + 1]       = f2tf32(p01);
            Pswu[(gr + 8) * PST + 8 * nf + 2 * tg]     = f2tf32(p10);
            Pswu[(gr + 8) * PST + 8 * nf + 2 * tg + 1] = f2tf32(p11);
        }
        ps0 += __shfl_xor_sync(0xffffffffu, ps0, 1);
        ps0 += __shfl_xor_sync(0xffffffffu, ps0, 2);
        ps1 += __shfl_xor_sync(0xffffffffu, ps1, 1);
        ps1 += __shfl_xor_sync(0xffffffffu, ps1, 2);
        l0 = l0 * al0 + ps0;
        l1 = l1 * al1 + ps1;
        m0 = nm0; m1 = nm1;

#pragma unroll
        for (int nf = 0; nf < 8; nf++) {
            o[nf][0] *= al0; o[nf][1] *= al0;
            o[nf][2] *= al1; o[nf][3] *= al1;
        }
        __syncwarp();

        // ---- O += P @ V (V loads conflict-free with stride 72) ----
#pragma unroll
        for (int kf = 0; kf < 8; kf++) {
            uint32_t aP[4];
            aP[0] = Pswu[gr * PST + 8 * kf + tg];
            aP[1] = Pswu[(gr + 8) * PST + 8 * kf + tg];
            aP[2] = Pswu[gr * PST + 8 * kf + tg + 4];
            aP[3] = Pswu[(gr + 8) * PST + 8 * kf + tg + 4];
#pragma unroll
            for (int nf = 0; nf < 8; nf++) {
                const uint32_t vb0 = Vsu[(8 * kf + tg) * VST + 8 * nf + gr];
                const uint32_t vb1 = Vsu[(8 * kf + tg + 4) * VST + 8 * nf + gr];
                mma_tf32(o[nf], aP, vb0, vb1);
            }
        }
    }

    const float inv0 = 1.f / l0;
    const float inv1 = 1.f / l1;
#pragma unroll
    for (int nf = 0; nf < 8; nf++) {
        const size_t base0 = (size_t)(b * S_ + r0g) * NX_ + h * DH_ + 8 * nf + 2 * tg;
        const size_t base1 = (size_t)(b * S_ + r1g) * NX_ + h * DH_ + 8 * nf + 2 * tg;
        float2 v0, v1;
        v0.x = o[nf][0] * inv0; v0.y = o[nf][1] * inv0;
        v1.x = o[nf][2] * inv1; v1.y = o[nf][3] * inv1;
        *(float2*)(out + base0) = v0;
        *(float2*)(out + base1) = v1;
    }
}

// ----------------------------------------------------------------------------
// Launch
// ----------------------------------------------------------------------------
extern "C" void kernel_launch(void* const* d_in, const int* in_sizes, int n_in,
                              void* d_out, int out_size)
{
    const float* x      = (const float*)d_in[0];
    const float* M      = (const float*)d_in[1];
    const float* Mmask  = (const float*)d_in[2];
    const float* amask  = (const float*)d_in[3];
    const float* W_attn = (const float*)d_in[4];
    const float* b_attn = (const float*)d_in[5];
    const float* W_mem  = (const float*)d_in[6];
    const float* b_mem  = (const float*)d_in[7];
    const float* W_proj = (const float*)d_in[8];
    const float* b_proj = (const float*)d_in[9];
    float* out = (float*)d_out;

    float* qkv; cudaGetSymbolAddress((void**)&qkv, g_qkv);
    float* ekv; cudaGetSymbolAddress((void**)&ekv, g_ekv);
    float* a;   cudaGetSymbolAddress((void**)&a,   g_a);

    cudaFuncSetAttribute(tf32_gemm_bias, cudaFuncAttributeMaxDynamicSharedMemorySize,
                         GEMM_SMEM);
    cudaFuncSetAttribute(attn_mma, cudaFuncAttributeMaxDynamicSharedMemorySize,
                         ATTN_SMEM);

    // 1) qkv = x @ W_attn + b_attn
    {
        dim3 grid(3 * NX_ / 256, BS_ / 128);
        tf32_gemm_bias<<<grid, 256, GEMM_SMEM>>>(x, W_attn, b_attn, qkv, BS_, 3 * NX_, NX_);
    }
    // 2) ekv = M @ W_mem + b_mem
    {
        dim3 grid(2 * NX_ / 256, BP_ / 128);
        tf32_gemm_bias<<<grid, 256, GEMM_SMEM>>>(M, W_mem, b_mem, ekv, BP_, 2 * NX_, NX_);
    }
    // 3) flash attention (tensor cores, prefetched) -> a
    {
        dim3 grid(S_ / 128, B_ * H_);
        attn_mma<<<grid, 256, ATTN_SMEM>>>(qkv, ekv, Mmask, amask, a);
    }
    // 4) out = a @ W_proj + b_proj
    {
        dim3 grid(NX_ / 256, BS_ / 128);
        tf32_gemm_bias<<<grid, 256, GEMM_SMEM>>>(a, W_proj, b_proj, out, BS_, NX_, NX_);
    }
}

// round 9
// speedup vs baseline: 6.7296x; 1.0320x over previous
#include <cuda_runtime.h>
#include <cuda_bf16.h>
#include <cstdint>

// Problem constants
#define B_   4
#define S_   1024
#define P_   128
#define NX_  1024
#define H_   16
#define DH_  64
#define T_   (P_ + S_)      // 1152
#define BS_  (B_ * S_)      // 4096
#define BP_  (B_ * P_)      // 512

// Scratch (static device globals; no allocation allowed)
__device__ float g_qkv[(size_t)BS_ * 3 * NX_];   // [4096, 3072] fp32
__device__ float g_ekv[(size_t)BP_ * 2 * NX_];   // [512, 2048]  fp32
__device__ float g_a  [(size_t)BS_ * NX_];       // [4096, 1024] tf32 bits
// tf32-preconverted GEMM operands
__device__ uint32_t g_xt[(size_t)BS_ * NX_];         // x
__device__ uint32_t g_mt[(size_t)BP_ * NX_];         // M
__device__ uint32_t g_wa[(size_t)NX_ * 3 * NX_];     // W_attn
__device__ uint32_t g_wm[(size_t)NX_ * 2 * NX_];     // W_mem
__device__ uint32_t g_wp[(size_t)NX_ * NX_];         // W_proj

// ----------------------------------------------------------------------------
// Common MMA helpers
// ----------------------------------------------------------------------------
__device__ __forceinline__ uint32_t f2tf32(float x) {
    uint32_t u;
    asm("cvt.rna.tf32.f32 %0, %1;" : "=r"(u) : "f"(x));
    return u;
}

__device__ __forceinline__ void mma_tf32(float c[4], const uint32_t a[4],
                                         uint32_t b0, uint32_t b1) {
    asm volatile(
        "mma.sync.aligned.m16n8k8.row.col.f32.tf32.tf32.f32 "
        "{%0,%1,%2,%3}, {%4,%5,%6,%7}, {%8,%9}, {%0,%1,%2,%3};"
        : "+f"(c[0]), "+f"(c[1]), "+f"(c[2]), "+f"(c[3])
        : "r"(a[0]), "r"(a[1]), "r"(a[2]), "r"(a[3]), "r"(b0), "r"(b1));
}

__device__ __forceinline__ void ldsm_x4(uint32_t& r0, uint32_t& r1,
                                        uint32_t& r2, uint32_t& r3,
                                        const void* p) {
    uint32_t a = (uint32_t)__cvta_generic_to_shared(p);
    asm volatile("ldmatrix.sync.aligned.m8n8.x4.shared.b16 {%0,%1,%2,%3}, [%4];"
                 : "=r"(r0), "=r"(r1), "=r"(r2), "=r"(r3) : "r"(a));
}

__device__ __forceinline__ void cp_async16(uint32_t smem_addr, const void* gptr) {
    asm volatile("cp.async.cg.shared.global [%0], [%1], 16;"
                 :: "r"(smem_addr), "l"(gptr));
}
__device__ __forceinline__ void cp_commit() {
    asm volatile("cp.async.commit_group;");
}
template <int N>
__device__ __forceinline__ void cp_wait() {
    asm volatile("cp.async.wait_group %0;" :: "n"(N));
}

// ----------------------------------------------------------------------------
// tf32 pre-conversion (rna), vectorized grid-stride
// ----------------------------------------------------------------------------
__global__ void cvt_tf32_kernel(const float* __restrict__ src,
                                uint32_t* __restrict__ dst, int n4)
{
    for (int i = blockIdx.x * blockDim.x + threadIdx.x; i < n4;
         i += gridDim.x * blockDim.x) {
        const float4 v = ((const float4*)src)[i];
        uint4 u;
        u.x = f2tf32(v.x); u.y = f2tf32(v.y);
        u.z = f2tf32(v.z); u.w = f2tf32(v.w);
        ((uint4*)dst)[i] = u;
    }
}

// ----------------------------------------------------------------------------
// tf32 tensor-core GEMM, 3-stage cp.async pipeline.
// C[M,N] = A[M,K] @ B[K,N] + bias[N]; A,B already tf32 bits.
// Block 128(M) x 256(N), 8 warps (2M x 4N), warp tile m64 x n64, K-chunk 16.
// As [m=128][k=16] stride 20, Bs [k=16][n=256] stride 264.
// ----------------------------------------------------------------------------
#define AST 20
#define BST 264
#define A_WORDS (128 * AST)                 // 2560
#define B_WORDS (16 * BST)                  // 4224
#define SSTRIDE (A_WORDS + B_WORDS)         // 6784 words / stage
#define GSTAGES 3
#define GEMM_SMEM (GSTAGES * SSTRIDE * 4)   // 81408 bytes

__global__ __launch_bounds__(256, 1) void tf32_gemm_bias(
    const uint32_t* __restrict__ A, const uint32_t* __restrict__ B,
    const float* __restrict__ bias, float* __restrict__ C,
    int M, int N, int K)
{
    extern __shared__ uint32_t smg[];
    const uint32_t smem_base = (uint32_t)__cvta_generic_to_shared(smg);

    const int tid = threadIdx.x;
    const int w = tid >> 5, lane = tid & 31;
    const int gr = lane >> 2, tg = lane & 3;
    const int m0w = (w & 1) * 64;
    const int n0w = (w >> 1) * 64;

    const int lq = lane >> 3;
    const int lr = lane & 7;
    const int a_row = lr + ((lq & 1) << 3);
    const int a_col = (lq >> 1) << 2;

    const uint32_t* Ag = A + (size_t)(blockIdx.y * 128) * K;
    const uint32_t* Bg = B + blockIdx.x * 256;

    const int a_srow = tid >> 2;             // 0..63, +64*it
    const int a_sc4 = (tid & 3) << 2;        // 0,4,8,12
    const int b_kr0 = tid >> 6;              // 0..3, +4*it
    const int b_c4 = (tid & 63) << 2;        // 0..252

    const int nk = K >> 4;

    // Issue one K-chunk's cp.asyncs into stage (kc % 3), then commit.
    auto issue = [&](int kc) {
        const int st = kc % GSTAGES;
        const int k0 = kc << 4;
        const uint32_t abase = smem_base + (uint32_t)(st * SSTRIDE) * 4;
        const uint32_t bbase = abase + A_WORDS * 4;
#pragma unroll
        for (int it = 0; it < 2; it++) {
            const int row = a_srow + 64 * it;
            cp_async16(abase + (uint32_t)(row * AST + a_sc4) * 4,
                       Ag + (size_t)row * K + k0 + a_sc4);
        }
#pragma unroll
        for (int it = 0; it < 4; it++) {
            const int kr = b_kr0 + 4 * it;
            cp_async16(bbase + (uint32_t)(kr * BST + b_c4) * 4,
                       Bg + (size_t)(k0 + kr) * N + b_c4);
        }
        cp_commit();
    };

    float c[4][8][4];
#pragma unroll
    for (int mi = 0; mi < 4; mi++)
#pragma unroll
        for (int nf = 0; nf < 8; nf++)
#pragma unroll
            for (int j = 0; j < 4; j++) c[mi][nf][j] = 0.f;

    // Prologue: 2 chunks in flight
    issue(0);
    issue(1);

    for (int kc = 0; kc < nk; kc++) {
        if (kc == nk - 1) cp_wait<0>(); else cp_wait<1>();
        __syncthreads();

        if (kc + 2 < nk) issue(kc + 2);   // fills stage freed by compute(kc-1)

        const uint32_t* As = smg + (kc % GSTAGES) * SSTRIDE;
        const uint32_t* Bs = As + A_WORDS;

#pragma unroll
        for (int kf = 0; kf < 2; kf++) {
            const int kb = kf << 3;
            uint32_t a[4][4];
#pragma unroll
            for (int mi = 0; mi < 4; mi++)
                ldsm_x4(a[mi][0], a[mi][1], a[mi][2], a[mi][3],
                        As + (m0w + 16 * mi + a_row) * AST + kb + a_col);
            const uint32_t* b0p = Bs + (kb + tg) * BST + n0w + gr;
            const uint32_t* b1p = b0p + 4 * BST;
#pragma unroll
            for (int nf = 0; nf < 8; nf++) {
                const uint32_t b0 = b0p[8 * nf];
                const uint32_t b1 = b1p[8 * nf];
#pragma unroll
                for (int mi = 0; mi < 4; mi++)
                    mma_tf32(c[mi][nf], a[mi], b0, b1);
            }
        }
        __syncthreads();   // all warps done with stage before it is refilled
    }

    // Epilogue with bias
#pragma unroll
    for (int nf = 0; nf < 8; nf++) {
        const int col = blockIdx.x * 256 + n0w + 8 * nf + 2 * tg;
        const float bb0 = bias[col];
        const float bb1 = bias[col + 1];
#pragma unroll
        for (int mi = 0; mi < 4; mi++) {
            const size_t r0 = (size_t)(blockIdx.y * 128 + m0w + 16 * mi + gr);
            float2 v0, v1;
            v0.x = c[mi][nf][0] + bb0; v0.y = c[mi][nf][1] + bb1;
            v1.x = c[mi][nf][2] + bb0; v1.y = c[mi][nf][3] + bb1;
            *(float2*)(C + r0 * N + col)       = v0;
            *(float2*)(C + (r0 + 8) * N + col) = v1;
        }
    }
}

// ----------------------------------------------------------------------------
// Flash attention with tf32 tensor cores + register prefetch (R8 structure).
// Epilogue now writes tf32-rounded values (idempotent for the proj GEMM).
// ----------------------------------------------------------------------------
#define KST 68
#define VST 72
#define PST 68
#define VS_OFF  (64 * KST)
#define PS_OFF  (VS_OFF + 64 * VST)
#define CB_OFF  (PS_OFF + 8 * 16 * PST)
#define ATTN_SMEM ((CB_OFF + 64) * 4)

__global__ __launch_bounds__(256) void attn_mma(
    const float* __restrict__ qkv,   // [BS, 3*NX]
    const float* __restrict__ ekv,   // [BP, 2*NX]
    const float* __restrict__ Mmask, // [B, P]
    const float* __restrict__ amask, // [B,1,1,S]
    float* __restrict__ out)         // [BS, NX] (tf32-rounded bits)
{
    extern __shared__ float sm[];
    uint32_t* Ksu = (uint32_t*)sm;
    uint32_t* Vsu = (uint32_t*)(sm + VS_OFF);
    float*    Ps  = sm + PS_OFF;
    float*    Cb  = sm + CB_OFF;
    uint32_t* Qtu = (uint32_t*)sm;

    const int bh = blockIdx.y;
    const int b = bh >> 4, h = bh & 15;
    const int q0 = blockIdx.x * 128;
    const int tid = threadIdx.x;
    const int w = tid >> 5;
    const int lane = tid & 31;
    const int gr = lane >> 2;
    const int tg = lane & 3;

#pragma unroll
    for (int it = 0; it < 8; it++) {
        const int fid = tid + it * 256;
        const int r = fid >> 4;
        const int c4 = (fid & 15) * 4;
        const float4 q = *(const float4*)(
            qkv + (size_t)(b * S_ + q0 + r) * (3 * NX_) + h * DH_ + c4);
        uint32_t* d = Qtu + r * KST + c4;
        d[0] = f2tf32(q.x * 0.125f);
        d[1] = f2tf32(q.y * 0.125f);
        d[2] = f2tf32(q.z * 0.125f);
        d[3] = f2tf32(q.w * 0.125f);
    }
    __syncthreads();

    uint32_t aQ[8][4];
    {
        const int r0 = 16 * w + gr;
#pragma unroll
        for (int kf = 0; kf < 8; kf++) {
            aQ[kf][0] = Qtu[r0 * KST + 8 * kf + tg];
            aQ[kf][1] = Qtu[(r0 + 8) * KST + 8 * kf + tg];
            aQ[kf][2] = Qtu[r0 * KST + 8 * kf + tg + 4];
            aQ[kf][3] = Qtu[(r0 + 8) * KST + 8 * kf + tg + 4];
        }
    }

    float m0 = -1e30f, m1 = -1e30f, l0 = 0.f, l1 = 0.f;
    float o[8][4];
#pragma unroll
    for (int nf = 0; nf < 8; nf++)
#pragma unroll
        for (int j = 0; j < 4; j++) o[nf][j] = 0.f;

    uint32_t* Pswu = (uint32_t*)(Ps + w * 16 * PST);
    const int r0g = q0 + 16 * w + gr;
    const int r1g = r0g + 8;
    const int ntiles = 2 * blockIdx.x + 4;

    const int st_t  = tid >> 4;
    const int st_c4 = (tid & 15) * 4;

    float4 pk[4], pv[4];
    float cbv = 0.f;
#pragma unroll
    for (int it = 0; it < 4; it++) {
        const int tg_ = st_t + 16 * it;
        const float* kp;
        const float* vp;
        if (tg_ < P_) {
            const float* e = ekv + (size_t)(b * P_ + tg_) * (2 * NX_) + h * DH_;
            kp = e; vp = e + NX_;
        } else {
            const float* s = qkv + (size_t)(b * S_ + tg_ - P_) * (3 * NX_) + h * DH_;
            kp = s + NX_; vp = s + 2 * NX_;
        }
        pk[it] = *(const float4*)(kp + st_c4);
        pv[it] = *(const float4*)(vp + st_c4);
    }
    if (tid < 64) {
        cbv = (tid < P_) ? (1.f - Mmask[b * P_ + tid]) * -10000.f
                         : amask[b * S_ + (tid - P_)];
    }

    for (int kt = 0; kt < ntiles; kt++) {
        const int t0k = kt * 64;
        __syncthreads();

#pragma unroll
        for (int it = 0; it < 4; it++) {
            const int t = st_t + 16 * it;
            uint32_t* kd = Ksu + t * KST + st_c4;
            kd[0] = f2tf32(pk[it].x); kd[1] = f2tf32(pk[it].y);
            kd[2] = f2tf32(pk[it].z); kd[3] = f2tf32(pk[it].w);
            uint32_t* vd = Vsu + t * VST + st_c4;
            vd[0] = f2tf32(pv[it].x); vd[1] = f2tf32(pv[it].y);
            vd[2] = f2tf32(pv[it].z); vd[3] = f2tf32(pv[it].w);
        }
        if (tid < 64) Cb[tid] = cbv;
        __syncthreads();

        if (kt + 1 < ntiles) {
            const int t1 = t0k + 64;
#pragma unroll
            for (int it = 0; it < 4; it++) {
                const int tg_ = t1 + st_t + 16 * it;
                const float* kp;
                const float* vp;
                if (tg_ < P_) {
                    const float* e = ekv + (size_t)(b * P_ + tg_) * (2 * NX_) + h * DH_;
                    kp = e; vp = e + NX_;
                } else {
                    const float* s = qkv + (size_t)(b * S_ + tg_ - P_) * (3 * NX_) + h * DH_;
                    kp = s + NX_; vp = s + 2 * NX_;
                }
                pk[it] = *(const float4*)(kp + st_c4);
                pv[it] = *(const float4*)(vp + st_c4);
            }
            if (tid < 64) {
                const int t = t1 + tid;
                cbv = (t < P_) ? (1.f - Mmask[b * P_ + t]) * -10000.f
                               : amask[b * S_ + (t - P_)];
            }
        }

        float s[8][4];
#pragma unroll
        for (int nf = 0; nf < 8; nf++)
#pragma unroll
            for (int j = 0; j < 4; j++) s[nf][j] = 0.f;

#pragma unroll
        for (int kf = 0; kf < 8; kf++) {
#pragma unroll
            for (int nf = 0; nf < 8; nf++) {
                const uint32_t kb0 = Ksu[(8 * nf + gr) * KST + 8 * kf + tg];
                const uint32_t kb1 = Ksu[(8 * nf + gr) * KST + 8 * kf + tg + 4];
                mma_tf32(s[nf], aQ[kf], kb0, kb1);
            }
        }

        float mx0 = -1e30f, mx1 = -1e30f;
#pragma unroll
        for (int nf = 0; nf < 8; nf++) {
            const int tc = t0k + 8 * nf + 2 * tg;
            const float cb0 = Cb[8 * nf + 2 * tg];
            const float cb1 = Cb[8 * nf + 2 * tg + 1];
            const int ts0 = tc - P_;
            const int ts1 = ts0 + 1;
            const float l00 = (ts0 <= r0g ? s[nf][0] : -10000.f) + cb0;
            const float l01 = (ts1 <= r0g ? s[nf][1] : -10000.f) + cb1;
            const float l10 = (ts0 <= r1g ? s[nf][2] : -10000.f) + cb0;
            const float l11 = (ts1 <= r1g ? s[nf][3] : -10000.f) + cb1;
            s[nf][0] = l00; s[nf][1] = l01; s[nf][2] = l10; s[nf][3] = l11;
            mx0 = fmaxf(mx0, fmaxf(l00, l01));
            mx1 = fmaxf(mx1, fmaxf(l10, l11));
        }
        mx0 = fmaxf(mx0, __shfl_xor_sync(0xffffffffu, mx0, 1));
        mx0 = fmaxf(mx0, __shfl_xor_sync(0xffffffffu, mx0, 2));
        mx1 = fmaxf(mx1, __shfl_xor_sync(0xffffffffu, mx1, 1));
        mx1 = fmaxf(mx1, __shfl_xor_sync(0xffffffffu, mx1, 2));

        const float nm0 = fmaxf(m0, mx0);
        const float nm1 = fmaxf(m1, mx1);
        const float al0 = __expf(m0 - nm0);
        const float al1 = __expf(m1 - nm1);
        float ps0 = 0.f, ps1 = 0.f;
#pragma unroll
        for (int nf = 0; nf < 8; nf++) {
            const float p00 = __expf(s[nf][0] - nm0);
            const float p01 = __expf(s[nf][1] - nm0);
            const float p10 = __expf(s[nf][2] - nm1);
            const float p11 = __expf(s[nf][3] - nm1);
            ps0 += p00 + p01;
            ps1 += p10 + p11;
            Pswu[gr * PST + 8 * nf + 2 * tg]           = f2tf32(p00);
            Pswu[gr * PST + 8 * nf + 2 * tg + 1]       = f2tf32(p01);
            Pswu[(gr + 8) * PST + 8 * nf + 2 * tg]     = f2tf32(p10);
            Pswu[(gr + 8) * PST + 8 * nf + 2 * tg + 1] = f2tf32(p11);
        }
        ps0 += __shfl_xor_sync(0xffffffffu, ps0, 1);
        ps0 += __shfl_xor_sync(0xffffffffu, ps0, 2);
        ps1 += __shfl_xor_sync(0xffffffffu, ps1, 1);
        ps1 += __shfl_xor_sync(0xffffffffu, ps1, 2);
        l0 = l0 * al0 + ps0;
        l1 = l1 * al1 + ps1;
        m0 = nm0; m1 = nm1;

#pragma unroll
        for (int nf = 0; nf < 8; nf++) {
            o[nf][0] *= al0; o[nf][1] *= al0;
            o[nf][2] *= al1; o[nf][3] *= al1;
        }
        __syncwarp();

#pragma unroll
        for (int kf = 0; kf < 8; kf++) {
            uint32_t aP[4];
            aP[0] = Pswu[gr * PST + 8 * kf + tg];
            aP[1] = Pswu[(gr + 8) * PST + 8 * kf + tg];
            aP[2] = Pswu[gr * PST + 8 * kf + tg + 4];
            aP[3] = Pswu[(gr + 8) * PST + 8 * kf + tg + 4];
#pragma unroll
            for (int nf = 0; nf < 8; nf++) {
                const uint32_t vb0 = Vsu[(8 * kf + tg) * VST + 8 * nf + gr];
                const uint32_t vb1 = Vsu[(8 * kf + tg + 4) * VST + 8 * nf + gr];
                mma_tf32(o[nf], aP, vb0, vb1);
            }
        }
    }

    const float inv0 = 1.f / l0;
    const float inv1 = 1.f / l1;
#pragma unroll
    for (int nf = 0; nf < 8; nf++) {
        const size_t base0 = (size_t)(b * S_ + r0g) * NX_ + h * DH_ + 8 * nf + 2 * tg;
        const size_t base1 = (size_t)(b * S_ + r1g) * NX_ + h * DH_ + 8 * nf + 2 * tg;
        uint2 v0, v1;   // tf32-rounded bits (idempotent for the proj GEMM)
        v0.x = f2tf32(o[nf][0] * inv0); v0.y = f2tf32(o[nf][1] * inv0);
        v1.x = f2tf32(o[nf][2] * inv1); v1.y = f2tf32(o[nf][3] * inv1);
        *(uint2*)((uint32_t*)out + base0) = v0;
        *(uint2*)((uint32_t*)out + base1) = v1;
    }
}

// ----------------------------------------------------------------------------
// Launch
// ----------------------------------------------------------------------------
extern "C" void kernel_launch(void* const* d_in, const int* in_sizes, int n_in,
                              void* d_out, int out_size)
{
    const float* x      = (const float*)d_in[0];
    const float* M      = (const float*)d_in[1];
    const float* Mmask  = (const float*)d_in[2];
    const float* amask  = (const float*)d_in[3];
    const float* W_attn = (const float*)d_in[4];
    const float* b_attn = (const float*)d_in[5];
    const float* W_mem  = (const float*)d_in[6];
    const float* b_mem  = (const float*)d_in[7];
    const float* W_proj = (const float*)d_in[8];
    const float* b_proj = (const float*)d_in[9];
    float* out = (float*)d_out;

    float* qkv; cudaGetSymbolAddress((void**)&qkv, g_qkv);
    float* ekv; cudaGetSymbolAddress((void**)&ekv, g_ekv);
    float* a;   cudaGetSymbolAddress((void**)&a,   g_a);
    uint32_t* xt; cudaGetSymbolAddress((void**)&xt, g_xt);
    uint32_t* mt; cudaGetSymbolAddress((void**)&mt, g_mt);
    uint32_t* wa; cudaGetSymbolAddress((void**)&wa, g_wa);
    uint32_t* wm; cudaGetSymbolAddress((void**)&wm, g_wm);
    uint32_t* wp; cudaGetSymbolAddress((void**)&wp, g_wp);

    cudaFuncSetAttribute(tf32_gemm_bias, cudaFuncAttributeMaxDynamicSharedMemorySize,
                         GEMM_SMEM);
    cudaFuncSetAttribute(attn_mma, cudaFuncAttributeMaxDynamicSharedMemorySize,
                         ATTN_SMEM);

    // 0) tf32 pre-conversion of GEMM operands
    cvt_tf32_kernel<<<1024, 256>>>(x, xt, BS_ * NX_ / 4);
    cvt_tf32_kernel<<<512,  256>>>(M, mt, BP_ * NX_ / 4);
    cvt_tf32_kernel<<<1024, 256>>>(W_attn, wa, NX_ * 3 * NX_ / 4);
    cvt_tf32_kernel<<<1024, 256>>>(W_mem, wm, NX_ * 2 * NX_ / 4);
    cvt_tf32_kernel<<<512,  256>>>(W_proj, wp, NX_ * NX_ / 4);

    // 1) qkv = x @ W_attn + b_attn
    {
        dim3 grid(3 * NX_ / 256, BS_ / 128);
        tf32_gemm_bias<<<grid, 256, GEMM_SMEM>>>(xt, wa, b_attn, qkv, BS_, 3 * NX_, NX_);
    }
    // 2) ekv = M @ W_mem + b_mem
    {
        dim3 grid(2 * NX_ / 256, BP_ / 128);
        tf32_gemm_bias<<<grid, 256, GEMM_SMEM>>>(mt, wm, b_mem, ekv, BP_, 2 * NX_, NX_);
    }
    // 3) flash attention (tensor cores, prefetched) -> a (tf32-rounded)
    {
        dim3 grid(S_ / 128, B_ * H_);
        attn_mma<<<grid, 256, ATTN_SMEM>>>(qkv, ekv, Mmask, amask, a);
    }
    // 4) out = a @ W_proj + b_proj
    {
        dim3 grid(NX_ / 256, BS_ / 128);
        tf32_gemm_bias<<<grid, 256, GEMM_SMEM>>>((const uint32_t*)a, wp, b_proj, out,
                                                 BS_, NX_, NX_);
    }
}

// round 10
// speedup vs baseline: 6.7685x; 1.0058x over previous
#include <cuda_runtime.h>
#include <cuda_bf16.h>
#include <cstdint>

// Problem constants
#define B_   4
#define S_   1024
#define P_   128
#define NX_  1024
#define H_   16
#define DH_  64
#define T_   (P_ + S_)      // 1152
#define BS_  (B_ * S_)      // 4096
#define BP_  (B_ * P_)      // 512

// Scratch (static device globals; no allocation allowed)
__device__ float g_qkv[(size_t)BS_ * 3 * NX_];   // [4096, 3072] fp32
__device__ float g_ekv[(size_t)BP_ * 2 * NX_];   // [512, 2048]  fp32
__device__ float g_a  [(size_t)BS_ * NX_];       // [4096, 1024] tf32 bits
// tf32-preconverted GEMM operands
__device__ uint32_t g_xt[(size_t)BS_ * NX_];
__device__ uint32_t g_mt[(size_t)BP_ * NX_];
__device__ uint32_t g_wa[(size_t)NX_ * 3 * NX_];
__device__ uint32_t g_wm[(size_t)NX_ * 2 * NX_];
__device__ uint32_t g_wp[(size_t)NX_ * NX_];

// ----------------------------------------------------------------------------
// Common MMA helpers
// ----------------------------------------------------------------------------
__device__ __forceinline__ uint32_t f2tf32(float x) {
    uint32_t u;
    asm("cvt.rna.tf32.f32 %0, %1;" : "=r"(u) : "f"(x));
    return u;
}

__device__ __forceinline__ void mma_tf32(float c[4], const uint32_t a[4],
                                         uint32_t b0, uint32_t b1) {
    asm volatile(
        "mma.sync.aligned.m16n8k8.row.col.f32.tf32.tf32.f32 "
        "{%0,%1,%2,%3}, {%4,%5,%6,%7}, {%8,%9}, {%0,%1,%2,%3};"
        : "+f"(c[0]), "+f"(c[1]), "+f"(c[2]), "+f"(c[3])
        : "r"(a[0]), "r"(a[1]), "r"(a[2]), "r"(a[3]), "r"(b0), "r"(b1));
}

__device__ __forceinline__ void ldsm_x4(uint32_t& r0, uint32_t& r1,
                                        uint32_t& r2, uint32_t& r3,
                                        const void* p) {
    uint32_t a = (uint32_t)__cvta_generic_to_shared(p);
    asm volatile("ldmatrix.sync.aligned.m8n8.x4.shared.b16 {%0,%1,%2,%3}, [%4];"
                 : "=r"(r0), "=r"(r1), "=r"(r2), "=r"(r3) : "r"(a));
}

__device__ __forceinline__ void cp_async16(uint32_t smem_addr, const void* gptr) {
    asm volatile("cp.async.cg.shared.global [%0], [%1], 16;"
                 :: "r"(smem_addr), "l"(gptr));
}
__device__ __forceinline__ void cp_commit() {
    asm volatile("cp.async.commit_group;");
}
template <int N>
__device__ __forceinline__ void cp_wait() {
    asm volatile("cp.async.wait_group %0;" :: "n"(N));
}

// ----------------------------------------------------------------------------
// tf32 pre-conversion (rna), vectorized grid-stride
// ----------------------------------------------------------------------------
__global__ void cvt_tf32_kernel(const float* __restrict__ src,
                                uint32_t* __restrict__ dst, int n4)
{
    for (int i = blockIdx.x * blockDim.x + threadIdx.x; i < n4;
         i += gridDim.x * blockDim.x) {
        const float4 v = ((const float4*)src)[i];
        uint4 u;
        u.x = f2tf32(v.x); u.y = f2tf32(v.y);
        u.z = f2tf32(v.z); u.w = f2tf32(v.w);
        ((uint4*)dst)[i] = u;
    }
}

// ----------------------------------------------------------------------------
// tf32 tensor-core GEMM, 3-stage cp.async pipeline, 512 threads.
// C[M,N] = A[M,K] @ B[K,N] + bias[N]; A,B already tf32 bits.
// Block 128(M) x NT(N), 16 warps (4M x 4N), warp tile m32 x (NT/4), K-chunk 16.
// As [m=128][k=16] stride 20, Bs [k=16][n=NT] stride NT+8.
// Requires M%128==0, N%NT==0, K%16==0.
// ----------------------------------------------------------------------------
#define AST 20
#define A_WORDS (128 * AST)                 // 2560

template <int NT>
__global__ __launch_bounds__(512, 1) void tf32_gemm_bias(
    const uint32_t* __restrict__ A, const uint32_t* __restrict__ B,
    const float* __restrict__ bias, float* __restrict__ C,
    int M, int N, int K)
{
    constexpr int BSTl = NT + 8;
    constexpr int B_WORDS = 16 * BSTl;
    constexpr int SS = A_WORDS + B_WORDS;     // words per stage
    constexpr int NFR = NT / 32;              // n-fragments per warp
    constexpr int TPR = NT / 4;               // threads per B row
    constexpr int BITERS = NT / 128;          // B staging iterations
    constexpr int KRSTEP = 2048 / NT;         // k-rows per B pass

    extern __shared__ uint32_t smg[];
    const uint32_t smem_base = (uint32_t)__cvta_generic_to_shared(smg);

    const int tid = threadIdx.x;
    const int w = tid >> 5, lane = tid & 31;
    const int gr = lane >> 2, tg = lane & 3;
    const int m0w = (w & 3) * 32;
    const int n0w = (w >> 2) * (NT / 4);

    const int lq = lane >> 3;
    const int lr = lane & 7;
    const int a_row = lr + ((lq & 1) << 3);
    const int a_col = (lq >> 1) << 2;

    const uint32_t* Ag = A + (size_t)(blockIdx.y * 128) * K;
    const uint32_t* Bg = B + blockIdx.x * NT;

    // A staging: 512 float4 slots, 1/thread
    const int a_srow = tid >> 2;              // 0..127
    const int a_sc4 = (tid & 3) << 2;         // 0,4,8,12
    // B staging: 4*NT float4 slots
    const int b_kr0 = tid / TPR;              // 0..KRSTEP-1
    const int b_c4 = (tid % TPR) << 2;

    const int nk = K >> 4;

    auto issue = [&](int kc) {
        const int st = kc % 3;
        const int k0 = kc << 4;
        const uint32_t abase = smem_base + (uint32_t)(st * SS) * 4;
        const uint32_t bbase = abase + A_WORDS * 4;
        cp_async16(abase + (uint32_t)(a_srow * AST + a_sc4) * 4,
                   Ag + (size_t)a_srow * K + k0 + a_sc4);
#pragma unroll
        for (int it = 0; it < BITERS; it++) {
            const int kr = b_kr0 + KRSTEP * it;
            cp_async16(bbase + (uint32_t)(kr * BSTl + b_c4) * 4,
                       Bg + (size_t)(k0 + kr) * N + b_c4);
        }
        cp_commit();
    };

    float c[2][NFR][4];
#pragma unroll
    for (int mi = 0; mi < 2; mi++)
#pragma unroll
        for (int nf = 0; nf < NFR; nf++)
#pragma unroll
            for (int j = 0; j < 4; j++) c[mi][nf][j] = 0.f;

    issue(0);
    issue(1);

    for (int kc = 0; kc < nk; kc++) {
        if (kc == nk - 1) cp_wait<0>(); else cp_wait<1>();
        __syncthreads();

        if (kc + 2 < nk) issue(kc + 2);   // stage freed by compute(kc-1)

        const uint32_t* As = smg + (kc % 3) * SS;
        const uint32_t* Bs = As + A_WORDS;

#pragma unroll
        for (int kf = 0; kf < 2; kf++) {
            const int kb = kf << 3;
            uint32_t a[2][4];
#pragma unroll
            for (int mi = 0; mi < 2; mi++)
                ldsm_x4(a[mi][0], a[mi][1], a[mi][2], a[mi][3],
                        As + (m0w + 16 * mi + a_row) * AST + kb + a_col);
            const uint32_t* b0p = Bs + (kb + tg) * BSTl + n0w + gr;
            const uint32_t* b1p = b0p + 4 * BSTl;
#pragma unroll
            for (int nf = 0; nf < NFR; nf++) {
                const uint32_t b0 = b0p[8 * nf];
                const uint32_t b1 = b1p[8 * nf];
                mma_tf32(c[0][nf], a[0], b0, b1);
                mma_tf32(c[1][nf], a[1], b0, b1);
            }
        }
        // no trailing sync needed: top-of-loop sync orders stage reuse
    }

    // Epilogue with bias
#pragma unroll
    for (int nf = 0; nf < NFR; nf++) {
        const int col = blockIdx.x * NT + n0w + 8 * nf + 2 * tg;
        const float bb0 = bias[col];
        const float bb1 = bias[col + 1];
#pragma unroll
        for (int mi = 0; mi < 2; mi++) {
            const size_t r0 = (size_t)(blockIdx.y * 128 + m0w + 16 * mi + gr);
            float2 v0, v1;
            v0.x = c[mi][nf][0] + bb0; v0.y = c[mi][nf][1] + bb1;
            v1.x = c[mi][nf][2] + bb0; v1.y = c[mi][nf][3] + bb1;
            *(float2*)(C + r0 * N + col)       = v0;
            *(float2*)(C + (r0 + 8) * N + col) = v1;
        }
    }
}

#define GEMM_SMEM_256 (3 * (A_WORDS + 16 * 264) * 4)   // 81408
#define GEMM_SMEM_128 (3 * (A_WORDS + 16 * 136) * 4)   // 56832

// ----------------------------------------------------------------------------
// Flash attention with tf32 tensor cores + register prefetch (unchanged R9).
// ----------------------------------------------------------------------------
#define KST 68
#define VST 72
#define PST 68
#define VS_OFF  (64 * KST)
#define PS_OFF  (VS_OFF + 64 * VST)
#define CB_OFF  (PS_OFF + 8 * 16 * PST)
#define ATTN_SMEM ((CB_OFF + 64) * 4)

__global__ __launch_bounds__(256) void attn_mma(
    const float* __restrict__ qkv,   // [BS, 3*NX]
    const float* __restrict__ ekv,   // [BP, 2*NX]
    const float* __restrict__ Mmask, // [B, P]
    const float* __restrict__ amask, // [B,1,1,S]
    float* __restrict__ out)         // [BS, NX] (tf32-rounded bits)
{
    extern __shared__ float sm[];
    uint32_t* Ksu = (uint32_t*)sm;
    uint32_t* Vsu = (uint32_t*)(sm + VS_OFF);
    float*    Ps  = sm + PS_OFF;
    float*    Cb  = sm + CB_OFF;
    uint32_t* Qtu = (uint32_t*)sm;

    const int bh = blockIdx.y;
    const int b = bh >> 4, h = bh & 15;
    const int q0 = blockIdx.x * 128;
    const int tid = threadIdx.x;
    const int w = tid >> 5;
    const int lane = tid & 31;
    const int gr = lane >> 2;
    const int tg = lane & 3;

#pragma unroll
    for (int it = 0; it < 8; it++) {
        const int fid = tid + it * 256;
        const int r = fid >> 4;
        const int c4 = (fid & 15) * 4;
        const float4 q = *(const float4*)(
            qkv + (size_t)(b * S_ + q0 + r) * (3 * NX_) + h * DH_ + c4);
        uint32_t* d = Qtu + r * KST + c4;
        d[0] = f2tf32(q.x * 0.125f);
        d[1] = f2tf32(q.y * 0.125f);
        d[2] = f2tf32(q.z * 0.125f);
        d[3] = f2tf32(q.w * 0.125f);
    }
    __syncthreads();

    uint32_t aQ[8][4];
    {
        const int r0 = 16 * w + gr;
#pragma unroll
        for (int kf = 0; kf < 8; kf++) {
            aQ[kf][0] = Qtu[r0 * KST + 8 * kf + tg];
            aQ[kf][1] = Qtu[(r0 + 8) * KST + 8 * kf + tg];
            aQ[kf][2] = Qtu[r0 * KST + 8 * kf + tg + 4];
            aQ[kf][3] = Qtu[(r0 + 8) * KST + 8 * kf + tg + 4];
        }
    }

    float m0 = -1e30f, m1 = -1e30f, l0 = 0.f, l1 = 0.f;
    float o[8][4];
#pragma unroll
    for (int nf = 0; nf < 8; nf++)
#pragma unroll
        for (int j = 0; j < 4; j++) o[nf][j] = 0.f;

    uint32_t* Pswu = (uint32_t*)(Ps + w * 16 * PST);
    const int r0g = q0 + 16 * w + gr;
    const int r1g = r0g + 8;
    const int ntiles = 2 * blockIdx.x + 4;

    const int st_t  = tid >> 4;
    const int st_c4 = (tid & 15) * 4;

    float4 pk[4], pv[4];
    float cbv = 0.f;
#pragma unroll
    for (int it = 0; it < 4; it++) {
        const int tg_ = st_t + 16 * it;
        const float* kp;
        const float* vp;
        if (tg_ < P_) {
            const float* e = ekv + (size_t)(b * P_ + tg_) * (2 * NX_) + h * DH_;
            kp = e; vp = e + NX_;
        } else {
            const float* s = qkv + (size_t)(b * S_ + tg_ - P_) * (3 * NX_) + h * DH_;
            kp = s + NX_; vp = s + 2 * NX_;
        }
        pk[it] = *(const float4*)(kp + st_c4);
        pv[it] = *(const float4*)(vp + st_c4);
    }
    if (tid < 64) {
        cbv = (tid < P_) ? (1.f - Mmask[b * P_ + tid]) * -10000.f
                         : amask[b * S_ + (tid - P_)];
    }

    for (int kt = 0; kt < ntiles; kt++) {
        const int t0k = kt * 64;
        __syncthreads();

#pragma unroll
        for (int it = 0; it < 4; it++) {
            const int t = st_t + 16 * it;
            uint32_t* kd = Ksu + t * KST + st_c4;
            kd[0] = f2tf32(pk[it].x); kd[1] = f2tf32(pk[it].y);
            kd[2] = f2tf32(pk[it].z); kd[3] = f2tf32(pk[it].w);
            uint32_t* vd = Vsu + t * VST + st_c4;
            vd[0] = f2tf32(pv[it].x); vd[1] = f2tf32(pv[it].y);
            vd[2] = f2tf32(pv[it].z); vd[3] = f2tf32(pv[it].w);
        }
        if (tid < 64) Cb[tid] = cbv;
        __syncthreads();

        if (kt + 1 < ntiles) {
            const int t1 = t0k + 64;
#pragma unroll
            for (int it = 0; it < 4; it++) {
                const int tg_ = t1 + st_t + 16 * it;
                const float* kp;
                const float* vp;
                if (tg_ < P_) {
                    const float* e = ekv + (size_t)(b * P_ + tg_) * (2 * NX_) + h * DH_;
                    kp = e; vp = e + NX_;
                } else {
                    const float* s = qkv + (size_t)(b * S_ + tg_ - P_) * (3 * NX_) + h * DH_;
                    kp = s + NX_; vp = s + 2 * NX_;
                }
                pk[it] = *(const float4*)(kp + st_c4);
                pv[it] = *(const float4*)(vp + st_c4);
            }
            if (tid < 64) {
                const int t = t1 + tid;
                cbv = (t < P_) ? (1.f - Mmask[b * P_ + t]) * -10000.f
                               : amask[b * S_ + (t - P_)];
            }
        }

        float s[8][4];
#pragma unroll
        for (int nf = 0; nf < 8; nf++)
#pragma unroll
            for (int j = 0; j < 4; j++) s[nf][j] = 0.f;

#pragma unroll
        for (int kf = 0; kf < 8; kf++) {
#pragma unroll
            for (int nf = 0; nf < 8; nf++) {
                const uint32_t kb0 = Ksu[(8 * nf + gr) * KST + 8 * kf + tg];
                const uint32_t kb1 = Ksu[(8 * nf + gr) * KST + 8 * kf + tg + 4];
                mma_tf32(s[nf], aQ[kf], kb0, kb1);
            }
        }

        float mx0 = -1e30f, mx1 = -1e30f;
#pragma unroll
        for (int nf = 0; nf < 8; nf++) {
            const int tc = t0k + 8 * nf + 2 * tg;
            const float cb0 = Cb[8 * nf + 2 * tg];
            const float cb1 = Cb[8 * nf + 2 * tg + 1];
            const int ts0 = tc - P_;
            const int ts1 = ts0 + 1;
            const float l00 = (ts0 <= r0g ? s[nf][0] : -10000.f) + cb0;
            const float l01 = (ts1 <= r0g ? s[nf][1] : -10000.f) + cb1;
            const float l10 = (ts0 <= r1g ? s[nf][2] : -10000.f) + cb0;
            const float l11 = (ts1 <= r1g ? s[nf][3] : -10000.f) + cb1;
            s[nf][0] = l00; s[nf][1] = l01; s[nf][2] = l10; s[nf][3] = l11;
            mx0 = fmaxf(mx0, fmaxf(l00, l01));
            mx1 = fmaxf(mx1, fmaxf(l10, l11));
        }
        mx0 = fmaxf(mx0, __shfl_xor_sync(0xffffffffu, mx0, 1));
        mx0 = fmaxf(mx0, __shfl_xor_sync(0xffffffffu, mx0, 2));
        mx1 = fmaxf(mx1, __shfl_xor_sync(0xffffffffu, mx1, 1));
        mx1 = fmaxf(mx1, __shfl_xor_sync(0xffffffffu, mx1, 2));

        const float nm0 = fmaxf(m0, mx0);
        const float nm1 = fmaxf(m1, mx1);
        const float al0 = __expf(m0 - nm0);
        const float al1 = __expf(m1 - nm1);
        float ps0 = 0.f, ps1 = 0.f;
#pragma unroll
        for (int nf = 0; nf < 8; nf++) {
            const float p00 = __expf(s[nf][0] - nm0);
            const float p01 = __expf(s[nf][1] - nm0);
            const float p10 = __expf(s[nf][2] - nm1);
            const float p11 = __expf(s[nf][3] - nm1);
            ps0 += p00 + p01;
            ps1 += p10 + p11;
            Pswu[gr * PST + 8 * nf + 2 * tg]           = f2tf32(p00);
            Pswu[gr * PST + 8 * nf + 2 * tg + 1]       = f2tf32(p01);
            Pswu[(gr + 8) * PST + 8 * nf + 2 * tg]     = f2tf32(p10);
            Pswu[(gr + 8) * PST + 8 * nf + 2 * tg + 1] = f2tf32(p11);
        }
        ps0 += __shfl_xor_sync(0xffffffffu, ps0, 1);
        ps0 += __shfl_xor_sync(0xffffffffu, ps0, 2);
        ps1 += __shfl_xor_sync(0xffffffffu, ps1, 1);
        ps1 += __shfl_xor_sync(0xffffffffu, ps1, 2);
        l0 = l0 * al0 + ps0;
        l1 = l1 * al1 + ps1;
        m0 = nm0; m1 = nm1;

#pragma unroll
        for (int nf = 0; nf < 8; nf++) {
            o[nf][0] *= al0; o[nf][1] *= al0;
            o[nf][2] *= al1; o[nf][3] *= al1;
        }
        __syncwarp();

#pragma unroll
        for (int kf = 0; kf < 8; kf++) {
            uint32_t aP[4];
            aP[0] = Pswu[gr * PST + 8 * kf + tg];
            aP[1] = Pswu[(gr + 8) * PST + 8 * kf + tg];
            aP[2] = Pswu[gr * PST + 8 * kf + tg + 4];
            aP[3] = Pswu[(gr + 8) * PST + 8 * kf + tg + 4];
#pragma unroll
            for (int nf = 0; nf < 8; nf++) {
                const uint32_t vb0 = Vsu[(8 * kf + tg) * VST + 8 * nf + gr];
                const uint32_t vb1 = Vsu[(8 * kf + tg + 4) * VST + 8 * nf + gr];
                mma_tf32(o[nf], aP, vb0, vb1);
            }
        }
    }

    const float inv0 = 1.f / l0;
    const float inv1 = 1.f / l1;
#pragma unroll
    for (int nf = 0; nf < 8; nf++) {
        const size_t base0 = (size_t)(b * S_ + r0g) * NX_ + h * DH_ + 8 * nf + 2 * tg;
        const size_t base1 = (size_t)(b * S_ + r1g) * NX_ + h * DH_ + 8 * nf + 2 * tg;
        uint2 v0, v1;   // tf32-rounded bits (idempotent for the proj GEMM)
        v0.x = f2tf32(o[nf][0] * inv0); v0.y = f2tf32(o[nf][1] * inv0);
        v1.x = f2tf32(o[nf][2] * inv1); v1.y = f2tf32(o[nf][3] * inv1);
        *(uint2*)((uint32_t*)out + base0) = v0;
        *(uint2*)((uint32_t*)out + base1) = v1;
    }
}

// ----------------------------------------------------------------------------
// Launch
// ----------------------------------------------------------------------------
extern "C" void kernel_launch(void* const* d_in, const int* in_sizes, int n_in,
                              void* d_out, int out_size)
{
    const float* x      = (const float*)d_in[0];
    const float* M      = (const float*)d_in[1];
    const float* Mmask  = (const float*)d_in[2];
    const float* amask  = (const float*)d_in[3];
    const float* W_attn = (const float*)d_in[4];
    const float* b_attn = (const float*)d_in[5];
    const float* W_mem  = (const float*)d_in[6];
    const float* b_mem  = (const float*)d_in[7];
    const float* W_proj = (const float*)d_in[8];
    const float* b_proj = (const float*)d_in[9];
    float* out = (float*)d_out;

    float* qkv; cudaGetSymbolAddress((void**)&qkv, g_qkv);
    float* ekv; cudaGetSymbolAddress((void**)&ekv, g_ekv);
    float* a;   cudaGetSymbolAddress((void**)&a,   g_a);
    uint32_t* xt; cudaGetSymbolAddress((void**)&xt, g_xt);
    uint32_t* mt; cudaGetSymbolAddress((void**)&mt, g_mt);
    uint32_t* wa; cudaGetSymbolAddress((void**)&wa, g_wa);
    uint32_t* wm; cudaGetSymbolAddress((void**)&wm, g_wm);
    uint32_t* wp; cudaGetSymbolAddress((void**)&wp, g_wp);

    cudaFuncSetAttribute(tf32_gemm_bias<256>,
                         cudaFuncAttributeMaxDynamicSharedMemorySize, GEMM_SMEM_256);
    cudaFuncSetAttribute(tf32_gemm_bias<128>,
                         cudaFuncAttributeMaxDynamicSharedMemorySize, GEMM_SMEM_128);
    cudaFuncSetAttribute(attn_mma, cudaFuncAttributeMaxDynamicSharedMemorySize,
                         ATTN_SMEM);

    // 0) tf32 pre-conversion of GEMM operands
    cvt_tf32_kernel<<<1024, 256>>>(x, xt, BS_ * NX_ / 4);
    cvt_tf32_kernel<<<512,  256>>>(M, mt, BP_ * NX_ / 4);
    cvt_tf32_kernel<<<1024, 256>>>(W_attn, wa, NX_ * 3 * NX_ / 4);
    cvt_tf32_kernel<<<1024, 256>>>(W_mem, wm, NX_ * 2 * NX_ / 4);
    cvt_tf32_kernel<<<512,  256>>>(W_proj, wp, NX_ * NX_ / 4);

    // 1) qkv = x @ W_attn + b_attn
    {
        dim3 grid(3 * NX_ / 256, BS_ / 128);
        tf32_gemm_bias<256><<<grid, 512, GEMM_SMEM_256>>>(xt, wa, b_attn, qkv,
                                                          BS_, 3 * NX_, NX_);
    }
    // 2) ekv = M @ W_mem + b_mem  (N-tile 128 -> 64 blocks)
    {
        dim3 grid(2 * NX_ / 128, BP_ / 128);
        tf32_gemm_bias<128><<<grid, 512, GEMM_SMEM_128>>>(mt, wm, b_mem, ekv,
                                                          BP_, 2 * NX_, NX_);
    }
    // 3) flash attention (tensor cores, prefetched) -> a (tf32-rounded)
    {
        dim3 grid(S_ / 128, B_ * H_);
        attn_mma<<<grid, 256, ATTN_SMEM>>>(qkv, ekv, Mmask, amask, a);
    }
    // 4) out = a @ W_proj + b_proj
    {
        dim3 grid(NX_ / 256, BS_ / 128);
        tf32_gemm_bias<256><<<grid, 512, GEMM_SMEM_256>>>((const uint32_t*)a, wp,
                                                          b_proj, out, BS_, NX_, NX_);
    }
}

// round 12
// speedup vs baseline: 7.9476x; 1.1742x over previous
#include <cuda_runtime.h>
#include <cuda_bf16.h>
#include <cstdint>

// Problem constants
#define B_   4
#define S_   1024
#define P_   128
#define NX_  1024
#define H_   16
#define DH_  64
#define T_   (P_ + S_)      // 1152
#define BS_  (B_ * S_)      // 4096
#define BP_  (B_ * P_)      // 512

// Scratch (static device globals; no allocation allowed)
__device__ float g_qkv[(size_t)BS_ * 3 * NX_];   // [4096, 3072] fp32
__device__ float g_ekv[(size_t)BP_ * 2 * NX_];   // [512, 2048]  fp32
__device__ float g_a  [(size_t)BS_ * NX_];       // [4096, 1024] tf32 bits
// tf32-preconverted GEMM operands ([K][N] for weights, [M][K] for acts)
__device__ uint32_t g_xt[(size_t)BS_ * NX_];
__device__ uint32_t g_mt[(size_t)BP_ * NX_];
__device__ uint32_t g_wa[(size_t)NX_ * 3 * NX_];
__device__ uint32_t g_wm[(size_t)NX_ * 2 * NX_];
__device__ uint32_t g_wp[(size_t)NX_ * NX_];

// ----------------------------------------------------------------------------
// Common MMA helpers
// ----------------------------------------------------------------------------
__device__ __forceinline__ uint32_t f2tf32(float x) {
    uint32_t u;
    asm("cvt.rna.tf32.f32 %0, %1;" : "=r"(u) : "f"(x));
    return u;
}

__device__ __forceinline__ void mma_tf32(float c[4], const uint32_t a[4],
                                         uint32_t b0, uint32_t b1) {
    asm volatile(
        "mma.sync.aligned.m16n8k8.row.col.f32.tf32.tf32.f32 "
        "{%0,%1,%2,%3}, {%4,%5,%6,%7}, {%8,%9}, {%0,%1,%2,%3};"
        : "+f"(c[0]), "+f"(c[1]), "+f"(c[2]), "+f"(c[3])
        : "r"(a[0]), "r"(a[1]), "r"(a[2]), "r"(a[3]), "r"(b0), "r"(b1));
}

__device__ __forceinline__ void ldsm_x4(uint32_t& r0, uint32_t& r1,
                                        uint32_t& r2, uint32_t& r3,
                                        const void* p) {
    uint32_t a = (uint32_t)__cvta_generic_to_shared(p);
    asm volatile("ldmatrix.sync.aligned.m8n8.x4.shared.b16 {%0,%1,%2,%3}, [%4];"
                 : "=r"(r0), "=r"(r1), "=r"(r2), "=r"(r3) : "r"(a));
}

__device__ __forceinline__ void cp_async16(uint32_t smem_addr, const void* gptr) {
    asm volatile("cp.async.cg.shared.global [%0], [%1], 16;"
                 :: "r"(smem_addr), "l"(gptr));
}
__device__ __forceinline__ void cp_commit() {
    asm volatile("cp.async.commit_group;");
}
template <int N>
__device__ __forceinline__ void cp_wait() {
    asm volatile("cp.async.wait_group %0;" :: "n"(N));
}

// ----------------------------------------------------------------------------
// tf32 pre-conversion (rna), vectorized grid-stride
// ----------------------------------------------------------------------------
__global__ void cvt_tf32_kernel(const float* __restrict__ src,
                                uint32_t* __restrict__ dst, int n4)
{
    for (int i = blockIdx.x * blockDim.x + threadIdx.x; i < n4;
         i += gridDim.x * blockDim.x) {
        const float4 v = ((const float4*)src)[i];
        uint4 u;
        u.x = f2tf32(v.x); u.y = f2tf32(v.y);
        u.z = f2tf32(v.z); u.w = f2tf32(v.w);
        ((uint4*)dst)[i] = u;
    }
}

// ----------------------------------------------------------------------------
// tf32 tensor-core GEMM, 3-stage cp.async pipeline, K-chunk 32, 512 threads.
// Handles TWO GEMMs in one launch (block-range dispatch) to overlap the small
// ekv GEMM with qkv's tail wave. Both GEMMs share K.
// C[M,N] = A[M,K] @ B[K,N] + bias[N]; A,B tf32 bits.
// Block 128(M) x 256(N), 16 warps (4M x 4N), warp tile m32 x n64.
// As [m=128][k=32] stride 36 (ldsm rows on distinct banks: 4r mod 32)
// Bs [k=32][n=256] stride 264 (STS and frag-LDS conflict-free)
// ----------------------------------------------------------------------------
#define AST 36
#define BST 264
#define A_WORDS (128 * AST)                 // 4608
#define B_WORDS (32 * BST)                  // 8448
#define SS (A_WORDS + B_WORDS)              // 13056 words / stage
#define GEMM_SMEM (3 * SS * 4)              // 156672 bytes

__global__ __launch_bounds__(512, 1) void tf32_gemm_dual(
    const uint32_t* __restrict__ A0, const uint32_t* __restrict__ B0,
    const float* __restrict__ bias0, float* __restrict__ C0,
    int N0, int nbx0, int total0,
    const uint32_t* __restrict__ A1, const uint32_t* __restrict__ B1,
    const float* __restrict__ bias1, float* __restrict__ C1,
    int N1, int nbx1, int K)
{
    extern __shared__ uint32_t smg[];
    const uint32_t smem_base = (uint32_t)__cvta_generic_to_shared(smg);

    // Block-range dispatch between the two GEMMs
    const uint32_t* A; const uint32_t* Bm; const float* bias; float* C;
    int N, bx, by;
    {
        const int id = blockIdx.x;
        if (id < total0) {
            A = A0; Bm = B0; bias = bias0; C = C0; N = N0;
            bx = id % nbx0; by = id / nbx0;
        } else {
            const int j = id - total0;
            A = A1; Bm = B1; bias = bias1; C = C1; N = N1;
            bx = j % nbx1; by = j / nbx1;
        }
    }

    const int tid = threadIdx.x;
    const int w = tid >> 5, lane = tid & 31;
    const int gr = lane >> 2, tg = lane & 3;
    const int m0w = (w & 3) * 32;     // 4 M-tiles of 32
    const int n0w = (w >> 2) * 64;    // 4 N-tiles of 64

    const int lq = lane >> 3;
    const int lr = lane & 7;
    const int a_row = lr + ((lq & 1) << 3);
    const int a_col = (lq >> 1) << 2;

    const uint32_t* Ag = A + (size_t)(by * 128) * K;
    const uint32_t* Bg = Bm + bx * 256;

    // A staging: 1024 float4 slots (2 iters)
    const int a_srow = tid >> 3;              // 0..63, +64*it
    const int a_sc4 = (tid & 7) << 2;         // 0..28
    // B staging: 2048 float4 slots (4 iters)
    const int b_kr0 = tid >> 6;               // 0..7, +8*it
    const int b_c4 = (tid & 63) << 2;         // 0..252

    const int nk = K >> 5;                    // K-chunk 32

    auto issue = [&](int kc) {
        const int st = kc % 3;
        const int k0 = kc << 5;
        const uint32_t abase = smem_base + (uint32_t)(st * SS) * 4;
        const uint32_t bbase = abase + A_WORDS * 4;
#pragma unroll
        for (int it = 0; it < 2; it++) {
            const int row = a_srow + 64 * it;
            cp_async16(abase + (uint32_t)(row * AST + a_sc4) * 4,
                       Ag + (size_t)row * K + k0 + a_sc4);
        }
#pragma unroll
        for (int it = 0; it < 4; it++) {
            const int kr = b_kr0 + 8 * it;
            cp_async16(bbase + (uint32_t)(kr * BST + b_c4) * 4,
                       Bg + (size_t)(k0 + kr) * N + b_c4);
        }
        cp_commit();
    };

    float c[2][8][4];
#pragma unroll
    for (int mi = 0; mi < 2; mi++)
#pragma unroll
        for (int nf = 0; nf < 8; nf++)
#pragma unroll
            for (int j = 0; j < 4; j++) c[mi][nf][j] = 0.f;

    issue(0);
    issue(1);

    for (int kc = 0; kc < nk; kc++) {
        if (kc + 1 < nk) cp_wait<1>(); else cp_wait<0>();
        __syncthreads();

        if (kc + 2 < nk) issue(kc + 2);   // stage freed by compute(kc-1)

        const uint32_t* As = smg + (kc % 3) * SS;
        const uint32_t* Bs = As + A_WORDS;

#pragma unroll
        for (int kf = 0; kf < 4; kf++) {
            const int kb = kf << 3;
            uint32_t a[2][4];
#pragma unroll
            for (int mi = 0; mi < 2; mi++)
                ldsm_x4(a[mi][0], a[mi][1], a[mi][2], a[mi][3],
                        As + (m0w + 16 * mi + a_row) * AST + kb + a_col);
            const uint32_t* b0p = Bs + (kb + tg) * BST + n0w + gr;
            const uint32_t* b1p = b0p + 4 * BST;
#pragma unroll
            for (int nf = 0; nf < 8; nf++) {
                const uint32_t b0 = b0p[8 * nf];
                const uint32_t b1 = b1p[8 * nf];
                mma_tf32(c[0][nf], a[0], b0, b1);
                mma_tf32(c[1][nf], a[1], b0, b1);
            }
        }
        // no trailing sync: top-of-loop sync orders stage reuse
    }

    // Epilogue with bias
#pragma unroll
    for (int nf = 0; nf < 8; nf++) {
        const int col = bx * 256 + n0w + 8 * nf + 2 * tg;
        const float bb0 = bias[col];
        const float bb1 = bias[col + 1];
#pragma unroll
        for (int mi = 0; mi < 2; mi++) {
            const size_t r0 = (size_t)(by * 128 + m0w + 16 * mi + gr);
            float2 v0, v1;
            v0.x = c[mi][nf][0] + bb0; v0.y = c[mi][nf][1] + bb1;
            v1.x = c[mi][nf][2] + bb0; v1.y = c[mi][nf][3] + bb1;
            *(float2*)(C + r0 * N + col)       = v0;
            *(float2*)(C + (r0 + 8) * N + col) = v1;
        }
    }
}

// ----------------------------------------------------------------------------
// Flash attention with tf32 mma.sync + register prefetch (unchanged R10).
// ----------------------------------------------------------------------------
#define KST 68
#define VST 72
#define PST 68
#define VS_OFF  (64 * KST)
#define PS_OFF  (VS_OFF + 64 * VST)
#define CB_OFF  (PS_OFF + 8 * 16 * PST)
#define ATTN_SMEM ((CB_OFF + 64) * 4)

__global__ __launch_bounds__(256) void attn_mma(
    const float* __restrict__ qkv,   // [BS, 3*NX]
    const float* __restrict__ ekv,   // [BP, 2*NX]
    const float* __restrict__ Mmask, // [B, P]
    const float* __restrict__ amask, // [B,1,1,S]
    float* __restrict__ out)         // [BS, NX] (tf32-rounded bits)
{
    extern __shared__ float sm[];
    uint32_t* Ksu = (uint32_t*)sm;
    uint32_t* Vsu = (uint32_t*)(sm + VS_OFF);
    float*    Ps  = sm + PS_OFF;
    float*    Cb  = sm + CB_OFF;
    uint32_t* Qtu = (uint32_t*)sm;

    const int bh = blockIdx.y;
    const int b = bh >> 4, h = bh & 15;
    const int q0 = blockIdx.x * 128;
    const int tid = threadIdx.x;
    const int w = tid >> 5;
    const int lane = tid & 31;
    const int gr = lane >> 2;
    const int tg = lane & 3;

#pragma unroll
    for (int it = 0; it < 8; it++) {
        const int fid = tid + it * 256;
        const int r = fid >> 4;
        const int c4 = (fid & 15) * 4;
        const float4 q = *(const float4*)(
            qkv + (size_t)(b * S_ + q0 + r) * (3 * NX_) + h * DH_ + c4);
        uint32_t* d = Qtu + r * KST + c4;
        d[0] = f2tf32(q.x * 0.125f);
        d[1] = f2tf32(q.y * 0.125f);
        d[2] = f2tf32(q.z * 0.125f);
        d[3] = f2tf32(q.w * 0.125f);
    }
    __syncthreads();

    uint32_t aQ[8][4];
    {
        const int r0 = 16 * w + gr;
#pragma unroll
        for (int kf = 0; kf < 8; kf++) {
            aQ[kf][0] = Qtu[r0 * KST + 8 * kf + tg];
            aQ[kf][1] = Qtu[(r0 + 8) * KST + 8 * kf + tg];
            aQ[kf][2] = Qtu[r0 * KST + 8 * kf + tg + 4];
            aQ[kf][3] = Qtu[(r0 + 8) * KST + 8 * kf + tg + 4];
        }
    }

    float m0 = -1e30f, m1 = -1e30f, l0 = 0.f, l1 = 0.f;
    float o[8][4];
#pragma unroll
    for (int nf = 0; nf < 8; nf++)
#pragma unroll
        for (int j = 0; j < 4; j++) o[nf][j] = 0.f;

    uint32_t* Pswu = (uint32_t*)(Ps + w * 16 * PST);
    const int r0g = q0 + 16 * w + gr;
    const int r1g = r0g + 8;
    const int ntiles = 2 * blockIdx.x + 4;

    const int st_t  = tid >> 4;
    const int st_c4 = (tid & 15) * 4;

    float4 pk[4], pv[4];
    float cbv = 0.f;
#pragma unroll
    for (int it = 0; it < 4; it++) {
        const int tg_ = st_t + 16 * it;
        const float* kp;
        const float* vp;
        if (tg_ < P_) {
            const float* e = ekv + (size_t)(b * P_ + tg_) * (2 * NX_) + h * DH_;
            kp = e; vp = e + NX_;
        } else {
            const float* s = qkv + (size_t)(b * S_ + tg_ - P_) * (3 * NX_) + h * DH_;
            kp = s + NX_; vp = s + 2 * NX_;
        }
        pk[it] = *(const float4*)(kp + st_c4);
        pv[it] = *(const float4*)(vp + st_c4);
    }
    if (tid < 64) {
        cbv = (tid < P_) ? (1.f - Mmask[b * P_ + tid]) * -10000.f
                         : amask[b * S_ + (tid - P_)];
    }

    for (int kt = 0; kt < ntiles; kt++) {
        const int t0k = kt * 64;
        __syncthreads();

#pragma unroll
        for (int it = 0; it < 4; it++) {
            const int t = st_t + 16 * it;
            uint32_t* kd = Ksu + t * KST + st_c4;
            kd[0] = f2tf32(pk[it].x); kd[1] = f2tf32(pk[it].y);
            kd[2] = f2tf32(pk[it].z); kd[3] = f2tf32(pk[it].w);
            uint32_t* vd = Vsu + t * VST + st_c4;
            vd[0] = f2tf32(pv[it].x); vd[1] = f2tf32(pv[it].y);
            vd[2] = f2tf32(pv[it].z); vd[3] = f2tf32(pv[it].w);
        }
        if (tid < 64) Cb[tid] = cbv;
        __syncthreads();

        if (kt + 1 < ntiles) {
            const int t1 = t0k + 64;
#pragma unroll
            for (int it = 0; it < 4; it++) {
                const int tg_ = t1 + st_t + 16 * it;
                const float* kp;
                const float* vp;
                if (tg_ < P_) {
                    const float* e = ekv + (size_t)(b * P_ + tg_) * (2 * NX_) + h * DH_;
                    kp = e; vp = e + NX_;
                } else {
                    const float* s = qkv + (size_t)(b * S_ + tg_ - P_) * (3 * NX_) + h * DH_;
                    kp = s + NX_; vp = s + 2 * NX_;
                }
                pk[it] = *(const float4*)(kp + st_c4);
                pv[it] = *(const float4*)(vp + st_c4);
            }
            if (tid < 64) {
                const int t = t1 + tid;
                cbv = (t < P_) ? (1.f - Mmask[b * P_ + t]) * -10000.f
                               : amask[b * S_ + (t - P_)];
            }
        }

        float s[8][4];
#pragma unroll
        for (int nf = 0; nf < 8; nf++)
#pragma unroll
            for (int j = 0; j < 4; j++) s[nf][j] = 0.f;

#pragma unroll
        for (int kf = 0; kf < 8; kf++) {
#pragma unroll
            for (int nf = 0; nf < 8; nf++) {
                const uint32_t kb0 = Ksu[(8 * nf + gr) * KST + 8 * kf + tg];
                const uint32_t kb1 = Ksu[(8 * nf + gr) * KST + 8 * kf + tg + 4];
                mma_tf32(s[nf], aQ[kf], kb0, kb1);
            }
        }

        float mx0 = -1e30f, mx1 = -1e30f;
#pragma unroll
        for (int nf = 0; nf < 8; nf++) {
            const int tc = t0k + 8 * nf + 2 * tg;
            const float cb0 = Cb[8 * nf + 2 * tg];
            const float cb1 = Cb[8 * nf + 2 * tg + 1];
            const int ts0 = tc - P_;
            const int ts1 = ts0 + 1;
            const float l00 = (ts0 <= r0g ? s[nf][0] : -10000.f) + cb0;
            const float l01 = (ts1 <= r0g ? s[nf][1] : -10000.f) + cb1;
            const float l10 = (ts0 <= r1g ? s[nf][2] : -10000.f) + cb0;
            const float l11 = (ts1 <= r1g ? s[nf][3] : -10000.f) + cb1;
            s[nf][0] = l00; s[nf][1] = l01; s[nf][2] = l10; s[nf][3] = l11;
            mx0 = fmaxf(mx0, fmaxf(l00, l01));
            mx1 = fmaxf(mx1, fmaxf(l10, l11));
        }
        mx0 = fmaxf(mx0, __shfl_xor_sync(0xffffffffu, mx0, 1));
        mx0 = fmaxf(mx0, __shfl_xor_sync(0xffffffffu, mx0, 2));
        mx1 = fmaxf(mx1, __shfl_xor_sync(0xffffffffu, mx1, 1));
        mx1 = fmaxf(mx1, __shfl_xor_sync(0xffffffffu, mx1, 2));

        const float nm0 = fmaxf(m0, mx0);
        const float nm1 = fmaxf(m1, mx1);
        const float al0 = __expf(m0 - nm0);
        const float al1 = __expf(m1 - nm1);
        float ps0 = 0.f, ps1 = 0.f;
#pragma unroll
        for (int nf = 0; nf < 8; nf++) {
            const float p00 = __expf(s[nf][0] - nm0);
            const float p01 = __expf(s[nf][1] - nm0);
            const float p10 = __expf(s[nf][2] - nm1);
            const float p11 = __expf(s[nf][3] - nm1);
            ps0 += p00 + p01;
            ps1 += p10 + p11;
            Pswu[gr * PST + 8 * nf + 2 * tg]           = f2tf32(p00);
            Pswu[gr * PST + 8 * nf + 2 * tg + 1]       = f2tf32(p01);
            Pswu[(gr + 8) * PST + 8 * nf + 2 * tg]     = f2tf32(p10);
            Pswu[(gr + 8) * PST + 8 * nf + 2 * tg + 1] = f2tf32(p11);
        }
        ps0 += __shfl_xor_sync(0xffffffffu, ps0, 1);
        ps0 += __shfl_xor_sync(0xffffffffu, ps0, 2);
        ps1 += __shfl_xor_sync(0xffffffffu, ps1, 1);
        ps1 += __shfl_xor_sync(0xffffffffu, ps1, 2);
        l0 = l0 * al0 + ps0;
        l1 = l1 * al1 + ps1;
        m0 = nm0; m1 = nm1;

#pragma unroll
        for (int nf = 0; nf < 8; nf++) {
            o[nf][0] *= al0; o[nf][1] *= al0;
            o[nf][2] *= al1; o[nf][3] *= al1;
        }
        __syncwarp();

#pragma unroll
        for (int kf = 0; kf < 8; kf++) {
            uint32_t aP[4];
            aP[0] = Pswu[gr * PST + 8 * kf + tg];
            aP[1] = Pswu[(gr + 8) * PST + 8 * kf + tg];
            aP[2] = Pswu[gr * PST + 8 * kf + tg + 4];
            aP[3] = Pswu[(gr + 8) * PST + 8 * kf + tg + 4];
#pragma unroll
            for (int nf = 0; nf < 8; nf++) {
                const uint32_t vb0 = Vsu[(8 * kf + tg) * VST + 8 * nf + gr];
                const uint32_t vb1 = Vsu[(8 * kf + tg + 4) * VST + 8 * nf + gr];
                mma_tf32(o[nf], aP, vb0, vb1);
            }
        }
    }

    const float inv0 = 1.f / l0;
    const float inv1 = 1.f / l1;
#pragma unroll
    for (int nf = 0; nf < 8; nf++) {
        const size_t base0 = (size_t)(b * S_ + r0g) * NX_ + h * DH_ + 8 * nf + 2 * tg;
        const size_t base1 = (size_t)(b * S_ + r1g) * NX_ + h * DH_ + 8 * nf + 2 * tg;
        uint2 v0, v1;
        v0.x = f2tf32(o[nf][0] * inv0); v0.y = f2tf32(o[nf][1] * inv0);
        v1.x = f2tf32(o[nf][2] * inv1); v1.y = f2tf32(o[nf][3] * inv1);
        *(uint2*)((uint32_t*)out + base0) = v0;
        *(uint2*)((uint32_t*)out + base1) = v1;
    }
}

// ----------------------------------------------------------------------------
// Launch
// ----------------------------------------------------------------------------
extern "C" void kernel_launch(void* const* d_in, const int* in_sizes, int n_in,
                              void* d_out, int out_size)
{
    const float* x      = (const float*)d_in[0];
    const float* M      = (const float*)d_in[1];
    const float* Mmask  = (const float*)d_in[2];
    const float* amask  = (const float*)d_in[3];
    const float* W_attn = (const float*)d_in[4];
    const float* b_attn = (const float*)d_in[5];
    const float* W_mem  = (const float*)d_in[6];
    const float* b_mem  = (const float*)d_in[7];
    const float* W_proj = (const float*)d_in[8];
    const float* b_proj = (const float*)d_in[9];
    float* out = (float*)d_out;

    float* qkv; cudaGetSymbolAddress((void**)&qkv, g_qkv);
    float* ekv; cudaGetSymbolAddress((void**)&ekv, g_ekv);
    float* a;   cudaGetSymbolAddress((void**)&a,   g_a);
    uint32_t* xt; cudaGetSymbolAddress((void**)&xt, g_xt);
    uint32_t* mt; cudaGetSymbolAddress((void**)&mt, g_mt);
    uint32_t* wa; cudaGetSymbolAddress((void**)&wa, g_wa);
    uint32_t* wm; cudaGetSymbolAddress((void**)&wm, g_wm);
    uint32_t* wp; cudaGetSymbolAddress((void**)&wp, g_wp);

    cudaFuncSetAttribute(tf32_gemm_dual,
                         cudaFuncAttributeMaxDynamicSharedMemorySize, GEMM_SMEM);
    cudaFuncSetAttribute(attn_mma, cudaFuncAttributeMaxDynamicSharedMemorySize,
                         ATTN_SMEM);

    // 0) tf32 pre-conversion of GEMM operands
    cvt_tf32_kernel<<<1024, 256>>>(x, xt, BS_ * NX_ / 4);
    cvt_tf32_kernel<<<512,  256>>>(M, mt, BP_ * NX_ / 4);
    cvt_tf32_kernel<<<1024, 256>>>(W_attn, wa, NX_ * 3 * NX_ / 4);
    cvt_tf32_kernel<<<1024, 256>>>(W_mem, wm, NX_ * 2 * NX_ / 4);
    cvt_tf32_kernel<<<512,  256>>>(W_proj, wp, NX_ * NX_ / 4);

    // 1+2) fused launch: qkv (384 blocks) + ekv (32 blocks)
    {
        const int nbx0 = 3 * NX_ / 256;          // 12
        const int total0 = nbx0 * (BS_ / 128);   // 384
        const int nbx1 = 2 * NX_ / 256;          // 8
        const int total1 = nbx1 * (BP_ / 128);   // 32
        tf32_gemm_dual<<<total0 + total1, 512, GEMM_SMEM>>>(
            xt, wa, b_attn, qkv, 3 * NX_, nbx0, total0,
            mt, wm, b_mem, ekv, 2 * NX_, nbx1, NX_);
    }
    // 3) flash attention -> a (tf32-rounded bits)
    {
        dim3 grid(S_ / 128, B_ * H_);
        attn_mma<<<grid, 256, ATTN_SMEM>>>(qkv, ekv, Mmask, amask, a);
    }
    // 4) out = a @ W_proj + b_proj (second GEMM slot unused)
    {
        const int nbx0 = NX_ / 256;              // 4
        const int total0 = nbx0 * (BS_ / 128);   // 128
        tf32_gemm_dual<<<total0, 512, GEMM_SMEM>>>(
            (const uint32_t*)a, wp, b_proj, out, NX_, nbx0, total0,
            (const uint32_t*)a, wp, b_proj, out, NX_, 1, NX_);
    }
}

// round 13
// speedup vs baseline: 8.2381x; 1.0366x over previous
#include <cuda_runtime.h>
#include <cuda_bf16.h>
#include <cstdint>

// Problem constants
#define B_   4
#define S_   1024
#define P_   128
#define NX_  1024
#define H_   16
#define DH_  64
#define T_   (P_ + S_)      // 1152
#define BS_  (B_ * S_)      // 4096
#define BP_  (B_ * P_)      // 512

// Scratch (static device globals; no allocation allowed)
__device__ float g_qkv[(size_t)BS_ * 3 * NX_];   // [4096, 3072] tf32 bits
__device__ float g_ekv[(size_t)BP_ * 2 * NX_];   // [512, 2048]  tf32 bits
__device__ float g_a  [(size_t)BS_ * NX_];       // [4096, 1024] tf32 bits
// tf32-preconverted GEMM operands
__device__ uint32_t g_xt[(size_t)BS_ * NX_];
__device__ uint32_t g_mt[(size_t)BP_ * NX_];
__device__ uint32_t g_wa[(size_t)NX_ * 3 * NX_];
__device__ uint32_t g_wm[(size_t)NX_ * 2 * NX_];
__device__ uint32_t g_wp[(size_t)NX_ * NX_];

// ----------------------------------------------------------------------------
// Common MMA helpers
// ----------------------------------------------------------------------------
__device__ __forceinline__ uint32_t f2tf32(float x) {
    uint32_t u;
    asm("cvt.rna.tf32.f32 %0, %1;" : "=r"(u) : "f"(x));
    return u;
}

__device__ __forceinline__ void mma_tf32(float c[4], const uint32_t a[4],
                                         uint32_t b0, uint32_t b1) {
    asm volatile(
        "mma.sync.aligned.m16n8k8.row.col.f32.tf32.tf32.f32 "
        "{%0,%1,%2,%3}, {%4,%5,%6,%7}, {%8,%9}, {%0,%1,%2,%3};"
        : "+f"(c[0]), "+f"(c[1]), "+f"(c[2]), "+f"(c[3])
        : "r"(a[0]), "r"(a[1]), "r"(a[2]), "r"(a[3]), "r"(b0), "r"(b1));
}

__device__ __forceinline__ void ldsm_x4(uint32_t& r0, uint32_t& r1,
                                        uint32_t& r2, uint32_t& r3,
                                        const void* p) {
    uint32_t a = (uint32_t)__cvta_generic_to_shared(p);
    asm volatile("ldmatrix.sync.aligned.m8n8.x4.shared.b16 {%0,%1,%2,%3}, [%4];"
                 : "=r"(r0), "=r"(r1), "=r"(r2), "=r"(r3) : "r"(a));
}

__device__ __forceinline__ void cp_async16(uint32_t smem_addr, const void* gptr) {
    asm volatile("cp.async.cg.shared.global [%0], [%1], 16;"
                 :: "r"(smem_addr), "l"(gptr));
}
__device__ __forceinline__ void cp_commit() {
    asm volatile("cp.async.commit_group;");
}
template <int N>
__device__ __forceinline__ void cp_wait() {
    asm volatile("cp.async.wait_group %0;" :: "n"(N));
}

// ----------------------------------------------------------------------------
// Fused tf32 pre-conversion of all 5 GEMM operands (one launch)
// ----------------------------------------------------------------------------
__global__ void cvt_all_kernel(
    const float* s0, uint32_t* d0, int n0,
    const float* s1, uint32_t* d1, int n1,
    const float* s2, uint32_t* d2, int n2,
    const float* s3, uint32_t* d3, int n3,
    const float* s4, uint32_t* d4, int n4)
{
    const int stride = gridDim.x * blockDim.x;
    const int t = blockIdx.x * blockDim.x + threadIdx.x;
#define CVT_SEG(S, D, NN) \
    for (int i = t; i < (NN); i += stride) { \
        const float4 v = ((const float4*)(S))[i]; \
        uint4 u; \
        u.x = f2tf32(v.x); u.y = f2tf32(v.y); \
        u.z = f2tf32(v.z); u.w = f2tf32(v.w); \
        ((uint4*)(D))[i] = u; \
    }
    CVT_SEG(s0, d0, n0)
    CVT_SEG(s1, d1, n1)
    CVT_SEG(s2, d2, n2)
    CVT_SEG(s3, d3, n3)
    CVT_SEG(s4, d4, n4)
#undef CVT_SEG
}

// ----------------------------------------------------------------------------
// tf32 tensor-core GEMM, 3-stage cp.async pipeline, K-chunk 32, 512 threads.
// Dual-GEMM block-range dispatch (overlaps small second GEMM with first's tail).
// rndX != 0 -> outputs written tf32-rounded (bit pattern in fp32).
// ----------------------------------------------------------------------------
#define AST 36
#define BST 264
#define A_WORDS (128 * AST)                 // 4608
#define B_WORDS (32 * BST)                  // 8448
#define SS (A_WORDS + B_WORDS)              // 13056 words / stage
#define GEMM_SMEM (3 * SS * 4)              // 156672 bytes

__global__ __launch_bounds__(512, 1) void tf32_gemm_dual(
    const uint32_t* __restrict__ A0, const uint32_t* __restrict__ B0,
    const float* __restrict__ bias0, float* __restrict__ C0,
    int N0, int nbx0, int total0, int rnd0,
    const uint32_t* __restrict__ A1, const uint32_t* __restrict__ B1,
    const float* __restrict__ bias1, float* __restrict__ C1,
    int N1, int nbx1, int rnd1, int K)
{
    extern __shared__ uint32_t smg[];
    const uint32_t smem_base = (uint32_t)__cvta_generic_to_shared(smg);

    const uint32_t* A; const uint32_t* Bm; const float* bias; float* C;
    int N, bx, by, rnd;
    {
        const int id = blockIdx.x;
        if (id < total0) {
            A = A0; Bm = B0; bias = bias0; C = C0; N = N0; rnd = rnd0;
            bx = id % nbx0; by = id / nbx0;
        } else {
            const int j = id - total0;
            A = A1; Bm = B1; bias = bias1; C = C1; N = N1; rnd = rnd1;
            bx = j % nbx1; by = j / nbx1;
        }
    }

    const int tid = threadIdx.x;
    const int w = tid >> 5, lane = tid & 31;
    const int gr = lane >> 2, tg = lane & 3;
    const int m0w = (w & 3) * 32;
    const int n0w = (w >> 2) * 64;

    const int lq = lane >> 3;
    const int lr = lane & 7;
    const int a_row = lr + ((lq & 1) << 3);
    const int a_col = (lq >> 1) << 2;

    const uint32_t* Ag = A + (size_t)(by * 128) * K;
    const uint32_t* Bg = Bm + bx * 256;

    const int a_srow = tid >> 3;
    const int a_sc4 = (tid & 7) << 2;
    const int b_kr0 = tid >> 6;
    const int b_c4 = (tid & 63) << 2;

    const int nk = K >> 5;

    auto issue = [&](int kc) {
        const int st = kc % 3;
        const int k0 = kc << 5;
        const uint32_t abase = smem_base + (uint32_t)(st * SS) * 4;
        const uint32_t bbase = abase + A_WORDS * 4;
#pragma unroll
        for (int it = 0; it < 2; it++) {
            const int row = a_srow + 64 * it;
            cp_async16(abase + (uint32_t)(row * AST + a_sc4) * 4,
                       Ag + (size_t)row * K + k0 + a_sc4);
        }
#pragma unroll
        for (int it = 0; it < 4; it++) {
            const int kr = b_kr0 + 8 * it;
            cp_async16(bbase + (uint32_t)(kr * BST + b_c4) * 4,
                       Bg + (size_t)(k0 + kr) * N + b_c4);
        }
        cp_commit();
    };

    float c[2][8][4];
#pragma unroll
    for (int mi = 0; mi < 2; mi++)
#pragma unroll
        for (int nf = 0; nf < 8; nf++)
#pragma unroll
            for (int j = 0; j < 4; j++) c[mi][nf][j] = 0.f;

    issue(0);
    issue(1);

    for (int kc = 0; kc < nk; kc++) {
        if (kc + 1 < nk) cp_wait<1>(); else cp_wait<0>();
        __syncthreads();

        if (kc + 2 < nk) issue(kc + 2);

        const uint32_t* As = smg + (kc % 3) * SS;
        const uint32_t* Bs = As + A_WORDS;

#pragma unroll
        for (int kf = 0; kf < 4; kf++) {
            const int kb = kf << 3;
            uint32_t a[2][4];
#pragma unroll
            for (int mi = 0; mi < 2; mi++)
                ldsm_x4(a[mi][0], a[mi][1], a[mi][2], a[mi][3],
                        As + (m0w + 16 * mi + a_row) * AST + kb + a_col);
            const uint32_t* b0p = Bs + (kb + tg) * BST + n0w + gr;
            const uint32_t* b1p = b0p + 4 * BST;
#pragma unroll
            for (int nf = 0; nf < 8; nf++) {
                const uint32_t b0 = b0p[8 * nf];
                const uint32_t b1 = b1p[8 * nf];
                mma_tf32(c[0][nf], a[0], b0, b1);
                mma_tf32(c[1][nf], a[1], b0, b1);
            }
        }
    }

    // Epilogue with bias (optionally tf32-rounded output bits)
#pragma unroll
    for (int nf = 0; nf < 8; nf++) {
        const int col = bx * 256 + n0w + 8 * nf + 2 * tg;
        const float bb0 = bias[col];
        const float bb1 = bias[col + 1];
#pragma unroll
        for (int mi = 0; mi < 2; mi++) {
            const size_t r0 = (size_t)(by * 128 + m0w + 16 * mi + gr);
            const float v00 = c[mi][nf][0] + bb0, v01 = c[mi][nf][1] + bb1;
            const float v10 = c[mi][nf][2] + bb0, v11 = c[mi][nf][3] + bb1;
            if (rnd) {
                uint2 u0, u1;
                u0.x = f2tf32(v00); u0.y = f2tf32(v01);
                u1.x = f2tf32(v10); u1.y = f2tf32(v11);
                *(uint2*)((uint32_t*)C + r0 * N + col)       = u0;
                *(uint2*)((uint32_t*)C + (r0 + 8) * N + col) = u1;
            } else {
                float2 v0, v1;
                v0.x = v00; v0.y = v01; v1.x = v10; v1.y = v11;
                *(float2*)(C + r0 * N + col)       = v0;
                *(float2*)(C + (r0 + 8) * N + col) = v1;
            }
        }
    }
}

// ----------------------------------------------------------------------------
// Flash attention, tf32 mma.sync, 3-stage cp.async K/V pipeline.
// Inputs qkv/ekv are already tf32-rounded bits -> K/V copied raw via cp.async.
// Q scale 0.125 is a power of two (stays on tf32 grid, no cvt needed).
// ----------------------------------------------------------------------------
#define KST 68
#define VST 72
#define PST 68
#define KWORDS (64 * KST)                    // 4352
#define VWORDS (64 * VST)                    // 4608
#define STAGEW (KWORDS + VWORDS)             // 8960
#define PS_OFF  (3 * STAGEW)                 // 26880
#define CB_OFF  (PS_OFF + 8 * 16 * PST)      // +8704
#define ATTN_SMEM ((CB_OFF + 128) * 4)       // 142848 bytes

__global__ __launch_bounds__(256) void attn_mma(
    const float* __restrict__ qkv,   // [BS, 3*NX] tf32 bits
    const float* __restrict__ ekv,   // [BP, 2*NX] tf32 bits
    const float* __restrict__ Mmask, // [B, P]
    const float* __restrict__ amask, // [B,1,1,S]
    float* __restrict__ out)         // [BS, NX] (tf32-rounded bits)
{
    extern __shared__ float sm[];
    uint32_t* smu = (uint32_t*)sm;
    const uint32_t smem_base = (uint32_t)__cvta_generic_to_shared(sm);
    float* Ps = sm + PS_OFF;
    float* Cb = sm + CB_OFF;                 // [2][64] double-buffered
    uint32_t* Qtu = smu;                     // Q staged over stages 0-1: [128][68]

    const int bh = blockIdx.y;
    const int b = bh >> 4, h = bh & 15;
    const int q0 = blockIdx.x * 128;
    const int tid = threadIdx.x;
    const int w = tid >> 5;
    const int lane = tid & 31;
    const int gr = lane >> 2;
    const int tg = lane & 3;

    // ---- Stage Q (x 0.125, exact on tf32 grid) ----
#pragma unroll
    for (int it = 0; it < 8; it++) {
        const int fid = tid + it * 256;
        const int r = fid >> 4;
        const int c4 = (fid & 15) * 4;
        const float4 q = *(const float4*)(
            qkv + (size_t)(b * S_ + q0 + r) * (3 * NX_) + h * DH_ + c4);
        uint32_t* d = Qtu + r * KST + c4;
        d[0] = __float_as_uint(q.x * 0.125f);
        d[1] = __float_as_uint(q.y * 0.125f);
        d[2] = __float_as_uint(q.z * 0.125f);
        d[3] = __float_as_uint(q.w * 0.125f);
    }
    __syncthreads();

    uint32_t aQ[8][4];
    {
        const int r0 = 16 * w + gr;
#pragma unroll
        for (int kf = 0; kf < 8; kf++) {
            aQ[kf][0] = Qtu[r0 * KST + 8 * kf + tg];
            aQ[kf][1] = Qtu[(r0 + 8) * KST + 8 * kf + tg];
            aQ[kf][2] = Qtu[r0 * KST + 8 * kf + tg + 4];
            aQ[kf][3] = Qtu[(r0 + 8) * KST + 8 * kf + tg + 4];
        }
    }
    __syncthreads();   // all aQ reads done before cp.async overwrites Q area

    const int ntiles = 2 * blockIdx.x + 4;
    const int st_t  = tid >> 4;          // row 0..15, +16*it
    const int st_c4 = (tid & 15) * 4;

    // Issue K/V tile kt into stage kt%3 (raw 16B copies; data already tf32)
    auto issueKV = [&](int kt) {
        const uint32_t kbase = smem_base + (uint32_t)((kt % 3) * STAGEW) * 4;
        const uint32_t vbase = kbase + KWORDS * 4;
        const int t0 = kt * 64;
#pragma unroll
        for (int it = 0; it < 4; it++) {
            const int t = st_t + 16 * it;
            const int tg_ = t0 + t;
            const float* kp;
            const float* vp;
            if (tg_ < P_) {
                const float* e = ekv + (size_t)(b * P_ + tg_) * (2 * NX_) + h * DH_;
                kp = e; vp = e + NX_;
            } else {
                const float* s = qkv + (size_t)(b * S_ + tg_ - P_) * (3 * NX_) + h * DH_;
                kp = s + NX_; vp = s + 2 * NX_;
            }
            cp_async16(kbase + (uint32_t)(t * KST + st_c4) * 4, kp + st_c4);
            cp_async16(vbase + (uint32_t)(t * VST + st_c4) * 4, vp + st_c4);
        }
        cp_commit();
    };

    issueKV(0);
    issueKV(1);

    // Column-bias prefetch for tile 0
    float cbv = 0.f;
    if (tid < 64) {
        cbv = (tid < P_) ? (1.f - Mmask[b * P_ + tid]) * -10000.f
                         : amask[b * S_ + (tid - P_)];
    }

    float m0 = -1e30f, m1 = -1e30f, l0 = 0.f, l1 = 0.f;
    float o[8][4];
#pragma unroll
    for (int nf = 0; nf < 8; nf++)
#pragma unroll
        for (int j = 0; j < 4; j++) o[nf][j] = 0.f;

    uint32_t* Pswu = (uint32_t*)(Ps + w * 16 * PST);
    const int r0g = q0 + 16 * w + gr;
    const int r1g = r0g + 8;

    for (int kt = 0; kt < ntiles; kt++) {
        const int t0k = kt * 64;
        if (kt + 1 < ntiles) cp_wait<1>(); else cp_wait<0>();
        if (tid < 64) Cb[(kt & 1) * 64 + tid] = cbv;
        __syncthreads();   // stage kt ready; Cb visible; compute(kt-1) done

        if (kt + 2 < ntiles) issueKV(kt + 2);
        if (kt + 1 < ntiles && tid < 64) {
            const int t = (kt + 1) * 64 + tid;
            cbv = (t < P_) ? (1.f - Mmask[b * P_ + t]) * -10000.f
                           : amask[b * S_ + (t - P_)];
        }

        const uint32_t* Ksu = smu + (kt % 3) * STAGEW;
        const uint32_t* Vsu = Ksu + KWORDS;
        const float* Cbt = Cb + (kt & 1) * 64;

        // ---- S = Q @ K^T ----
        float s[8][4];
#pragma unroll
        for (int nf = 0; nf < 8; nf++)
#pragma unroll
            for (int j = 0; j < 4; j++) s[nf][j] = 0.f;

#pragma unroll
        for (int kf = 0; kf < 8; kf++) {
#pragma unroll
            for (int nf = 0; nf < 8; nf++) {
                const uint32_t kb0 = Ksu[(8 * nf + gr) * KST + 8 * kf + tg];
                const uint32_t kb1 = Ksu[(8 * nf + gr) * KST + 8 * kf + tg + 4];
                mma_tf32(s[nf], aQ[kf], kb0, kb1);
            }
        }

        // ---- Mask + online softmax ----
        float mx0 = -1e30f, mx1 = -1e30f;
#pragma unroll
        for (int nf = 0; nf < 8; nf++) {
            const int tc = t0k + 8 * nf + 2 * tg;
            const float cb0 = Cbt[8 * nf + 2 * tg];
            const float cb1 = Cbt[8 * nf + 2 * tg + 1];
            const int ts0 = tc - P_;
            const int ts1 = ts0 + 1;
            const float l00 = (ts0 <= r0g ? s[nf][0] : -10000.f) + cb0;
            const float l01 = (ts1 <= r0g ? s[nf][1] : -10000.f) + cb1;
            const float l10 = (ts0 <= r1g ? s[nf][2] : -10000.f) + cb0;
            const float l11 = (ts1 <= r1g ? s[nf][3] : -10000.f) + cb1;
            s[nf][0] = l00; s[nf][1] = l01; s[nf][2] = l10; s[nf][3] = l11;
            mx0 = fmaxf(mx0, fmaxf(l00, l01));
            mx1 = fmaxf(mx1, fmaxf(l10, l11));
        }
        mx0 = fmaxf(mx0, __shfl_xor_sync(0xffffffffu, mx0, 1));
        mx0 = fmaxf(mx0, __shfl_xor_sync(0xffffffffu, mx0, 2));
        mx1 = fmaxf(mx1, __shfl_xor_sync(0xffffffffu, mx1, 1));
        mx1 = fmaxf(mx1, __shfl_xor_sync(0xffffffffu, mx1, 2));

        const float nm0 = fmaxf(m0, mx0);
        const float nm1 = fmaxf(m1, mx1);
        const float al0 = __expf(m0 - nm0);
        const float al1 = __expf(m1 - nm1);
        float ps0 = 0.f, ps1 = 0.f;
#pragma unroll
        for (int nf = 0; nf < 8; nf++) {
            const float p00 = __expf(s[nf][0] - nm0);
            const float p01 = __expf(s[nf][1] - nm0);
            const float p10 = __expf(s[nf][2] - nm1);
            const float p11 = __expf(s[nf][3] - nm1);
            ps0 += p00 + p01;
            ps1 += p10 + p11;
            Pswu[gr * PST + 8 * nf + 2 * tg]           = f2tf32(p00);
            Pswu[gr * PST + 8 * nf + 2 * tg + 1]       = f2tf32(p01);
            Pswu[(gr + 8) * PST + 8 * nf + 2 * tg]     = f2tf32(p10);
            Pswu[(gr + 8) * PST + 8 * nf + 2 * tg + 1] = f2tf32(p11);
        }
        ps0 += __shfl_xor_sync(0xffffffffu, ps0, 1);
        ps0 += __shfl_xor_sync(0xffffffffu, ps0, 2);
        ps1 += __shfl_xor_sync(0xffffffffu, ps1, 1);
        ps1 += __shfl_xor_sync(0xffffffffu, ps1, 2);
        l0 = l0 * al0 + ps0;
        l1 = l1 * al1 + ps1;
        m0 = nm0; m1 = nm1;

#pragma unroll
        for (int nf = 0; nf < 8; nf++) {
            o[nf][0] *= al0; o[nf][1] *= al0;
            o[nf][2] *= al1; o[nf][3] *= al1;
        }
        __syncwarp();

        // ---- O += P @ V ----
#pragma unroll
        for (int kf = 0; kf < 8; kf++) {
            uint32_t aP[4];
            aP[0] = Pswu[gr * PST + 8 * kf + tg];
            aP[1] = Pswu[(gr + 8) * PST + 8 * kf + tg];
            aP[2] = Pswu[gr * PST + 8 * kf + tg + 4];
            aP[3] = Pswu[(gr + 8) * PST + 8 * kf + tg + 4];
#pragma unroll
            for (int nf = 0; nf < 8; nf++) {
                const uint32_t vb0 = Vsu[(8 * kf + tg) * VST + 8 * nf + gr];
                const uint32_t vb1 = Vsu[(8 * kf + tg + 4) * VST + 8 * nf + gr];
                mma_tf32(o[nf], aP, vb0, vb1);
            }
        }
    }

    const float inv0 = 1.f / l0;
    const float inv1 = 1.f / l1;
#pragma unroll
    for (int nf = 0; nf < 8; nf++) {
        const size_t base0 = (size_t)(b * S_ + r0g) * NX_ + h * DH_ + 8 * nf + 2 * tg;
        const size_t base1 = (size_t)(b * S_ + r1g) * NX_ + h * DH_ + 8 * nf + 2 * tg;
        uint2 v0, v1;
        v0.x = f2tf32(o[nf][0] * inv0); v0.y = f2tf32(o[nf][1] * inv0);
        v1.x = f2tf32(o[nf][2] * inv1); v1.y = f2tf32(o[nf][3] * inv1);
        *(uint2*)((uint32_t*)out + base0) = v0;
        *(uint2*)((uint32_t*)out + base1) = v1;
    }
}

// ----------------------------------------------------------------------------
// Launch
// ----------------------------------------------------------------------------
extern "C" void kernel_launch(void* const* d_in, const int* in_sizes, int n_in,
                              void* d_out, int out_size)
{
    const float* x      = (const float*)d_in[0];
    const float* M      = (const float*)d_in[1];
    const float* Mmask  = (const float*)d_in[2];
    const float* amask  = (const float*)d_in[3];
    const float* W_attn = (const float*)d_in[4];
    const float* b_attn = (const float*)d_in[5];
    const float* W_mem  = (const float*)d_in[6];
    const float* b_mem  = (const float*)d_in[7];
    const float* W_proj = (const float*)d_in[8];
    const float* b_proj = (const float*)d_in[9];
    float* out = (float*)d_out;

    float* qkv; cudaGetSymbolAddress((void**)&qkv, g_qkv);
    float* ekv; cudaGetSymbolAddress((void**)&ekv, g_ekv);
    float* a;   cudaGetSymbolAddress((void**)&a,   g_a);
    uint32_t* xt; cudaGetSymbolAddress((void**)&xt, g_xt);
    uint32_t* mt; cudaGetSymbolAddress((void**)&mt, g_mt);
    uint32_t* wa; cudaGetSymbolAddress((void**)&wa, g_wa);
    uint32_t* wm; cudaGetSymbolAddress((void**)&wm, g_wm);
    uint32_t* wp; cudaGetSymbolAddress((void**)&wp, g_wp);

    cudaFuncSetAttribute(tf32_gemm_dual,
                         cudaFuncAttributeMaxDynamicSharedMemorySize, GEMM_SMEM);
    cudaFuncSetAttribute(attn_mma, cudaFuncAttributeMaxDynamicSharedMemorySize,
                         ATTN_SMEM);

    // 0) fused tf32 pre-conversion of all GEMM operands
    cvt_all_kernel<<<1480, 256>>>(
        x, xt, BS_ * NX_ / 4,
        M, mt, BP_ * NX_ / 4,
        W_attn, wa, NX_ * 3 * NX_ / 4,
        W_mem, wm, NX_ * 2 * NX_ / 4,
        W_proj, wp, NX_ * NX_ / 4);

    // 1+2) fused launch: qkv (384 blocks) + ekv (32 blocks), tf32-rounded out
    {
        const int nbx0 = 3 * NX_ / 256;
        const int total0 = nbx0 * (BS_ / 128);
        const int nbx1 = 2 * NX_ / 256;
        const int total1 = nbx1 * (BP_ / 128);
        tf32_gemm_dual<<<total0 + total1, 512, GEMM_SMEM>>>(
            xt, wa, b_attn, qkv, 3 * NX_, nbx0, total0, 1,
            mt, wm, b_mem, ekv, 2 * NX_, nbx1, 1, NX_);
    }
    // 3) flash attention -> a (tf32-rounded bits)
    {
        dim3 grid(S_ / 128, B_ * H_);
        attn_mma<<<grid, 256, ATTN_SMEM>>>(qkv, ekv, Mmask, amask, a);
    }
    // 4) out = a @ W_proj + b_proj (fp32 output)
    {
        const int nbx0 = NX_ / 256;
        const int total0 = nbx0 * (BS_ / 128);
        tf32_gemm_dual<<<total0, 512, GEMM_SMEM>>>(
            (const uint32_t*)a, wp, b_proj, out, NX_, nbx0, total0, 0,
            (const uint32_t*)a, wp, b_proj, out, NX_, 1, 0, NX_);
    }
}

// round 14
// speedup vs baseline: 13.0049x; 1.5786x over previous
#include <cuda_runtime.h>
#include <cuda_fp16.h>
#include <cstdint>

// Problem constants
#define B_   4
#define S_   1024
#define P_   128
#define NX_  1024
#define H_   16
#define DH_  64
#define T_   (P_ + S_)      // 1152
#define BS_  (B_ * S_)      // 4096
#define BP_  (B_ * P_)      // 512

// Scratch (static device globals; no allocation allowed)
__device__ __half g_qkv[(size_t)BS_ * 3 * NX_];   // fp16
__device__ __half g_ekv[(size_t)BP_ * 2 * NX_];   // fp16
__device__ __half g_a  [(size_t)BS_ * NX_];       // fp16
__device__ __half g_xt [(size_t)BS_ * NX_];       // x fp16 [M][K]
__device__ __half g_mt [(size_t)BP_ * NX_];       // M fp16 [M][K]
__device__ __half g_wa [(size_t)3 * NX_ * NX_];   // W_attn^T fp16 [N][K]
__device__ __half g_wm [(size_t)2 * NX_ * NX_];   // W_mem^T  fp16 [N][K]
__device__ __half g_wp [(size_t)NX_ * NX_];       // W_proj^T fp16 [N][K]

// ----------------------------------------------------------------------------
// Helpers
// ----------------------------------------------------------------------------
__device__ __forceinline__ uint32_t h2u(__half2 h) {
    uint32_t u; *(__half2*)&u = h; return u;
}

__device__ __forceinline__ void mma_f16(float c[4], const uint32_t a[4],
                                        uint32_t b0, uint32_t b1) {
    asm volatile(
        "mma.sync.aligned.m16n8k16.row.col.f32.f16.f16.f32 "
        "{%0,%1,%2,%3}, {%4,%5,%6,%7}, {%8,%9}, {%0,%1,%2,%3};"
        : "+f"(c[0]), "+f"(c[1]), "+f"(c[2]), "+f"(c[3])
        : "r"(a[0]), "r"(a[1]), "r"(a[2]), "r"(a[3]), "r"(b0), "r"(b1));
}

__device__ __forceinline__ void ldsm_x4(uint32_t& r0, uint32_t& r1,
                                        uint32_t& r2, uint32_t& r3,
                                        const void* p) {
    uint32_t a = (uint32_t)__cvta_generic_to_shared(p);
    asm volatile("ldmatrix.sync.aligned.m8n8.x4.shared.b16 {%0,%1,%2,%3}, [%4];"
                 : "=r"(r0), "=r"(r1), "=r"(r2), "=r"(r3) : "r"(a));
}

__device__ __forceinline__ void ldsm_x4_t(uint32_t& r0, uint32_t& r1,
                                          uint32_t& r2, uint32_t& r3,
                                          const void* p) {
    uint32_t a = (uint32_t)__cvta_generic_to_shared(p);
    asm volatile("ldmatrix.sync.aligned.m8n8.x4.trans.shared.b16 {%0,%1,%2,%3}, [%4];"
                 : "=r"(r0), "=r"(r1), "=r"(r2), "=r"(r3) : "r"(a));
}

__device__ __forceinline__ void cp_async16(uint32_t smem_addr, const void* gptr) {
    asm volatile("cp.async.cg.shared.global [%0], [%1], 16;"
                 :: "r"(smem_addr), "l"(gptr));
}
__device__ __forceinline__ void cp_commit() {
    asm volatile("cp.async.commit_group;");
}
template <int N>
__device__ __forceinline__ void cp_wait() {
    asm volatile("cp.async.wait_group %0;" :: "n"(N));
}

// ----------------------------------------------------------------------------
// fp16 conversion of activations (x, M) — one launch
// ----------------------------------------------------------------------------
__global__ void cvt_f16_dual(const float* __restrict__ s0, __half* __restrict__ d0, int n0,
                             const float* __restrict__ s1, __half* __restrict__ d1, int n1)
{
    const int stride = gridDim.x * blockDim.x;
    const int t = blockIdx.x * blockDim.x + threadIdx.x;
#define SEG(S, D, NN) \
    for (int i = t; i < (NN); i += stride) { \
        const float4 v0 = ((const float4*)(S))[2 * i]; \
        const float4 v1 = ((const float4*)(S))[2 * i + 1]; \
        uint4 u; \
        u.x = h2u(__floats2half2_rn(v0.x, v0.y)); \
        u.y = h2u(__floats2half2_rn(v0.z, v0.w)); \
        u.z = h2u(__floats2half2_rn(v1.x, v1.y)); \
        u.w = h2u(__floats2half2_rn(v1.z, v1.w)); \
        ((uint4*)(D))[i] = u; \
    }
    SEG(s0, d0, n0)
    SEG(s1, d1, n1)
#undef SEG
}

// Convert + transpose all 3 weights: W[K=1024][N] fp32 -> Wt[N][1024] fp16
__global__ void transpose_f16_all(
    const float* __restrict__ W0, __half* __restrict__ T0,
    const float* __restrict__ W1, __half* __restrict__ T1,
    const float* __restrict__ W2, __half* __restrict__ T2)
{
    int id = blockIdx.x;
    const float* W; __half* T; int N;
    if (id < 3072)      { W = W0; T = T0; N = 3072; }
    else if (id < 5120) { W = W1; T = T1; N = 2048; id -= 3072; }
    else                { W = W2; T = T2; N = 1024; id -= 5120; }
    const int nbx = N >> 5;
    const int n0 = (id % nbx) * 32, k0 = (id / nbx) * 32;

    __shared__ __half t[32][33];
    const int x = threadIdx.x, y = threadIdx.y;   // block (32,8)
#pragma unroll
    for (int i = 0; i < 32; i += 8)
        t[y + i][x] = __float2half_rn(W[(size_t)(k0 + y + i) * N + n0 + x]);
    __syncthreads();
#pragma unroll
    for (int i = 0; i < 32; i += 8)
        T[(size_t)(n0 + y + i) * 1024 + k0 + x] = t[x][y + i];
}

// ----------------------------------------------------------------------------
// fp16 tensor-core GEMM: C[M,N] = A[M,K] @ Bt[N,K]^T + bias[N]
// Block 128(M) x 256(N), 16 warps (4M x 4N), warp tile m32 x n64,
// K-chunk 32, 4-stage cp.async pipeline, 512 threads.
// Smem rows: 64B data + 16B pad = 20 words (ldsm rows on distinct bank groups).
// Dual-GEMM block-range dispatch. rnd!=0 -> fp16 output, else fp32.
// ----------------------------------------------------------------------------
#define RST 20                               // words per 64B row
#define A_WORDS (128 * RST)                  // 2560
#define B_WORDS (256 * RST)                  // 5120
#define SSW (A_WORDS + B_WORDS)              // 7680 words / stage
#define GEMM_SMEM (4 * SSW * 4)              // 122880 bytes

__global__ __launch_bounds__(512, 1) void f16_gemm_dual(
    const __half* __restrict__ A0, const __half* __restrict__ B0,
    const float* __restrict__ bias0, float* __restrict__ C0,
    int N0, int nbx0, int total0, int rnd0,
    const __half* __restrict__ A1, const __half* __restrict__ B1,
    const float* __restrict__ bias1, float* __restrict__ C1,
    int N1, int nbx1, int rnd1, int K)
{
    extern __shared__ uint32_t smg[];
    const uint32_t smem_base = (uint32_t)__cvta_generic_to_shared(smg);

    const __half* A; const __half* Bm; const float* bias; float* C;
    int N, bx, by, rnd;
    {
        const int id = blockIdx.x;
        if (id < total0) {
            A = A0; Bm = B0; bias = bias0; C = C0; N = N0; rnd = rnd0;
            bx = id % nbx0; by = id / nbx0;
        } else {
            const int j = id - total0;
            A = A1; Bm = B1; bias = bias1; C = C1; N = N1; rnd = rnd1;
            bx = j % nbx1; by = j / nbx1;
        }
    }

    const int tid = threadIdx.x;
    const int w = tid >> 5, lane = tid & 31;
    const int gr = lane >> 2, tg = lane & 3;
    const int m0w = (w & 3) * 32;
    const int n0w = (w >> 2) * 64;

    const int lq = lane >> 3;
    const int lr = lane & 7;
    const int f_row = lr + ((lq & 1) << 3);   // fragment row within 16
    const int f_seg = (lq >> 1) << 2;         // k 16B segment (words)

    const __half* Ag = A + (size_t)(by * 128) * K;
    const __half* Bg = Bm + (size_t)(bx * 256) * K;

    // A: 512 segs (1/thread); B: 1024 segs (2/thread)
    const int a_row = tid >> 2, a_seg = tid & 3;

    const int nk = K >> 5;

    auto issue = [&](int kc) {
        const int st = kc & 3;
        const int k0 = kc << 5;       // in halfs
        const uint32_t abase = smem_base + (uint32_t)(st * SSW) * 4;
        const uint32_t bbase = abase + A_WORDS * 4;
        cp_async16(abase + (uint32_t)(a_row * RST + a_seg * 4) * 4,
                   Ag + (size_t)a_row * K + k0 + a_seg * 8);
#pragma unroll
        for (int it = 0; it < 2; it++) {
            const int sid = tid + (it << 9);
            const int row = sid >> 2, seg = sid & 3;
            cp_async16(bbase + (uint32_t)(row * RST + seg * 4) * 4,
                       Bg + (size_t)row * K + k0 + seg * 8);
        }
        cp_commit();
    };

    float c[2][8][4];
#pragma unroll
    for (int mi = 0; mi < 2; mi++)
#pragma unroll
        for (int nf = 0; nf < 8; nf++)
#pragma unroll
            for (int j = 0; j < 4; j++) c[mi][nf][j] = 0.f;

    issue(0); issue(1); issue(2);

    for (int kc = 0; kc < nk; kc++) {
        if (kc + 2 < nk) cp_wait<2>();
        else if (kc + 1 < nk) cp_wait<1>();
        else cp_wait<0>();
        __syncthreads();

        if (kc + 3 < nk) issue(kc + 3);   // stage freed by compute(kc-1)

        const uint32_t* As = smg + (kc & 3) * SSW;
        const uint32_t* Bs = As + A_WORDS;

#pragma unroll
        for (int kf = 0; kf < 2; kf++) {
            const int kw = kf * 8 + f_seg;   // word offset in row
            uint32_t a[2][4];
#pragma unroll
            for (int mi = 0; mi < 2; mi++)
                ldsm_x4(a[mi][0], a[mi][1], a[mi][2], a[mi][3],
                        As + (m0w + 16 * mi + f_row) * RST + kw);
#pragma unroll
            for (int p = 0; p < 4; p++) {
                uint32_t b0, b1, b2, b3;
                ldsm_x4(b0, b1, b2, b3,
                        Bs + (n0w + 16 * p + f_row) * RST + kw);
                // b0=(n0-7,k0-7) b1=(n8-15,k0-7) b2=(n0-7,k8-15) b3=(n8-15,k8-15)
                mma_f16(c[0][2 * p],     a[0], b0, b2);
                mma_f16(c[1][2 * p],     a[1], b0, b2);
                mma_f16(c[0][2 * p + 1], a[0], b1, b3);
                mma_f16(c[1][2 * p + 1], a[1], b1, b3);
            }
        }
    }

    // Epilogue with bias
#pragma unroll
    for (int nf = 0; nf < 8; nf++) {
        const int col = bx * 256 + n0w + 8 * nf + 2 * tg;
        const float bb0 = bias[col];
        const float bb1 = bias[col + 1];
#pragma unroll
        for (int mi = 0; mi < 2; mi++) {
            const size_t r0 = (size_t)(by * 128 + m0w + 16 * mi + gr);
            const float v00 = c[mi][nf][0] + bb0, v01 = c[mi][nf][1] + bb1;
            const float v10 = c[mi][nf][2] + bb0, v11 = c[mi][nf][3] + bb1;
            if (rnd) {
                ((uint32_t*)C)[(r0 * N + col) >> 1] =
                    h2u(__floats2half2_rn(v00, v01));
                ((uint32_t*)C)[((r0 + 8) * N + col) >> 1] =
                    h2u(__floats2half2_rn(v10, v11));
            } else {
                float2 v0, v1;
                v0.x = v00; v0.y = v01; v1.x = v10; v1.y = v11;
                *(float2*)(C + r0 * N + col)       = v0;
                *(float2*)(C + (r0 + 8) * N + col) = v1;
            }
        }
    }
}

// ----------------------------------------------------------------------------
// Flash attention, fp16 m16n8k16, 3-stage cp.async K/V pipeline, 2 CTAs/SM.
// Q/K/V fp16 in gmem (raw cp.async). Q-scale 0.125 folded into the logit FMA.
// K used as B via ldsm on [t][dh]; V via ldsm.trans on [t][dh]; P as fp16 A.
// smem rows: 64 fp16 + pad = 36 words.
// ----------------------------------------------------------------------------
#define TST 36
#define KW_ (64 * TST)                        // 2304 words
#define STW (2 * KW_)                         // K+V stage: 4608 words
#define PS_OFF (3 * STW)                      // 13824
#define CB_OFF (PS_OFF + 8 * 16 * TST)        // +4608 -> 18432
#define ATTN_SMEM ((CB_OFF + 128) * 4)        // 74240 bytes

__global__ __launch_bounds__(256, 2) void attn_mma(
    const __half* __restrict__ qkv,   // [BS, 3*NX]
    const __half* __restrict__ ekv,   // [BP, 2*NX]
    const float* __restrict__ Mmask,  // [B, P]
    const float* __restrict__ amask,  // [B,1,1,S]
    __half* __restrict__ out)         // [BS, NX]
{
    extern __shared__ uint32_t smu[];
    const uint32_t smem_base = (uint32_t)__cvta_generic_to_shared(smu);
    float* Cb = (float*)(smu + CB_OFF);       // [2][64]

    const int bh = blockIdx.y;
    const int b = bh >> 4, h = bh & 15;
    const int q0 = blockIdx.x * 128;
    const int tid = threadIdx.x;
    const int w = tid >> 5;
    const int lane = tid & 31;
    const int gr = lane >> 2;
    const int tg = lane & 3;
    const int lq = lane >> 3;
    const int lr = lane & 7;
    const int f_row = lr + ((lq & 1) << 3);
    const int f_seg = (lq >> 1) << 2;         // words

    // ---- Stage Q raw via cp.async into stage-0 region (consumed before KV) ----
#pragma unroll
    for (int it = 0; it < 4; it++) {
        const int sid = tid + (it << 8);
        const int r = sid >> 3, seg = sid & 7;
        cp_async16(smem_base + (uint32_t)(r * TST + seg * 4) * 4,
                   qkv + (size_t)(b * S_ + q0 + r) * (3 * NX_) + h * DH_ + seg * 8);
    }
    cp_commit();
    cp_wait<0>();
    __syncthreads();

    uint32_t aQ[4][4];
    {
        const int r0 = 16 * w + f_row;
#pragma unroll
        for (int kf = 0; kf < 4; kf++)
            ldsm_x4(aQ[kf][0], aQ[kf][1], aQ[kf][2], aQ[kf][3],
                    smu + r0 * TST + kf * 8 + f_seg);
    }
    __syncthreads();   // all aQ reads done before KV overwrites stage 0

    const int ntiles = 2 * blockIdx.x + 4;

    auto issueKV = [&](int kt) {
        const uint32_t kbase = smem_base + (uint32_t)((kt % 3) * STW) * 4;
        const uint32_t vbase = kbase + KW_ * 4;
        const int t0 = kt * 64;
#pragma unroll
        for (int it = 0; it < 2; it++) {
            const int sid = tid + (it << 8);
            const int t = sid >> 3, seg = sid & 7;
            const int tg_ = t0 + t;
            const __half* kp;
            const __half* vp;
            if (tg_ < P_) {
                const __half* e = ekv + (size_t)(b * P_ + tg_) * (2 * NX_) + h * DH_;
                kp = e; vp = e + NX_;
            } else {
                const __half* s = qkv + (size_t)(b * S_ + tg_ - P_) * (3 * NX_) + h * DH_;
                kp = s + NX_; vp = s + 2 * NX_;
            }
            cp_async16(kbase + (uint32_t)(t * TST + seg * 4) * 4, kp + seg * 8);
            cp_async16(vbase + (uint32_t)(t * TST + seg * 4) * 4, vp + seg * 8);
        }
        cp_commit();
    };

    issueKV(0);
    issueKV(1);

    float cbv = 0.f;
    if (tid < 64) {
        cbv = (tid < P_) ? (1.f - Mmask[b * P_ + tid]) * -10000.f
                         : amask[b * S_ + (tid - P_)];
    }

    float m0 = -1e30f, m1 = -1e30f, l0 = 0.f, l1 = 0.f;
    float o[8][4];
#pragma unroll
    for (int nf = 0; nf < 8; nf++)
#pragma unroll
        for (int j = 0; j < 4; j++) o[nf][j] = 0.f;

    uint32_t* Psw = smu + PS_OFF + w * 16 * TST;   // [16][72 halfs], stride 36 words
    const int r0g = q0 + 16 * w + gr;
    const int r1g = r0g + 8;

    for (int kt = 0; kt < ntiles; kt++) {
        const int t0k = kt * 64;
        if (kt + 1 < ntiles) cp_wait<1>(); else cp_wait<0>();
        if (tid < 64) Cb[(kt & 1) * 64 + tid] = cbv;
        __syncthreads();

        if (kt + 2 < ntiles) issueKV(kt + 2);
        if (kt + 1 < ntiles && tid < 64) {
            const int t = (kt + 1) * 64 + tid;
            cbv = (t < P_) ? (1.f - Mmask[b * P_ + t]) * -10000.f
                           : amask[b * S_ + (t - P_)];
        }

        const uint32_t* Ks = smu + (kt % 3) * STW;
        const uint32_t* Vs = Ks + KW_;
        const float* Cbt = Cb + (kt & 1) * 64;

        // ---- S = Q @ K^T  (K: [t][dh] as [n][k], non-trans ldsm) ----
        float s[8][4];
#pragma unroll
        for (int nf = 0; nf < 8; nf++)
#pragma unroll
            for (int j = 0; j < 4; j++) s[nf][j] = 0.f;

#pragma unroll
        for (int kf = 0; kf < 4; kf++) {
            const int kw = kf * 8 + f_seg;
#pragma unroll
            for (int p = 0; p < 4; p++) {
                uint32_t b0, b1, b2, b3;
                ldsm_x4(b0, b1, b2, b3, Ks + (16 * p + f_row) * TST + kw);
                mma_f16(s[2 * p],     aQ[kf], b0, b2);
                mma_f16(s[2 * p + 1], aQ[kf], b1, b3);
            }
        }

        // ---- Mask + online softmax (scale 0.125 folded in) ----
        float mx0 = -1e30f, mx1 = -1e30f;
#pragma unroll
        for (int nf = 0; nf < 8; nf++) {
            const int tc = t0k + 8 * nf + 2 * tg;
            const float cb0 = Cbt[8 * nf + 2 * tg];
            const float cb1 = Cbt[8 * nf + 2 * tg + 1];
            const int ts0 = tc - P_;
            const int ts1 = ts0 + 1;
            const float l00 = (ts0 <= r0g ? fmaf(s[nf][0], 0.125f, cb0) : cb0 - 10000.f);
            const float l01 = (ts1 <= r0g ? fmaf(s[nf][1], 0.125f, cb1) : cb1 - 10000.f);
            const float l10 = (ts0 <= r1g ? fmaf(s[nf][2], 0.125f, cb0) : cb0 - 10000.f);
            const float l11 = (ts1 <= r1g ? fmaf(s[nf][3], 0.125f, cb1) : cb1 - 10000.f);
            s[nf][0] = l00; s[nf][1] = l01; s[nf][2] = l10; s[nf][3] = l11;
            mx0 = fmaxf(mx0, fmaxf(l00, l01));
            mx1 = fmaxf(mx1, fmaxf(l10, l11));
        }
        mx0 = fmaxf(mx0, __shfl_xor_sync(0xffffffffu, mx0, 1));
        mx0 = fmaxf(mx0, __shfl_xor_sync(0xffffffffu, mx0, 2));
        mx1 = fmaxf(mx1, __shfl_xor_sync(0xffffffffu, mx1, 1));
        mx1 = fmaxf(mx1, __shfl_xor_sync(0xffffffffu, mx1, 2));

        const float nm0 = fmaxf(m0, mx0);
        const float nm1 = fmaxf(m1, mx1);
        const float al0 = __expf(m0 - nm0);
        const float al1 = __expf(m1 - nm1);
        float ps0 = 0.f, ps1 = 0.f;
#pragma unroll
        for (int nf = 0; nf < 8; nf++) {
            const float p00 = __expf(s[nf][0] - nm0);
            const float p01 = __expf(s[nf][1] - nm0);
            const float p10 = __expf(s[nf][2] - nm1);
            const float p11 = __expf(s[nf][3] - nm1);
            ps0 += p00 + p01;
            ps1 += p10 + p11;
            // P as fp16: rows gr / gr+8, word col 4nf+tg (banks 4gr+tg distinct)
            Psw[gr * TST + 4 * nf + tg]       = h2u(__floats2half2_rn(p00, p01));
            Psw[(gr + 8) * TST + 4 * nf + tg] = h2u(__floats2half2_rn(p10, p11));
        }
        ps0 += __shfl_xor_sync(0xffffffffu, ps0, 1);
        ps0 += __shfl_xor_sync(0xffffffffu, ps0, 2);
        ps1 += __shfl_xor_sync(0xffffffffu, ps1, 1);
        ps1 += __shfl_xor_sync(0xffffffffu, ps1, 2);
        l0 = l0 * al0 + ps0;
        l1 = l1 * al1 + ps1;
        m0 = nm0; m1 = nm1;

#pragma unroll
        for (int nf = 0; nf < 8; nf++) {
            o[nf][0] *= al0; o[nf][1] *= al0;
            o[nf][2] *= al1; o[nf][3] *= al1;
        }
        __syncwarp();

        // ---- O += P @ V  (P fp16 A-frags; V via ldsm.trans on [t][dh]) ----
#pragma unroll
        for (int kf = 0; kf < 4; kf++) {
            uint32_t aP[4];
            ldsm_x4(aP[0], aP[1], aP[2], aP[3],
                    Psw + f_row * TST + kf * 8 + f_seg);
#pragma unroll
            for (int p = 0; p < 4; p++) {
                uint32_t v0, v1, v2, v3;
                // rows = t (k), col segment = n half-block
                ldsm_x4_t(v0, v1, v2, v3,
                          Vs + (kf * 16 + f_row) * TST + 8 * p + f_seg);
                // v0=b0(n0-7) v1=b1(n0-7) v2=b0(n8-15) v3=b1(n8-15)
                mma_f16(o[2 * p],     aP, v0, v1);
                mma_f16(o[2 * p + 1], aP, v2, v3);
            }
        }
    }

    const float inv0 = 1.f / l0;
    const float inv1 = 1.f / l1;
#pragma unroll
    for (int nf = 0; nf < 8; nf++) {
        const size_t base0 = (size_t)(b * S_ + r0g) * NX_ + h * DH_ + 8 * nf + 2 * tg;
        const size_t base1 = (size_t)(b * S_ + r1g) * NX_ + h * DH_ + 8 * nf + 2 * tg;
        ((uint32_t*)out)[base0 >> 1] =
            h2u(__floats2half2_rn(o[nf][0] * inv0, o[nf][1] * inv0));
        ((uint32_t*)out)[base1 >> 1] =
            h2u(__floats2half2_rn(o[nf][2] * inv1, o[nf][3] * inv1));
    }
}

// ----------------------------------------------------------------------------
// Launch
// ----------------------------------------------------------------------------
extern "C" void kernel_launch(void* const* d_in, const int* in_sizes, int n_in,
                              void* d_out, int out_size)
{
    const float* x      = (const float*)d_in[0];
    const float* M      = (const float*)d_in[1];
    const float* Mmask  = (const float*)d_in[2];
    const float* amask  = (const float*)d_in[3];
    const float* W_attn = (const float*)d_in[4];
    const float* b_attn = (const float*)d_in[5];
    const float* W_mem  = (const float*)d_in[6];
    const float* b_mem  = (const float*)d_in[7];
    const float* W_proj = (const float*)d_in[8];
    const float* b_proj = (const float*)d_in[9];
    float* out = (float*)d_out;

    __half* qkv; cudaGetSymbolAddress((void**)&qkv, g_qkv);
    __half* ekv; cudaGetSymbolAddress((void**)&ekv, g_ekv);
    __half* a;   cudaGetSymbolAddress((void**)&a,   g_a);
    __half* xt;  cudaGetSymbolAddress((void**)&xt,  g_xt);
    __half* mt;  cudaGetSymbolAddress((void**)&mt,  g_mt);
    __half* wa;  cudaGetSymbolAddress((void**)&wa,  g_wa);
    __half* wm;  cudaGetSymbolAddress((void**)&wm,  g_wm);
    __half* wp;  cudaGetSymbolAddress((void**)&wp,  g_wp);

    cudaFuncSetAttribute(f16_gemm_dual,
                         cudaFuncAttributeMaxDynamicSharedMemorySize, GEMM_SMEM);
    cudaFuncSetAttribute(attn_mma,
                         cudaFuncAttributeMaxDynamicSharedMemorySize, ATTN_SMEM);

    // 0) fp16 conversion: activations + transposed weights
    cvt_f16_dual<<<740, 256>>>(x, xt, BS_ * NX_ / 8, M, mt, BP_ * NX_ / 8);
    {
        dim3 blk(32, 8);
        transpose_f16_all<<<6144, blk>>>(W_attn, wa, W_mem, wm, W_proj, wp);
    }

    // 1+2) fused launch: qkv (384 blocks) + ekv (32 blocks), fp16 outputs
    {
        const int nbx0 = 3 * NX_ / 256;          // 12
        const int total0 = nbx0 * (BS_ / 128);   // 384
        const int nbx1 = 2 * NX_ / 256;          // 8
        const int total1 = nbx1 * (BP_ / 128);   // 32
        f16_gemm_dual<<<total0 + total1, 512, GEMM_SMEM>>>(
            xt, wa, b_attn, (float*)qkv, 3 * NX_, nbx0, total0, 1,
            mt, wm, b_mem, (float*)ekv, 2 * NX_, nbx1, 1, NX_);
    }
    // 3) flash attention -> a (fp16)
    {
        dim3 grid(S_ / 128, B_ * H_);
        attn_mma<<<grid, 256, ATTN_SMEM>>>(qkv, ekv, Mmask, amask, a);
    }
    // 4) out = a @ W_proj + b_proj (fp32 output)
    {
        const int nbx0 = NX_ / 256;              // 4
        const int total0 = nbx0 * (BS_ / 128);   // 128
        f16_gemm_dual<<<total0, 512, GEMM_SMEM>>>(
            a, wp, b_proj, out, NX_, nbx0, total0, 0,
            a, wp, b_proj, out, NX_, 1, 0, NX_);
    }
}

// round 16
// speedup vs baseline: 13.4512x; 1.0343x over previous
#include <cuda_runtime.h>
#include <cuda_fp16.h>
#include <cstdint>

// Problem constants
#define B_   4
#define S_   1024
#define P_   128
#define NX_  1024
#define H_   16
#define DH_  64
#define T_   (P_ + S_)      // 1152
#define BS_  (B_ * S_)      // 4096
#define BP_  (B_ * P_)      // 512

// Scratch (static device globals; no allocation allowed)
__device__ __half g_qkv[(size_t)BS_ * 3 * NX_];   // fp16
__device__ __half g_ekv[(size_t)BP_ * 2 * NX_];   // fp16
__device__ __half g_a  [(size_t)BS_ * NX_];       // fp16
__device__ __half g_xt [(size_t)BS_ * NX_];       // x fp16 [M][K]
__device__ __half g_mt [(size_t)BP_ * NX_];       // M fp16 [M][K]
__device__ __half g_wa [(size_t)3 * NX_ * NX_];   // W_attn^T fp16 [N][K]
__device__ __half g_wm [(size_t)2 * NX_ * NX_];   // W_mem^T  fp16 [N][K]
__device__ __half g_wp [(size_t)NX_ * NX_];       // W_proj^T fp16 [N][K]

// ----------------------------------------------------------------------------
// Helpers
// ----------------------------------------------------------------------------
__device__ __forceinline__ uint32_t h2u(__half2 h) {
    uint32_t u; *(__half2*)&u = h; return u;
}

__device__ __forceinline__ float fexp2(float x) {
    float r;
    asm("ex2.approx.f32 %0, %1;" : "=f"(r) : "f"(x));
    return r;
}

__device__ __forceinline__ void mma_f16(float c[4], const uint32_t a[4],
                                        uint32_t b0, uint32_t b1) {
    asm volatile(
        "mma.sync.aligned.m16n8k16.row.col.f32.f16.f16.f32 "
        "{%0,%1,%2,%3}, {%4,%5,%6,%7}, {%8,%9}, {%0,%1,%2,%3};"
        : "+f"(c[0]), "+f"(c[1]), "+f"(c[2]), "+f"(c[3])
        : "r"(a[0]), "r"(a[1]), "r"(a[2]), "r"(a[3]), "r"(b0), "r"(b1));
}

__device__ __forceinline__ void ldsm_x4(uint32_t& r0, uint32_t& r1,
                                        uint32_t& r2, uint32_t& r3,
                                        const void* p) {
    uint32_t a = (uint32_t)__cvta_generic_to_shared(p);
    asm volatile("ldmatrix.sync.aligned.m8n8.x4.shared.b16 {%0,%1,%2,%3}, [%4];"
                 : "=r"(r0), "=r"(r1), "=r"(r2), "=r"(r3) : "r"(a));
}

__device__ __forceinline__ void ldsm_x4_t(uint32_t& r0, uint32_t& r1,
                                          uint32_t& r2, uint32_t& r3,
                                          const void* p) {
    uint32_t a = (uint32_t)__cvta_generic_to_shared(p);
    asm volatile("ldmatrix.sync.aligned.m8n8.x4.trans.shared.b16 {%0,%1,%2,%3}, [%4];"
                 : "=r"(r0), "=r"(r1), "=r"(r2), "=r"(r3) : "r"(a));
}

__device__ __forceinline__ void cp_async16(uint32_t smem_addr, const void* gptr) {
    asm volatile("cp.async.cg.shared.global [%0], [%1], 16;"
                 :: "r"(smem_addr), "l"(gptr));
}
__device__ __forceinline__ void cp_commit() {
    asm volatile("cp.async.commit_group;");
}
template <int N>
__device__ __forceinline__ void cp_wait() {
    asm volatile("cp.async.wait_group %0;" :: "n"(N));
}

// ----------------------------------------------------------------------------
// fp16 conversion of activations (x, M) — one launch
// ----------------------------------------------------------------------------
__global__ void cvt_f16_dual(const float* __restrict__ s0, __half* __restrict__ d0, int n0,
                             const float* __restrict__ s1, __half* __restrict__ d1, int n1)
{
    const int stride = gridDim.x * blockDim.x;
    const int t = blockIdx.x * blockDim.x + threadIdx.x;
#define SEG(S, D, NN) \
    for (int i = t; i < (NN); i += stride) { \
        const float4 v0 = ((const float4*)(S))[2 * i]; \
        const float4 v1 = ((const float4*)(S))[2 * i + 1]; \
        uint4 u; \
        u.x = h2u(__floats2half2_rn(v0.x, v0.y)); \
        u.y = h2u(__floats2half2_rn(v0.z, v0.w)); \
        u.z = h2u(__floats2half2_rn(v1.x, v1.y)); \
        u.w = h2u(__floats2half2_rn(v1.z, v1.w)); \
        ((uint4*)(D))[i] = u; \
    }
    SEG(s0, d0, n0)
    SEG(s1, d1, n1)
#undef SEG
}

// Convert + transpose all 3 weights: W[K=1024][N] fp32 -> Wt[N][1024] fp16
__global__ void transpose_f16_all(
    const float* __restrict__ W0, __half* __restrict__ T0,
    const float* __restrict__ W1, __half* __restrict__ T1,
    const float* __restrict__ W2, __half* __restrict__ T2)
{
    int id = blockIdx.x;
    const float* W; __half* T; int N;
    if (id < 3072)      { W = W0; T = T0; N = 3072; }
    else if (id < 5120) { W = W1; T = T1; N = 2048; id -= 3072; }
    else                { W = W2; T = T2; N = 1024; id -= 5120; }
    const int nbx = N >> 5;
    const int n0 = (id % nbx) * 32, k0 = (id / nbx) * 32;

    __shared__ __half t[32][33];
    const int x = threadIdx.x, y = threadIdx.y;   // block (32,8)
#pragma unroll
    for (int i = 0; i < 32; i += 8)
        t[y + i][x] = __float2half_rn(W[(size_t)(k0 + y + i) * N + n0 + x]);
    __syncthreads();
#pragma unroll
    for (int i = 0; i < 32; i += 8)
        T[(size_t)(n0 + y + i) * 1024 + k0 + x] = t[x][y + i];
}

// ----------------------------------------------------------------------------
// fp16 tensor-core GEMM (unchanged from R14): C = A @ Bt^T + bias
// Block 128x256, 16 warps, warp m32 x n64, K-chunk 32, 4-stage cp.async.
// ----------------------------------------------------------------------------
#define RST 20
#define A_WORDS (128 * RST)
#define B_WORDS (256 * RST)
#define SSW (A_WORDS + B_WORDS)
#define GEMM_SMEM (4 * SSW * 4)

__global__ __launch_bounds__(512, 1) void f16_gemm_dual(
    const __half* __restrict__ A0, const __half* __restrict__ B0,
    const float* __restrict__ bias0, float* __restrict__ C0,
    int N0, int nbx0, int total0, int rnd0,
    const __half* __restrict__ A1, const __half* __restrict__ B1,
    const float* __restrict__ bias1, float* __restrict__ C1,
    int N1, int nbx1, int rnd1, int K)
{
    extern __shared__ uint32_t smg[];
    const uint32_t smem_base = (uint32_t)__cvta_generic_to_shared(smg);

    const __half* A; const __half* Bm; const float* bias; float* C;
    int N, bx, by, rnd;
    {
        const int id = blockIdx.x;
        if (id < total0) {
            A = A0; Bm = B0; bias = bias0; C = C0; N = N0; rnd = rnd0;
            bx = id % nbx0; by = id / nbx0;
        } else {
            const int j = id - total0;
            A = A1; Bm = B1; bias = bias1; C = C1; N = N1; rnd = rnd1;
            bx = j % nbx1; by = j / nbx1;
        }
    }

    const int tid = threadIdx.x;
    const int w = tid >> 5, lane = tid & 31;
    const int gr = lane >> 2, tg = lane & 3;
    const int m0w = (w & 3) * 32;
    const int n0w = (w >> 2) * 64;

    const int lq = lane >> 3;
    const int lr = lane & 7;
    const int f_row = lr + ((lq & 1) << 3);
    const int f_seg = (lq >> 1) << 2;

    const __half* Ag = A + (size_t)(by * 128) * K;
    const __half* Bg = Bm + (size_t)(bx * 256) * K;

    const int a_row = tid >> 2, a_seg = tid & 3;
    const int nk = K >> 5;

    auto issue = [&](int kc) {
        const int st = kc & 3;
        const int k0 = kc << 5;
        const uint32_t abase = smem_base + (uint32_t)(st * SSW) * 4;
        const uint32_t bbase = abase + A_WORDS * 4;
        cp_async16(abase + (uint32_t)(a_row * RST + a_seg * 4) * 4,
                   Ag + (size_t)a_row * K + k0 + a_seg * 8);
#pragma unroll
        for (int it = 0; it < 2; it++) {
            const int sid = tid + (it << 9);
            const int row = sid >> 2, seg = sid & 3;
            cp_async16(bbase + (uint32_t)(row * RST + seg * 4) * 4,
                       Bg + (size_t)row * K + k0 + seg * 8);
        }
        cp_commit();
    };

    float c[2][8][4];
#pragma unroll
    for (int mi = 0; mi < 2; mi++)
#pragma unroll
        for (int nf = 0; nf < 8; nf++)
#pragma unroll
            for (int j = 0; j < 4; j++) c[mi][nf][j] = 0.f;

    issue(0); issue(1); issue(2);

    for (int kc = 0; kc < nk; kc++) {
        if (kc + 2 < nk) cp_wait<2>();
        else if (kc + 1 < nk) cp_wait<1>();
        else cp_wait<0>();
        __syncthreads();

        if (kc + 3 < nk) issue(kc + 3);

        const uint32_t* As = smg + (kc & 3) * SSW;
        const uint32_t* Bs = As + A_WORDS;

#pragma unroll
        for (int kf = 0; kf < 2; kf++) {
            const int kw = kf * 8 + f_seg;
            uint32_t a[2][4];
#pragma unroll
            for (int mi = 0; mi < 2; mi++)
                ldsm_x4(a[mi][0], a[mi][1], a[mi][2], a[mi][3],
                        As + (m0w + 16 * mi + f_row) * RST + kw);
#pragma unroll
            for (int p = 0; p < 4; p++) {
                uint32_t b0, b1, b2, b3;
                ldsm_x4(b0, b1, b2, b3,
                        Bs + (n0w + 16 * p + f_row) * RST + kw);
                mma_f16(c[0][2 * p],     a[0], b0, b2);
                mma_f16(c[1][2 * p],     a[1], b0, b2);
                mma_f16(c[0][2 * p + 1], a[0], b1, b3);
                mma_f16(c[1][2 * p + 1], a[1], b1, b3);
            }
        }
    }

#pragma unroll
    for (int nf = 0; nf < 8; nf++) {
        const int col = bx * 256 + n0w + 8 * nf + 2 * tg;
        const float bb0 = bias[col];
        const float bb1 = bias[col + 1];
#pragma unroll
        for (int mi = 0; mi < 2; mi++) {
            const size_t r0 = (size_t)(by * 128 + m0w + 16 * mi + gr);
            const float v00 = c[mi][nf][0] + bb0, v01 = c[mi][nf][1] + bb1;
            const float v10 = c[mi][nf][2] + bb0, v11 = c[mi][nf][3] + bb1;
            if (rnd) {
                ((uint32_t*)C)[(r0 * N + col) >> 1] =
                    h2u(__floats2half2_rn(v00, v01));
                ((uint32_t*)C)[((r0 + 8) * N + col) >> 1] =
                    h2u(__floats2half2_rn(v10, v11));
            } else {
                float2 v0, v1;
                v0.x = v00; v0.y = v01; v1.x = v10; v1.y = v11;
                *(float2*)(C + r0 * N + col)       = v0;
                *(float2*)(C + (r0 + 8) * N + col) = v1;
            }
        }
    }
}

// ----------------------------------------------------------------------------
// Flash attention, fp16 m16n8k16, 3-stage cp.async K/V pipeline, 2 CTAs/SM.
// P kept IN REGISTERS (QK C-frag == PV A-frag layout for m16n8k16).
// exp2-domain softmax (scale+log2e folded into FMA/bias).
// Warp-uniform causal fast path; reversed bx for tail balance.
// ----------------------------------------------------------------------------
#define TST 36
#define KW_ (64 * TST)                        // 2304 words
#define STW (2 * KW_)                         // K+V stage: 4608 words
#define CB_OFF (3 * STW)                      // 13824
#define ATTN_SMEM ((CB_OFF + 128) * 4)        // 55808 bytes

#define LOG2E  1.44269504f
#define QSCL   0.18033688f                    // 0.125 * log2(e)
#define MASKL  14426.9504f                    // 10000 * log2(e)

__global__ __launch_bounds__(256, 2) void attn_mma(
    const __half* __restrict__ qkv,   // [BS, 3*NX]
    const __half* __restrict__ ekv,   // [BP, 2*NX]
    const float* __restrict__ Mmask,  // [B, P]
    const float* __restrict__ amask,  // [B,1,1,S]
    __half* __restrict__ out)         // [BS, NX]
{
    extern __shared__ uint32_t smu[];
    const uint32_t smem_base = (uint32_t)__cvta_generic_to_shared(smu);
    float* Cb = (float*)(smu + CB_OFF);       // [2][64], log2-domain bias

    const int bh = blockIdx.y;
    const int b = bh >> 4, h = bh & 15;
    const int qb = (int)gridDim.x - 1 - (int)blockIdx.x;   // heavy blocks first
    const int q0 = qb * 128;
    const int tid = threadIdx.x;
    const int w = tid >> 5;
    const int lane = tid & 31;
    const int gr = lane >> 2;
    const int tg = lane & 3;
    const int lq = lane >> 3;
    const int lr = lane & 7;
    const int f_row = lr + ((lq & 1) << 3);
    const int f_seg = (lq >> 1) << 2;

    // ---- Stage Q raw via cp.async into stage-0 region ----
#pragma unroll
    for (int it = 0; it < 4; it++) {
        const int sid = tid + (it << 8);
        const int r = sid >> 3, seg = sid & 7;
        cp_async16(smem_base + (uint32_t)(r * TST + seg * 4) * 4,
                   qkv + (size_t)(b * S_ + q0 + r) * (3 * NX_) + h * DH_ + seg * 8);
    }
    cp_commit();
    cp_wait<0>();
    __syncthreads();

    uint32_t aQ[4][4];
    {
        const int r0 = 16 * w + f_row;
#pragma unroll
        for (int kf = 0; kf < 4; kf++)
            ldsm_x4(aQ[kf][0], aQ[kf][1], aQ[kf][2], aQ[kf][3],
                    smu + r0 * TST + kf * 8 + f_seg);
    }
    __syncthreads();   // aQ reads done before KV overwrites stage 0

    const int ntiles = 2 * qb + 4;

    auto issueKV = [&](int kt) {
        const uint32_t kbase = smem_base + (uint32_t)((kt % 3) * STW) * 4;
        const uint32_t vbase = kbase + KW_ * 4;
        const int t0 = kt * 64;
#pragma unroll
        for (int it = 0; it < 2; it++) {
            const int sid = tid + (it << 8);
            const int t = sid >> 3, seg = sid & 7;
            const int tg_ = t0 + t;
            const __half* kp;
            const __half* vp;
            if (tg_ < P_) {
                const __half* e = ekv + (size_t)(b * P_ + tg_) * (2 * NX_) + h * DH_;
                kp = e; vp = e + NX_;
            } else {
                const __half* s = qkv + (size_t)(b * S_ + tg_ - P_) * (3 * NX_) + h * DH_;
                kp = s + NX_; vp = s + 2 * NX_;
            }
            cp_async16(kbase + (uint32_t)(t * TST + seg * 4) * 4, kp + seg * 8);
            cp_async16(vbase + (uint32_t)(t * TST + seg * 4) * 4, vp + seg * 8);
        }
        cp_commit();
    };

    issueKV(0);
    issueKV(1);

    float cbv = 0.f;
    if (tid < 64) {
        cbv = (tid < P_) ? (1.f - Mmask[b * P_ + tid]) * -MASKL
                         : amask[b * S_ + (tid - P_)] * LOG2E;
    }

    float m0 = -1e30f, m1 = -1e30f, l0 = 0.f, l1 = 0.f;
    float o[8][4];
#pragma unroll
    for (int nf = 0; nf < 8; nf++)
#pragma unroll
        for (int j = 0; j < 4; j++) o[nf][j] = 0.f;

    const int r0g = q0 + 16 * w + gr;
    const int r1g = r0g + 8;
    const int rw_min = q0 + 16 * w;            // warp's min query row

    for (int kt = 0; kt < ntiles; kt++) {
        const int t0k = kt * 64;
        if (kt + 1 < ntiles) cp_wait<1>(); else cp_wait<0>();
        if (tid < 64) Cb[(kt & 1) * 64 + tid] = cbv;
        __syncthreads();

        if (kt + 2 < ntiles) issueKV(kt + 2);
        if (kt + 1 < ntiles && tid < 64) {
            const int t = (kt + 1) * 64 + tid;
            cbv = (t < P_) ? (1.f - Mmask[b * P_ + t]) * -MASKL
                           : amask[b * S_ + (t - P_)] * LOG2E;
        }

        const uint32_t* Ks = smu + (kt % 3) * STW;
        const uint32_t* Vs = Ks + KW_;
        const float* Cbt = Cb + (kt & 1) * 64;

        // ---- S = Q @ K^T ----
        float s[8][4];
#pragma unroll
        for (int nf = 0; nf < 8; nf++)
#pragma unroll
            for (int j = 0; j < 4; j++) s[nf][j] = 0.f;

#pragma unroll
        for (int kf = 0; kf < 4; kf++) {
            const int kw = kf * 8 + f_seg;
#pragma unroll
            for (int p = 0; p < 4; p++) {
                uint32_t b0, b1, b2, b3;
                ldsm_x4(b0, b1, b2, b3, Ks + (16 * p + f_row) * TST + kw);
                mma_f16(s[2 * p],     aQ[kf], b0, b2);
                mma_f16(s[2 * p + 1], aQ[kf], b1, b3);
            }
        }

        // ---- Mask + online softmax (log2 domain) ----
        const bool full = (t0k + 63 - P_) <= rw_min;   // warp-uniform
        float mx0 = -1e30f, mx1 = -1e30f;
#pragma unroll
        for (int nf = 0; nf < 8; nf++) {
            const float cb0 = Cbt[8 * nf + 2 * tg];
            const float cb1 = Cbt[8 * nf + 2 * tg + 1];
            float l00, l01, l10, l11;
            if (full) {
                l00 = fmaf(s[nf][0], QSCL, cb0);
                l01 = fmaf(s[nf][1], QSCL, cb1);
                l10 = fmaf(s[nf][2], QSCL, cb0);
                l11 = fmaf(s[nf][3], QSCL, cb1);
            } else {
                const int ts0 = t0k + 8 * nf + 2 * tg - P_;
                const int ts1 = ts0 + 1;
                l00 = (ts0 <= r0g ? fmaf(s[nf][0], QSCL, cb0) : cb0 - MASKL);
                l01 = (ts1 <= r0g ? fmaf(s[nf][1], QSCL, cb1) : cb1 - MASKL);
                l10 = (ts0 <= r1g ? fmaf(s[nf][2], QSCL, cb0) : cb0 - MASKL);
                l11 = (ts1 <= r1g ? fmaf(s[nf][3], QSCL, cb1) : cb1 - MASKL);
            }
            s[nf][0] = l00; s[nf][1] = l01; s[nf][2] = l10; s[nf][3] = l11;
            mx0 = fmaxf(mx0, fmaxf(l00, l01));
            mx1 = fmaxf(mx1, fmaxf(l10, l11));
        }
        mx0 = fmaxf(mx0, __shfl_xor_sync(0xffffffffu, mx0, 1));
        mx0 = fmaxf(mx0, __shfl_xor_sync(0xffffffffu, mx0, 2));
        mx1 = fmaxf(mx1, __shfl_xor_sync(0xffffffffu, mx1, 1));
        mx1 = fmaxf(mx1, __shfl_xor_sync(0xffffffffu, mx1, 2));

        const float nm0 = fmaxf(m0, mx0);
        const float nm1 = fmaxf(m1, mx1);
        const float al0 = fexp2(m0 - nm0);
        const float al1 = fexp2(m1 - nm1);

        // exp2 + pack P directly into A-fragments (C-frag == A-frag layout)
        uint32_t aP[4][4];
        float ps0 = 0.f, ps1 = 0.f;
#pragma unroll
        for (int nf = 0; nf < 8; nf++) {
            const float p00 = fexp2(s[nf][0] - nm0);
            const float p01 = fexp2(s[nf][1] - nm0);
            const float p10 = fexp2(s[nf][2] - nm1);
            const float p11 = fexp2(s[nf][3] - nm1);
            ps0 += p00 + p01;
            ps1 += p10 + p11;
            const int kf = nf >> 1, hi = (nf & 1) << 1;
            aP[kf][hi]     = h2u(__floats2half2_rn(p00, p01));
            aP[kf][hi + 1] = h2u(__floats2half2_rn(p10, p11));
        }
        ps0 += __shfl_xor_sync(0xffffffffu, ps0, 1);
        ps0 += __shfl_xor_sync(0xffffffffu, ps0, 2);
        ps1 += __shfl_xor_sync(0xffffffffu, ps1, 1);
        ps1 += __shfl_xor_sync(0xffffffffu, ps1, 2);
        l0 = l0 * al0 + ps0;
        l1 = l1 * al1 + ps1;
        m0 = nm0; m1 = nm1;

#pragma unroll
        for (int nf = 0; nf < 8; nf++) {
            o[nf][0] *= al0; o[nf][1] *= al0;
            o[nf][2] *= al1; o[nf][3] *= al1;
        }

        // ---- O += P @ V  (V via ldsm.trans on [t][dh]) ----
#pragma unroll
        for (int kf = 0; kf < 4; kf++) {
#pragma unroll
            for (int p = 0; p < 4; p++) {
                uint32_t v0, v1, v2, v3;
                ldsm_x4_t(v0, v1, v2, v3,
                          Vs + (kf * 16 + f_row) * TST + 8 * p + f_seg);
                mma_f16(o[2 * p],     aP[kf], v0, v1);
                mma_f16(o[2 * p + 1], aP[kf], v2, v3);
            }
        }
    }

    const float inv0 = 1.f / l0;
    const float inv1 = 1.f / l1;
#pragma unroll
    for (int nf = 0; nf < 8; nf++) {
        const size_t base0 = (size_t)(b * S_ + r0g) * NX_ + h * DH_ + 8 * nf + 2 * tg;
        const size_t base1 = (size_t)(b * S_ + r1g) * NX_ + h * DH_ + 8 * nf + 2 * tg;
        ((uint32_t*)out)[base0 >> 1] =
            h2u(__floats2half2_rn(o[nf][0] * inv0, o[nf][1] * inv0));
        ((uint32_t*)out)[base1 >> 1] =
            h2u(__floats2half2_rn(o[nf][2] * inv1, o[nf][3] * inv1));
    }
}

// ----------------------------------------------------------------------------
// Launch
// ----------------------------------------------------------------------------
extern "C" void kernel_launch(void* const* d_in, const int* in_sizes, int n_in,
                              void* d_out, int out_size)
{
    const float* x      = (const float*)d_in[0];
    const float* M      = (const float*)d_in[1];
    const float* Mmask  = (const float*)d_in[2];
    const float* amask  = (const float*)d_in[3];
    const float* W_attn = (const float*)d_in[4];
    const float* b_attn = (const float*)d_in[5];
    const float* W_mem  = (const float*)d_in[6];
    const float* b_mem  = (const float*)d_in[7];
    const float* W_proj = (const float*)d_in[8];
    const float* b_proj = (const float*)d_in[9];
    float* out = (float*)d_out;

    __half* qkv; cudaGetSymbolAddress((void**)&qkv, g_qkv);
    __half* ekv; cudaGetSymbolAddress((void**)&ekv, g_ekv);
    __half* a;   cudaGetSymbolAddress((void**)&a,   g_a);
    __half* xt;  cudaGetSymbolAddress((void**)&xt,  g_xt);
    __half* mt;  cudaGetSymbolAddress((void**)&mt,  g_mt);
    __half* wa;  cudaGetSymbolAddress((void**)&wa,  g_wa);
    __half* wm;  cudaGetSymbolAddress((void**)&wm,  g_wm);
    __half* wp;  cudaGetSymbolAddress((void**)&wp,  g_wp);

    cudaFuncSetAttribute(f16_gemm_dual,
                         cudaFuncAttributeMaxDynamicSharedMemorySize, GEMM_SMEM);
    cudaFuncSetAttribute(attn_mma,
                         cudaFuncAttributeMaxDynamicSharedMemorySize, ATTN_SMEM);

    // 0) fp16 conversion: activations + transposed weights
    cvt_f16_dual<<<740, 256>>>(x, xt, BS_ * NX_ / 8, M, mt, BP_ * NX_ / 8);
    {
        dim3 blk(32, 8);
        transpose_f16_all<<<6144, blk>>>(W_attn, wa, W_mem, wm, W_proj, wp);
    }

    // 1+2) fused launch: qkv (384 blocks) + ekv (32 blocks), fp16 outputs
    {
        const int nbx0 = 3 * NX_ / 256;
        const int total0 = nbx0 * (BS_ / 128);
        const int nbx1 = 2 * NX_ / 256;
        const int total1 = nbx1 * (BP_ / 128);
        f16_gemm_dual<<<total0 + total1, 512, GEMM_SMEM>>>(
            xt, wa, b_attn, (float*)qkv, 3 * NX_, nbx0, total0, 1,
            mt, wm, b_mem, (float*)ekv, 2 * NX_, nbx1, 1, NX_);
    }
    // 3) flash attention -> a (fp16)
    {
        dim3 grid(S_ / 128, B_ * H_);
        attn_mma<<<grid, 256, ATTN_SMEM>>>(qkv, ekv, Mmask, amask, a);
    }
    // 4) out = a @ W_proj + b_proj (fp32 output)
    {
        const int nbx0 = NX_ / 256;
        const int total0 = nbx0 * (BS_ / 128);
        f16_gemm_dual<<<total0, 512, GEMM_SMEM>>>(
            a, wp, b_proj, out, NX_, nbx0, total0, 0,
            a, wp, b_proj, out, NX_, 1, 0, NX_);
    }
}

// round 17
// speedup vs baseline: 13.5289x; 1.0058x over previous
#include <cuda_runtime.h>
#include <cuda_fp16.h>
#include <cstdint>

// Problem constants
#define B_   4
#define S_   1024
#define P_   128
#define NX_  1024
#define H_   16
#define DH_  64
#define T_   (P_ + S_)      // 1152
#define BS_  (B_ * S_)      // 4096
#define BP_  (B_ * P_)      // 512

// Scratch (static device globals; no allocation allowed)
__device__ __half g_qkv[(size_t)BS_ * 3 * NX_];   // fp16
__device__ __half g_ekv[(size_t)BP_ * 2 * NX_];   // fp16
__device__ __half g_a  [(size_t)BS_ * NX_];       // fp16
__device__ __half g_xt [(size_t)BS_ * NX_];       // x fp16 [M][K]
__device__ __half g_mt [(size_t)BP_ * NX_];       // M fp16 [M][K]
__device__ __half g_wa [(size_t)3 * NX_ * NX_];   // W_attn^T fp16 [N][K]
__device__ __half g_wm [(size_t)2 * NX_ * NX_];   // W_mem^T  fp16 [N][K]
__device__ __half g_wp [(size_t)NX_ * NX_];       // W_proj^T fp16 [N][K]

// ----------------------------------------------------------------------------
// Helpers
// ----------------------------------------------------------------------------
__device__ __forceinline__ uint32_t h2u(__half2 h) {
    uint32_t u; *(__half2*)&u = h; return u;
}

__device__ __forceinline__ float fexp2(float x) {
    float r;
    asm("ex2.approx.f32 %0, %1;" : "=f"(r) : "f"(x));
    return r;
}

__device__ __forceinline__ void mma_f16(float c[4], const uint32_t a[4],
                                        uint32_t b0, uint32_t b1) {
    asm volatile(
        "mma.sync.aligned.m16n8k16.row.col.f32.f16.f16.f32 "
        "{%0,%1,%2,%3}, {%4,%5,%6,%7}, {%8,%9}, {%0,%1,%2,%3};"
        : "+f"(c[0]), "+f"(c[1]), "+f"(c[2]), "+f"(c[3])
        : "r"(a[0]), "r"(a[1]), "r"(a[2]), "r"(a[3]), "r"(b0), "r"(b1));
}

__device__ __forceinline__ void ldsm_x4(uint32_t& r0, uint32_t& r1,
                                        uint32_t& r2, uint32_t& r3,
                                        const void* p) {
    uint32_t a = (uint32_t)__cvta_generic_to_shared(p);
    asm volatile("ldmatrix.sync.aligned.m8n8.x4.shared.b16 {%0,%1,%2,%3}, [%4];"
                 : "=r"(r0), "=r"(r1), "=r"(r2), "=r"(r3) : "r"(a));
}

__device__ __forceinline__ void ldsm_x4_t(uint32_t& r0, uint32_t& r1,
                                          uint32_t& r2, uint32_t& r3,
                                          const void* p) {
    uint32_t a = (uint32_t)__cvta_generic_to_shared(p);
    asm volatile("ldmatrix.sync.aligned.m8n8.x4.trans.shared.b16 {%0,%1,%2,%3}, [%4];"
                 : "=r"(r0), "=r"(r1), "=r"(r2), "=r"(r3) : "r"(a));
}

__device__ __forceinline__ void cp_async16(uint32_t smem_addr, const void* gptr) {
    asm volatile("cp.async.cg.shared.global [%0], [%1], 16;"
                 :: "r"(smem_addr), "l"(gptr));
}
__device__ __forceinline__ void cp_commit() {
    asm volatile("cp.async.commit_group;");
}
template <int N>
__device__ __forceinline__ void cp_wait() {
    asm volatile("cp.async.wait_group %0;" :: "n"(N));
}

// ----------------------------------------------------------------------------
// Fused conversion: blocks [0,6144) convert+transpose weights (32x32 tiles);
// blocks [6144, 6144+NCVT) vector-convert x and M to fp16.
// ----------------------------------------------------------------------------
#define NCVT 592

__global__ void cvt_all_f16(
    const float* __restrict__ W0, __half* __restrict__ T0,
    const float* __restrict__ W1, __half* __restrict__ T1,
    const float* __restrict__ W2, __half* __restrict__ T2,
    const float* __restrict__ x, __half* __restrict__ xt, int nx8,
    const float* __restrict__ Mm, __half* __restrict__ mt, int nm8)
{
    int id = blockIdx.x;
    if (id >= 6144) {
        // vector convert path (256 threads)
        const int t = (id - 6144) * blockDim.x + threadIdx.x;
        const int stride = NCVT * blockDim.x;
#define SEG(S, D, NN) \
        for (int i = t; i < (NN); i += stride) { \
            const float4 v0 = ((const float4*)(S))[2 * i]; \
            const float4 v1 = ((const float4*)(S))[2 * i + 1]; \
            uint4 u; \
            u.x = h2u(__floats2half2_rn(v0.x, v0.y)); \
            u.y = h2u(__floats2half2_rn(v0.z, v0.w)); \
            u.z = h2u(__floats2half2_rn(v1.x, v1.y)); \
            u.w = h2u(__floats2half2_rn(v1.z, v1.w)); \
            ((uint4*)(D))[i] = u; \
        }
        SEG(x, xt, nx8)
        SEG(Mm, mt, nm8)
#undef SEG
        return;
    }
    // transpose path: block = (32,8) emulated from 256 threads
    const float* W; __half* T; int N;
    if (id < 3072)      { W = W0; T = T0; N = 3072; }
    else if (id < 5120) { W = W1; T = T1; N = 2048; id -= 3072; }
    else                { W = W2; T = T2; N = 1024; id -= 5120; }
    const int nbx = N >> 5;
    const int n0 = (id % nbx) * 32, k0 = (id / nbx) * 32;

    __shared__ __half t[32][33];
    const int x_ = threadIdx.x & 31, y_ = threadIdx.x >> 5;
#pragma unroll
    for (int i = 0; i < 32; i += 8)
        t[y_ + i][x_] = __float2half_rn(W[(size_t)(k0 + y_ + i) * N + n0 + x_]);
    __syncthreads();
#pragma unroll
    for (int i = 0; i < 32; i += 8)
        T[(size_t)(n0 + y_ + i) * 1024 + k0 + x_] = t[x_][y_ + i];
}

// ----------------------------------------------------------------------------
// fp16 tensor-core GEMM (unchanged): C = A @ Bt^T + bias
// Block 128x256, 16 warps, warp m32 x n64, K-chunk 32, 4-stage cp.async.
// ----------------------------------------------------------------------------
#define RST 20
#define A_WORDS (128 * RST)
#define B_WORDS (256 * RST)
#define SSW (A_WORDS + B_WORDS)
#define GEMM_SMEM (4 * SSW * 4)

__global__ __launch_bounds__(512, 1) void f16_gemm_dual(
    const __half* __restrict__ A0, const __half* __restrict__ B0,
    const float* __restrict__ bias0, float* __restrict__ C0,
    int N0, int nbx0, int total0, int rnd0,
    const __half* __restrict__ A1, const __half* __restrict__ B1,
    const float* __restrict__ bias1, float* __restrict__ C1,
    int N1, int nbx1, int rnd1, int K)
{
    extern __shared__ uint32_t smg[];
    const uint32_t smem_base = (uint32_t)__cvta_generic_to_shared(smg);

    const __half* A; const __half* Bm; const float* bias; float* C;
    int N, bx, by, rnd;
    {
        const int id = blockIdx.x;
        if (id < total0) {
            A = A0; Bm = B0; bias = bias0; C = C0; N = N0; rnd = rnd0;
            bx = id % nbx0; by = id / nbx0;
        } else {
            const int j = id - total0;
            A = A1; Bm = B1; bias = bias1; C = C1; N = N1; rnd = rnd1;
            bx = j % nbx1; by = j / nbx1;
        }
    }

    const int tid = threadIdx.x;
    const int w = tid >> 5, lane = tid & 31;
    const int gr = lane >> 2, tg = lane & 3;
    const int m0w = (w & 3) * 32;
    const int n0w = (w >> 2) * 64;

    const int lq = lane >> 3;
    const int lr = lane & 7;
    const int f_row = lr + ((lq & 1) << 3);
    const int f_seg = (lq >> 1) << 2;

    const __half* Ag = A + (size_t)(by * 128) * K;
    const __half* Bg = Bm + (size_t)(bx * 256) * K;

    const int a_row = tid >> 2, a_seg = tid & 3;
    const int nk = K >> 5;

    auto issue = [&](int kc) {
        const int st = kc & 3;
        const int k0 = kc << 5;
        const uint32_t abase = smem_base + (uint32_t)(st * SSW) * 4;
        const uint32_t bbase = abase + A_WORDS * 4;
        cp_async16(abase + (uint32_t)(a_row * RST + a_seg * 4) * 4,
                   Ag + (size_t)a_row * K + k0 + a_seg * 8);
#pragma unroll
        for (int it = 0; it < 2; it++) {
            const int sid = tid + (it << 9);
            const int row = sid >> 2, seg = sid & 3;
            cp_async16(bbase + (uint32_t)(row * RST + seg * 4) * 4,
                       Bg + (size_t)row * K + k0 + seg * 8);
        }
        cp_commit();
    };

    float c[2][8][4];
#pragma unroll
    for (int mi = 0; mi < 2; mi++)
#pragma unroll
        for (int nf = 0; nf < 8; nf++)
#pragma unroll
            for (int j = 0; j < 4; j++) c[mi][nf][j] = 0.f;

    issue(0); issue(1); issue(2);

    for (int kc = 0; kc < nk; kc++) {
        if (kc + 2 < nk) cp_wait<2>();
        else if (kc + 1 < nk) cp_wait<1>();
        else cp_wait<0>();
        __syncthreads();

        if (kc + 3 < nk) issue(kc + 3);

        const uint32_t* As = smg + (kc & 3) * SSW;
        const uint32_t* Bs = As + A_WORDS;

#pragma unroll
        for (int kf = 0; kf < 2; kf++) {
            const int kw = kf * 8 + f_seg;
            uint32_t a[2][4];
#pragma unroll
            for (int mi = 0; mi < 2; mi++)
                ldsm_x4(a[mi][0], a[mi][1], a[mi][2], a[mi][3],
                        As + (m0w + 16 * mi + f_row) * RST + kw);
#pragma unroll
            for (int p = 0; p < 4; p++) {
                uint32_t b0, b1, b2, b3;
                ldsm_x4(b0, b1, b2, b3,
                        Bs + (n0w + 16 * p + f_row) * RST + kw);
                mma_f16(c[0][2 * p],     a[0], b0, b2);
                mma_f16(c[1][2 * p],     a[1], b0, b2);
                mma_f16(c[0][2 * p + 1], a[0], b1, b3);
                mma_f16(c[1][2 * p + 1], a[1], b1, b3);
            }
        }
    }

#pragma unroll
    for (int nf = 0; nf < 8; nf++) {
        const int col = bx * 256 + n0w + 8 * nf + 2 * tg;
        const float bb0 = bias[col];
        const float bb1 = bias[col + 1];
#pragma unroll
        for (int mi = 0; mi < 2; mi++) {
            const size_t r0 = (size_t)(by * 128 + m0w + 16 * mi + gr);
            const float v00 = c[mi][nf][0] + bb0, v01 = c[mi][nf][1] + bb1;
            const float v10 = c[mi][nf][2] + bb0, v11 = c[mi][nf][3] + bb1;
            if (rnd) {
                ((uint32_t*)C)[(r0 * N + col) >> 1] =
                    h2u(__floats2half2_rn(v00, v01));
                ((uint32_t*)C)[((r0 + 8) * N + col) >> 1] =
                    h2u(__floats2half2_rn(v10, v11));
            } else {
                float2 v0, v1;
                v0.x = v00; v0.y = v01; v1.x = v10; v1.y = v11;
                *(float2*)(C + r0 * N + col)       = v0;
                *(float2*)(C + (r0 + 8) * N + col) = v1;
            }
        }
    }
}

// ----------------------------------------------------------------------------
// Flash attention, fp16 m16n8k16, 3-stage cp.async K/V pipeline, 2 CTAs/SM.
// P in registers; exp2-domain softmax; exp2/pack interleaved with PV MMAs.
// ----------------------------------------------------------------------------
#define TST 36
#define KW_ (64 * TST)
#define STW (2 * KW_)
#define CB_OFF (3 * STW)
#define ATTN_SMEM ((CB_OFF + 128) * 4)

#define LOG2E  1.44269504f
#define QSCL   0.18033688f                    // 0.125 * log2(e)
#define MASKL  14426.9504f                    // 10000 * log2(e)

__global__ __launch_bounds__(256, 2) void attn_mma(
    const __half* __restrict__ qkv,   // [BS, 3*NX]
    const __half* __restrict__ ekv,   // [BP, 2*NX]
    const float* __restrict__ Mmask,  // [B, P]
    const float* __restrict__ amask,  // [B,1,1,S]
    __half* __restrict__ out)         // [BS, NX]
{
    extern __shared__ uint32_t smu[];
    const uint32_t smem_base = (uint32_t)__cvta_generic_to_shared(smu);
    float* Cb = (float*)(smu + CB_OFF);       // [2][64], log2-domain bias

    const int bh = blockIdx.y;
    const int b = bh >> 4, h = bh & 15;
    const int qb = (int)gridDim.x - 1 - (int)blockIdx.x;   // heavy blocks first
    const int q0 = qb * 128;
    const int tid = threadIdx.x;
    const int w = tid >> 5;
    const int lane = tid & 31;
    const int gr = lane >> 2;
    const int tg = lane & 3;
    const int lq = lane >> 3;
    const int lr = lane & 7;
    const int f_row = lr + ((lq & 1) << 3);
    const int f_seg = (lq >> 1) << 2;

    // ---- Stage Q raw via cp.async into stage-0 region ----
#pragma unroll
    for (int it = 0; it < 4; it++) {
        const int sid = tid + (it << 8);
        const int r = sid >> 3, seg = sid & 7;
        cp_async16(smem_base + (uint32_t)(r * TST + seg * 4) * 4,
                   qkv + (size_t)(b * S_ + q0 + r) * (3 * NX_) + h * DH_ + seg * 8);
    }
    cp_commit();
    cp_wait<0>();
    __syncthreads();

    uint32_t aQ[4][4];
    {
        const int r0 = 16 * w + f_row;
#pragma unroll
        for (int kf = 0; kf < 4; kf++)
            ldsm_x4(aQ[kf][0], aQ[kf][1], aQ[kf][2], aQ[kf][3],
                    smu + r0 * TST + kf * 8 + f_seg);
    }
    __syncthreads();   // aQ reads done before KV overwrites stage 0

    const int ntiles = 2 * qb + 4;

    auto issueKV = [&](int kt) {
        const uint32_t kbase = smem_base + (uint32_t)((kt % 3) * STW) * 4;
        const uint32_t vbase = kbase + KW_ * 4;
        const int t0 = kt * 64;
#pragma unroll
        for (int it = 0; it < 2; it++) {
            const int sid = tid + (it << 8);
            const int t = sid >> 3, seg = sid & 7;
            const int tg_ = t0 + t;
            const __half* kp;
            const __half* vp;
            if (tg_ < P_) {
                const __half* e = ekv + (size_t)(b * P_ + tg_) * (2 * NX_) + h * DH_;
                kp = e; vp = e + NX_;
            } else {
                const __half* s = qkv + (size_t)(b * S_ + tg_ - P_) * (3 * NX_) + h * DH_;
                kp = s + NX_; vp = s + 2 * NX_;
            }
            cp_async16(kbase + (uint32_t)(t * TST + seg * 4) * 4, kp + seg * 8);
            cp_async16(vbase + (uint32_t)(t * TST + seg * 4) * 4, vp + seg * 8);
        }
        cp_commit();
    };

    issueKV(0);
    issueKV(1);

    float cbv = 0.f;
    if (tid < 64) {
        cbv = (tid < P_) ? (1.f - Mmask[b * P_ + tid]) * -MASKL
                         : amask[b * S_ + (tid - P_)] * LOG2E;
    }

    float m0 = -1e30f, m1 = -1e30f, l0 = 0.f, l1 = 0.f;
    float o[8][4];
#pragma unroll
    for (int nf = 0; nf < 8; nf++)
#pragma unroll
        for (int j = 0; j < 4; j++) o[nf][j] = 0.f;

    const int r0g = q0 + 16 * w + gr;
    const int r1g = r0g + 8;
    const int rw_min = q0 + 16 * w;

    for (int kt = 0; kt < ntiles; kt++) {
        const int t0k = kt * 64;
        if (kt + 1 < ntiles) cp_wait<1>(); else cp_wait<0>();
        if (tid < 64) Cb[(kt & 1) * 64 + tid] = cbv;
        __syncthreads();

        if (kt + 2 < ntiles) issueKV(kt + 2);
        if (kt + 1 < ntiles && tid < 64) {
            const int t = (kt + 1) * 64 + tid;
            cbv = (t < P_) ? (1.f - Mmask[b * P_ + t]) * -MASKL
                           : amask[b * S_ + (t - P_)] * LOG2E;
        }

        const uint32_t* Ks = smu + (kt % 3) * STW;
        const uint32_t* Vs = Ks + KW_;
        const float* Cbt = Cb + (kt & 1) * 64;

        // ---- S = Q @ K^T ----
        float s[8][4];
#pragma unroll
        for (int nf = 0; nf < 8; nf++)
#pragma unroll
            for (int j = 0; j < 4; j++) s[nf][j] = 0.f;

#pragma unroll
        for (int kf = 0; kf < 4; kf++) {
            const int kw = kf * 8 + f_seg;
#pragma unroll
            for (int p = 0; p < 4; p++) {
                uint32_t b0, b1, b2, b3;
                ldsm_x4(b0, b1, b2, b3, Ks + (16 * p + f_row) * TST + kw);
                mma_f16(s[2 * p],     aQ[kf], b0, b2);
                mma_f16(s[2 * p + 1], aQ[kf], b1, b3);
            }
        }

        // ---- Mask + logits (log2 domain) + row maxes ----
        const bool full = (t0k + 63 - P_) <= rw_min;   // warp-uniform
        float mx0 = -1e30f, mx1 = -1e30f;
#pragma unroll
        for (int nf = 0; nf < 8; nf++) {
            const float2 cb = *(const float2*)(Cbt + 8 * nf + 2 * tg);
            float l00, l01, l10, l11;
            if (full) {
                l00 = fmaf(s[nf][0], QSCL, cb.x);
                l01 = fmaf(s[nf][1], QSCL, cb.y);
                l10 = fmaf(s[nf][2], QSCL, cb.x);
                l11 = fmaf(s[nf][3], QSCL, cb.y);
            } else {
                const int ts0 = t0k + 8 * nf + 2 * tg - P_;
                const int ts1 = ts0 + 1;
                l00 = (ts0 <= r0g ? fmaf(s[nf][0], QSCL, cb.x) : cb.x - MASKL);
                l01 = (ts1 <= r0g ? fmaf(s[nf][1], QSCL, cb.y) : cb.y - MASKL);
                l10 = (ts0 <= r1g ? fmaf(s[nf][2], QSCL, cb.x) : cb.x - MASKL);
                l11 = (ts1 <= r1g ? fmaf(s[nf][3], QSCL, cb.y) : cb.y - MASKL);
            }
            s[nf][0] = l00; s[nf][1] = l01; s[nf][2] = l10; s[nf][3] = l11;
            mx0 = fmaxf(mx0, fmaxf(l00, l01));
            mx1 = fmaxf(mx1, fmaxf(l10, l11));
        }
        mx0 = fmaxf(mx0, __shfl_xor_sync(0xffffffffu, mx0, 1));
        mx0 = fmaxf(mx0, __shfl_xor_sync(0xffffffffu, mx0, 2));
        mx1 = fmaxf(mx1, __shfl_xor_sync(0xffffffffu, mx1, 1));
        mx1 = fmaxf(mx1, __shfl_xor_sync(0xffffffffu, mx1, 2));

        const float nm0 = fmaxf(m0, mx0);
        const float nm1 = fmaxf(m1, mx1);
        const float al0 = fexp2(m0 - nm0);
        const float al1 = fexp2(m1 - nm1);
        m0 = nm0; m1 = nm1;

        // Rescale O first (must precede PV accumulation)
#pragma unroll
        for (int nf = 0; nf < 8; nf++) {
            o[nf][0] *= al0; o[nf][1] *= al0;
            o[nf][2] *= al1; o[nf][3] *= al1;
        }

        // ---- Interleaved: per kf group, exp2+pack aP[kf], then its PV MMAs ----
        float ps0 = 0.f, ps1 = 0.f;
#pragma unroll
        for (int kf = 0; kf < 4; kf++) {
            uint32_t aP[4];
#pragma unroll
            for (int half_ = 0; half_ < 2; half_++) {
                const int nf = 2 * kf + half_;
                const float p00 = fexp2(s[nf][0] - nm0);
                const float p01 = fexp2(s[nf][1] - nm0);
                const float p10 = fexp2(s[nf][2] - nm1);
                const float p11 = fexp2(s[nf][3] - nm1);
                ps0 += p00 + p01;
                ps1 += p10 + p11;
                aP[2 * half_]     = h2u(__floats2half2_rn(p00, p01));
                aP[2 * half_ + 1] = h2u(__floats2half2_rn(p10, p11));
            }
#pragma unroll
            for (int p = 0; p < 4; p++) {
                uint32_t v0, v1, v2, v3;
                ldsm_x4_t(v0, v1, v2, v3,
                          Vs + (kf * 16 + f_row) * TST + 8 * p + f_seg);
                mma_f16(o[2 * p],     aP, v0, v1);
                mma_f16(o[2 * p + 1], aP, v2, v3);
            }
        }
        ps0 += __shfl_xor_sync(0xffffffffu, ps0, 1);
        ps0 += __shfl_xor_sync(0xffffffffu, ps0, 2);
        ps1 += __shfl_xor_sync(0xffffffffu, ps1, 1);
        ps1 += __shfl_xor_sync(0xffffffffu, ps1, 2);
        l0 = l0 * al0 + ps0;
        l1 = l1 * al1 + ps1;
    }

    const float inv0 = 1.f / l0;
    const float inv1 = 1.f / l1;
#pragma unroll
    for (int nf = 0; nf < 8; nf++) {
        const size_t base0 = (size_t)(b * S_ + r0g) * NX_ + h * DH_ + 8 * nf + 2 * tg;
        const size_t base1 = (size_t)(b * S_ + r1g) * NX_ + h * DH_ + 8 * nf + 2 * tg;
        ((uint32_t*)out)[base0 >> 1] =
            h2u(__floats2half2_rn(o[nf][0] * inv0, o[nf][1] * inv0));
        ((uint32_t*)out)[base1 >> 1] =
            h2u(__floats2half2_rn(o[nf][2] * inv1, o[nf][3] * inv1));
    }
}

// ----------------------------------------------------------------------------
// Launch
// ----------------------------------------------------------------------------
extern "C" void kernel_launch(void* const* d_in, const int* in_sizes, int n_in,
                              void* d_out, int out_size)
{
    const float* x      = (const float*)d_in[0];
    const float* M      = (const float*)d_in[1];
    const float* Mmask  = (const float*)d_in[2];
    const float* amask  = (const float*)d_in[3];
    const float* W_attn = (const float*)d_in[4];
    const float* b_attn = (const float*)d_in[5];
    const float* W_mem  = (const float*)d_in[6];
    const float* b_mem  = (const float*)d_in[7];
    const float* W_proj = (const float*)d_in[8];
    const float* b_proj = (const float*)d_in[9];
    float* out = (float*)d_out;

    __half* qkv; cudaGetSymbolAddress((void**)&qkv, g_qkv);
    __half* ekv; cudaGetSymbolAddress((void**)&ekv, g_ekv);
    __half* a;   cudaGetSymbolAddress((void**)&a,   g_a);
    __half* xt;  cudaGetSymbolAddress((void**)&xt,  g_xt);
    __half* mt;  cudaGetSymbolAddress((void**)&mt,  g_mt);
    __half* wa;  cudaGetSymbolAddress((void**)&wa,  g_wa);
    __half* wm;  cudaGetSymbolAddress((void**)&wm,  g_wm);
    __half* wp;  cudaGetSymbolAddress((void**)&wp,  g_wp);

    cudaFuncSetAttribute(f16_gemm_dual,
                         cudaFuncAttributeMaxDynamicSharedMemorySize, GEMM_SMEM);
    cudaFuncSetAttribute(attn_mma,
                         cudaFuncAttributeMaxDynamicSharedMemorySize, ATTN_SMEM);

    // 0) fused fp16 conversion (weights transpose + activation convert)
    cvt_all_f16<<<6144 + NCVT, 256>>>(
        W_attn, wa, W_mem, wm, W_proj, wp,
        x, xt, BS_ * NX_ / 8, M, mt, BP_ * NX_ / 8);

    // 1+2) fused launch: qkv (384 blocks) + ekv (32 blocks), fp16 outputs
    {
        const int nbx0 = 3 * NX_ / 256;
        const int total0 = nbx0 * (BS_ / 128);
        const int nbx1 = 2 * NX_ / 256;
        const int total1 = nbx1 * (BP_ / 128);
        f16_gemm_dual<<<total0 + total1, 512, GEMM_SMEM>>>(
            xt, wa, b_attn, (float*)qkv, 3 * NX_, nbx0, total0, 1,
            mt, wm, b_mem, (float*)ekv, 2 * NX_, nbx1, 1, NX_);
    }
    // 3) flash attention -> a (fp16)
    {
        dim3 grid(S_ / 128, B_ * H_);
        attn_mma<<<grid, 256, ATTN_SMEM>>>(qkv, ekv, Mmask, amask, a);
    }
    // 4) out = a @ W_proj + b_proj (fp32 output)
    {
        const int nbx0 = NX_ / 256;
        const int total0 = nbx0 * (BS_ / 128);
        f16_gemm_dual<<<total0, 512, GEMM_SMEM>>>(
            a, wp, b_proj, out, NX_, nbx0, total0, 0,
            a, wp, b_proj, out, NX_, 1, 0, NX_);
    }
}